// round 1
// baseline (speedup 1.0000x reference)
#include <cuda_runtime.h>

#define N_PTS 200000
#define DIM 64
#define C 64
#define GRIDVOL (DIM*DIM*DIM)

// ---- scratch (allocation-free: __device__ globals) ----
__device__ float g_vox[GRIDVOL*C];   // scatter-accumulated voxel features
__device__ float g_h1[GRIDVOL*C];    // after conv1+relu+bn
__device__ float g_h2[GRIDVOL*C];    // after conv2+relu+bn
__device__ float g_mlp[N_PTS*C];     // point-branch output

// ---------------------------------------------------------------------------
// zero the voxel accumulation grid
// ---------------------------------------------------------------------------
__global__ void zero_vox_kernel() {
    float4* p = (float4*)g_vox;
    const int n4 = GRIDVOL * C / 4;
    for (int i = blockIdx.x * blockDim.x + threadIdx.x; i < n4;
         i += gridDim.x * blockDim.x)
        p[i] = make_float4(0.f, 0.f, 0.f, 0.f);
}

// ---------------------------------------------------------------------------
// point branch: mlp_out = BN(relu(in @ W + b))
// block = 16 points x 64 couts, 256 threads, 4 points per thread
// ---------------------------------------------------------------------------
__global__ __launch_bounds__(256) void mlp_kernel(
    const float* __restrict__ in, const float* __restrict__ w,
    const float* __restrict__ b,
    const float* __restrict__ g0, const float* __restrict__ be0,
    const float* __restrict__ m0, const float* __restrict__ v0)
{
    __shared__ float sW[64*64];
    __shared__ float sIn[16*64];
    const int tid = threadIdx.x;
    for (int i = tid; i < 4096; i += 256) sW[i] = w[i];
    const int n0 = blockIdx.x * 16;
    for (int i = tid; i < 1024; i += 256) {
        int n = n0 + (i >> 6);
        sIn[i] = (n < N_PTS) ? in[(n << 6) + (i & 63)] : 0.f;
    }
    __syncthreads();

    const int co = tid & 63;
    const int pg = tid >> 6;   // uniform per warp
    float acc[4];
    const float bias = b[co];
#pragma unroll
    for (int j = 0; j < 4; ++j) acc[j] = bias;

#pragma unroll 8
    for (int ci = 0; ci < 64; ++ci) {
        float wv = sW[(ci << 6) + co];
#pragma unroll
        for (int j = 0; j < 4; ++j)
            acc[j] += sIn[((pg * 4 + j) << 6) + ci] * wv;
    }

    const float s  = g0[co] * rsqrtf(v0[co] + 1e-3f);
    const float sh = be0[co] - m0[co] * s;
#pragma unroll
    for (int j = 0; j < 4; ++j) {
        int n = n0 + pg * 4 + j;
        if (n < N_PTS)
            g_mlp[(n << 6) + co] = fmaxf(acc[j], 0.f) * s + sh;
    }
}

// ---------------------------------------------------------------------------
// voxelize: scatter-add raw inputs into g_vox
// ---------------------------------------------------------------------------
__global__ void scatter_kernel(const float* __restrict__ in,
                               const int* __restrict__ vidx)
{
    int t = blockIdx.x * blockDim.x + threadIdx.x;
    if (t >= N_PTS * C) return;
    int n = t >> 6, c = t & 63;
    int ix = vidx[n * 3 + 0];
    int iy = vidx[n * 3 + 1];
    int iz = vidx[n * 3 + 2];
    atomicAdd(&g_vox[(((((ix << 6) + iy) << 6) + iz) << 6) + c], in[t]);
}

// ---------------------------------------------------------------------------
// 3x3x3 conv, 64->64, SAME padding, fused bias+relu+BN.
// STAGE 1: in = g_vox * pinv (per-voxel normalization), out = g_h1
// STAGE 2: in = g_h1, out = g_h2
// Block: 4x4x4 spatial tile x 64 couts. 256 threads: thread = 4 pos x 4 couts.
// cin processed in 2 chunks of 32 so the halo tile fits static smem.
// ---------------------------------------------------------------------------
template<int STAGE>
__global__ __launch_bounds__(256) void conv_kernel(
    const float* __restrict__ Kw, const float* __restrict__ cb,
    const float* __restrict__ g,  const float* __restrict__ be,
    const float* __restrict__ m,  const float* __restrict__ v,
    const float* __restrict__ pinv)
{
    const float* __restrict__ in  = (STAGE == 1) ? g_vox : g_h1;
    float* __restrict__       out = (STAGE == 1) ? g_h1  : g_h2;

    __shared__ float sIn[216 * 36];   // 6x6x6 halo tile, 32 chans, stride 36 (pad)
    __shared__ float sW[32 * 64];     // one tap, one cin chunk

    const int tid = threadIdx.x;
    const int bx = blockIdx.x * 4, by = blockIdx.y * 4, bz = blockIdx.z * 4;
    const int co = (tid & 15) * 4;    // 4 consecutive couts
    const int pg = tid >> 4;          // 16 position groups

    float acc[4][4];
#pragma unroll
    for (int j = 0; j < 4; ++j) {
        float bias;
#pragma unroll
        for (int k = 0; k < 4; ++k) { bias = cb[co + k]; acc[j][k] = bias; }
    }

    for (int cc = 0; cc < 64; cc += 32) {
        __syncthreads();   // protect sIn reuse across chunks
        // --- load 6x6x6 x 32-chan halo tile (zero padded), vectorized ---
        for (int i = tid; i < 216 * 8; i += 256) {
            int pos = i >> 3;
            int c4  = (i & 7) << 2;
            int lx = pos / 36, r = pos % 36, ly = r / 6, lz = r % 6;
            int gx = bx + lx - 1, gy = by + ly - 1, gz = bz + lz - 1;
            float4 val = make_float4(0.f, 0.f, 0.f, 0.f);
            if ((unsigned)gx < 64u && (unsigned)gy < 64u && (unsigned)gz < 64u) {
                int vox = (((gx << 6) + gy) << 6) + gz;
                val = *(const float4*)&in[(vox << 6) + cc + c4];
                if (STAGE == 1) {
                    float s = pinv[vox];
                    val.x *= s; val.y *= s; val.z *= s; val.w *= s;
                }
            }
            *(float4*)&sIn[pos * 36 + c4] = val;
        }

        for (int tap = 0; tap < 27; ++tap) {
            __syncthreads();   // sIn ready / previous sW consumed
            // --- load this tap's 32x64 weight slab ---
            const float* Kt = Kw + tap * 4096 + cc * 64;
            for (int i = tid; i < 512; i += 256)
                *(float4*)&sW[i * 4] = *(const float4*)&Kt[i * 4];
            __syncthreads();

            const int dx = tap / 9, dy = (tap / 3) % 3, dz = tap % 3;
            int sbase[4];
#pragma unroll
            for (int j = 0; j < 4; ++j) {
                int q  = pg * 4 + j;
                int px = q >> 4, py = (q >> 2) & 3, pz = q & 3;
                sbase[j] = (((px + dx) * 6 + (py + dy)) * 6 + (pz + dz)) * 36;
            }
#pragma unroll
            for (int ci = 0; ci < 32; ++ci) {
                float4 w4 = *(float4*)&sW[(ci << 6) + co];
#pragma unroll
                for (int j = 0; j < 4; ++j) {
                    float a = sIn[sbase[j] + ci];
                    acc[j][0] += a * w4.x;
                    acc[j][1] += a * w4.y;
                    acc[j][2] += a * w4.z;
                    acc[j][3] += a * w4.w;
                }
            }
        }
    }

    // --- fused relu + BN epilogue ---
    float sc[4], sh[4];
#pragma unroll
    for (int k = 0; k < 4; ++k) {
        float s = g[co + k] * rsqrtf(v[co + k] + 1e-3f);
        sc[k] = s;
        sh[k] = be[co + k] - m[co + k] * s;
    }
#pragma unroll
    for (int j = 0; j < 4; ++j) {
        int q  = pg * 4 + j;
        int px = q >> 4, py = (q >> 2) & 3, pz = q & 3;
        int vox = ((((bx + px) << 6) + (by + py)) << 6) + (bz + pz);
        float4 r;
        r.x = fmaxf(acc[j][0], 0.f) * sc[0] + sh[0];
        r.y = fmaxf(acc[j][1], 0.f) * sc[1] + sh[1];
        r.z = fmaxf(acc[j][2], 0.f) * sc[2] + sh[2];
        r.w = fmaxf(acc[j][3], 0.f) * sc[3] + sh[3];
        *(float4*)&out[(vox << 6) + co] = r;
    }
}

// ---------------------------------------------------------------------------
// devoxelize: trilinear gather from g_h2 + residual add of g_mlp
// ---------------------------------------------------------------------------
__global__ void gather_kernel(const float* __restrict__ coords,
                              float* __restrict__ out)
{
    int t = blockIdx.x * blockDim.x + threadIdx.x;
    if (t >= N_PTS * C) return;
    int n = t >> 6, c = t & 63;

    float px = fminf(fmaxf(coords[n * 3 + 0], 0.f), 63.f);
    float py = fminf(fmaxf(coords[n * 3 + 1], 0.f), 63.f);
    float pz = fminf(fmaxf(coords[n * 3 + 2], 0.f), 63.f);
    float fx = floorf(px), fy = floorf(py), fz = floorf(pz);
    int x0 = (int)fx, y0 = (int)fy, z0 = (int)fz;
    int x1 = min(x0 + 1, 63), y1 = min(y0 + 1, 63), z1 = min(z0 + 1, 63);
    float tx = px - fx, ty = py - fy, tz = pz - fz;

    const float* __restrict__ h = g_h2;
    auto at = [&](int x, int y, int z) {
        return h[(((((x << 6) + y) << 6) + z) << 6) + c];
    };

    float r = g_mlp[t];
    // reference loop order: dx outer, dy, dz inner
    r += (1.f - tx) * (1.f - ty) * (1.f - tz) * at(x0, y0, z0);
    r += (1.f - tx) * (1.f - ty) * tz          * at(x0, y0, z1);
    r += (1.f - tx) * ty          * (1.f - tz) * at(x0, y1, z0);
    r += (1.f - tx) * ty          * tz          * at(x0, y1, z1);
    r += tx          * (1.f - ty) * (1.f - tz) * at(x1, y0, z0);
    r += tx          * (1.f - ty) * tz          * at(x1, y0, z1);
    r += tx          * ty          * (1.f - tz) * at(x1, y1, z0);
    r += tx          * ty          * tz          * at(x1, y1, z1);

    out[t] = r;
}

// ---------------------------------------------------------------------------
extern "C" void kernel_launch(void* const* d_in, const int* in_sizes, int n_in,
                              void* d_out, int out_size)
{
    const float* inputs    = (const float*)d_in[0];
    const float* pt_coords = (const float*)d_in[1];
    const int*   vidx      = (const int*)  d_in[2];
    const float* pinv      = (const float*)d_in[3];
    const float* w_mlp     = (const float*)d_in[4];
    const float* b_mlp     = (const float*)d_in[5];
    const float* g0        = (const float*)d_in[6];
    const float* be0       = (const float*)d_in[7];
    const float* m0        = (const float*)d_in[8];
    const float* v0        = (const float*)d_in[9];
    const float* k1        = (const float*)d_in[10];
    const float* cb1       = (const float*)d_in[11];
    const float* g1        = (const float*)d_in[12];
    const float* be1       = (const float*)d_in[13];
    const float* m1        = (const float*)d_in[14];
    const float* v1        = (const float*)d_in[15];
    const float* k2        = (const float*)d_in[16];
    const float* cb2       = (const float*)d_in[17];
    const float* g2        = (const float*)d_in[18];
    const float* be2       = (const float*)d_in[19];
    const float* m2        = (const float*)d_in[20];
    const float* v2        = (const float*)d_in[21];
    float* out = (float*)d_out;

    zero_vox_kernel<<<2048, 256>>>();
    mlp_kernel<<<(N_PTS + 15) / 16, 256>>>(inputs, w_mlp, b_mlp, g0, be0, m0, v0);
    scatter_kernel<<<(N_PTS * C + 255) / 256, 256>>>(inputs, vidx);

    dim3 cgrid(16, 16, 16);
    conv_kernel<1><<<cgrid, 256>>>(k1, cb1, g1, be1, m1, v1, pinv);
    conv_kernel<2><<<cgrid, 256>>>(k2, cb2, g2, be2, m2, v2, pinv);

    gather_kernel<<<(N_PTS * C + 255) / 256, 256>>>(pt_coords, out);
}

// round 3
// speedup vs baseline: 2.2869x; 2.2869x over previous
#include <cuda_runtime.h>
#include <cuda_bf16.h>
#include <cstdint>

#define N_PTS 200000
#define GRIDVOL (64*64*64)

// padded 66^3 flat grid + guard rows so every tap-shifted 128-row window
// stays in-bounds.
#define PXS 4356            // x stride (66*66)
#define PYS 66              // y stride
#define PTOT 287496         // 66^3
#define GUARD 4608
#define PROWS (PTOT + 2*GUARD)
#define NTILE 2247          // ceil(PTOT/128)

// ---- scratch (allocation-free: __device__ globals, zero-initialized) ----
__device__ float g_vox[GRIDVOL*64];           // scatter accumulation (fp32)
__device__ float g_h2p[PROWS*64];             // conv2 output, padded fp32
__device__ float g_mlp[N_PTS*64];             // point branch
__device__ __nv_bfloat16 g_Phi[PROWS*64];     // conv1 input hi (pads stay 0)
__device__ __nv_bfloat16 g_Plo[PROWS*64];     // conv1 input lo
__device__ __nv_bfloat16 g_Qhi[PROWS*64];     // conv2 input hi (pads stay 0)
__device__ __nv_bfloat16 g_Qlo[PROWS*64];     // conv2 input lo
__device__ __nv_bfloat16 g_Whi[2][27*64*64];  // weights [tap][cout][cin] hi
__device__ __nv_bfloat16 g_Wlo[2][27*64*64];  // weights lo

// ---------------------------------------------------------------------------
// helpers
// ---------------------------------------------------------------------------
__device__ __forceinline__ uint32_t smem_u32(const void* p) {
    uint32_t a;
    asm("{ .reg .u64 t; cvta.to.shared.u64 t, %1; cvt.u32.u64 %0, t; }"
        : "=r"(a) : "l"(p));
    return a;
}
__device__ __forceinline__ void ldsm_x4(uint32_t* r, uint32_t a) {
    asm volatile("ldmatrix.sync.aligned.m8n8.x4.shared.b16 {%0,%1,%2,%3}, [%4];"
        : "=r"(r[0]), "=r"(r[1]), "=r"(r[2]), "=r"(r[3]) : "r"(a));
}
__device__ __forceinline__ void ldsm_x2(uint32_t* r, uint32_t a) {
    asm volatile("ldmatrix.sync.aligned.m8n8.x2.shared.b16 {%0,%1}, [%2];"
        : "=r"(r[0]), "=r"(r[1]) : "r"(a));
}
__device__ __forceinline__ void mma16816(float* c, const uint32_t* a,
                                         const uint32_t* b) {
    asm volatile("mma.sync.aligned.m16n8k16.row.col.f32.bf16.bf16.f32 "
        "{%0,%1,%2,%3}, {%4,%5,%6,%7}, {%8,%9}, {%0,%1,%2,%3};"
        : "+f"(c[0]), "+f"(c[1]), "+f"(c[2]), "+f"(c[3])
        : "r"(a[0]), "r"(a[1]), "r"(a[2]), "r"(a[3]), "r"(b[0]), "r"(b[1]));
}
__device__ __forceinline__ void bsplit(float x, __nv_bfloat16& h, __nv_bfloat16& l) {
    h = __float2bfloat16(x);
    l = __float2bfloat16(x - __bfloat162float(h));
}

// ---------------------------------------------------------------------------
// zero the voxel accumulation grid (atomics accumulate -> must re-zero)
// ---------------------------------------------------------------------------
__global__ void zero_vox_kernel() {
    float4* p = (float4*)g_vox;
    const int n4 = GRIDVOL * 64 / 4;
    for (int i = blockIdx.x * blockDim.x + threadIdx.x; i < n4;
         i += gridDim.x * blockDim.x)
        p[i] = make_float4(0.f, 0.f, 0.f, 0.f);
}

// ---------------------------------------------------------------------------
// point branch: mlp_out = BN(relu(in @ W + b))
// ---------------------------------------------------------------------------
__global__ __launch_bounds__(256) void mlp_kernel(
    const float* __restrict__ in, const float* __restrict__ w,
    const float* __restrict__ b,
    const float* __restrict__ g0, const float* __restrict__ be0,
    const float* __restrict__ m0, const float* __restrict__ v0)
{
    __shared__ float sW[64*64];
    __shared__ float sIn[16*64];
    const int tid = threadIdx.x;
    for (int i = tid; i < 4096; i += 256) sW[i] = w[i];
    const int n0 = blockIdx.x * 16;
    for (int i = tid; i < 1024; i += 256) {
        int n = n0 + (i >> 6);
        sIn[i] = (n < N_PTS) ? in[(n << 6) + (i & 63)] : 0.f;
    }
    __syncthreads();
    const int co = tid & 63;
    const int pg = tid >> 6;
    float acc[4];
    const float bias = b[co];
#pragma unroll
    for (int j = 0; j < 4; ++j) acc[j] = bias;
#pragma unroll 8
    for (int ci = 0; ci < 64; ++ci) {
        float wv = sW[(ci << 6) + co];
#pragma unroll
        for (int j = 0; j < 4; ++j)
            acc[j] += sIn[((pg * 4 + j) << 6) + ci] * wv;
    }
    const float s  = g0[co] * rsqrtf(v0[co] + 1e-3f);
    const float sh = be0[co] - m0[co] * s;
#pragma unroll
    for (int j = 0; j < 4; ++j) {
        int n = n0 + pg * 4 + j;
        if (n < N_PTS)
            g_mlp[(n << 6) + co] = fmaxf(acc[j], 0.f) * s + sh;
    }
}

// ---------------------------------------------------------------------------
// voxelize: scatter-add raw inputs into g_vox
// ---------------------------------------------------------------------------
__global__ void scatter_kernel(const float* __restrict__ in,
                               const int* __restrict__ vidx)
{
    int t = blockIdx.x * blockDim.x + threadIdx.x;
    if (t >= N_PTS * 64) return;
    int n = t >> 6;
    int ix = vidx[n * 3 + 0];
    int iy = vidx[n * 3 + 1];
    int iz = vidx[n * 3 + 2];
    atomicAdd(&g_vox[(((((ix << 6) + iy) << 6) + iz) << 6) + (t & 63)], in[t]);
}

// ---------------------------------------------------------------------------
// weight prep: k [tap][cin][cout] fp32 -> [tap][cout][cin] bf16 hi/lo
// ---------------------------------------------------------------------------
__global__ void build_W_kernel(const float* __restrict__ k, int stage) {
    int i = blockIdx.x * blockDim.x + threadIdx.x;
    if (i >= 27 * 64 * 64) return;
    int tap = i >> 12, r = i & 4095, cin = r >> 6, cout = r & 63;
    int o = (tap << 12) + (cout << 6) + cin;
    __nv_bfloat16 h, l;
    bsplit(k[i], h, l);
    g_Whi[stage][o] = h;
    g_Wlo[stage][o] = l;
}

// ---------------------------------------------------------------------------
// build padded bf16 hi/lo conv1 input: P = g_vox * pinv
// ---------------------------------------------------------------------------
__global__ void build_P_kernel(const float* __restrict__ pinv) {
    int t = blockIdx.x * blockDim.x + threadIdx.x;
    if (t >= GRIDVOL * 16) return;
    int vox = t >> 4, c4 = (t & 15) << 2;
    float s = pinv[vox];
    float4 v = *(const float4*)&g_vox[(vox << 6) + c4];
    int x = vox >> 12, y = (vox >> 6) & 63, z = vox & 63;
    long p = (long)(x + 1) * PXS + (y + 1) * PYS + (z + 1);
    long idx = (GUARD + p) * 64 + c4;
    __nv_bfloat16 h, l;
    bsplit(v.x * s, h, l); g_Phi[idx+0] = h; g_Plo[idx+0] = l;
    bsplit(v.y * s, h, l); g_Phi[idx+1] = h; g_Plo[idx+1] = l;
    bsplit(v.z * s, h, l); g_Phi[idx+2] = h; g_Plo[idx+2] = l;
    bsplit(v.w * s, h, l); g_Phi[idx+3] = h; g_Plo[idx+3] = l;
}

// ---------------------------------------------------------------------------
// mma.sync implicit-GEMM conv. CTA = 128 padded rows x 64 couts, 8 warps
// tiled 4Mx2N (warp tile 32x32). 9 stages (dx,dy): stage a 132-row A window
// (hi/lo) + 3 taps of W (hi/lo) into swizzled smem, then 3 dz taps x 4
// k-chunks x 3 split passes of m16n8k16 bf16 mma. Fragments are loaded from
// smem ONCE per (tap,kchunk) and reused across the 3 passes.
// smem layout (bytes): Ahi[0,16896) Alo[16896,33792)
//                      Whi[33792+dz*8192) Wlo[58368+dz*8192)
// ---------------------------------------------------------------------------
template<int STAGE>
__global__ __launch_bounds__(256) void conv_mma_kernel(
    const float* __restrict__ cb, const float* __restrict__ g,
    const float* __restrict__ be, const float* __restrict__ m,
    const float* __restrict__ v)
{
    extern __shared__ char dyn[];
    __shared__ float s_ep[192];   // bias | scale | shift

    const int tid  = threadIdx.x;
    const int lane = tid & 31;
    const int warp = tid >> 5;
    const int m0 = (warp >> 1) * 32;
    const int n0 = (warp & 1) * 32;
    const uint32_t S0 = smem_u32(dyn);

    if (tid < 64) {
        float sc = g[tid] * rsqrtf(v[tid] + 1e-3f);
        s_ep[tid]       = cb[tid];
        s_ep[64 + tid]  = sc;
        s_ep[128 + tid] = be[tid] - m[tid] * sc;
    }

    const __nv_bfloat16* __restrict__ SHI = (STAGE == 1) ? g_Phi : g_Qhi;
    const __nv_bfloat16* __restrict__ SLO = (STAGE == 1) ? g_Plo : g_Qlo;
    const uint4* __restrict__ WHI = (const uint4*)g_Whi[STAGE - 1];
    const uint4* __restrict__ WLO = (const uint4*)g_Wlo[STAGE - 1];

    float acc[2][4][4];
#pragma unroll
    for (int a = 0; a < 2; ++a)
#pragma unroll
        for (int b = 0; b < 4; ++b)
#pragma unroll
            for (int c = 0; c < 4; ++c) acc[a][b][c] = 0.f;

    const int arow_l = lane & 15, acsel = lane >> 4;
    const int nrow_l = lane & 7,  wcsel = (lane >> 3) & 1;

    for (int s = 0; s < 9; ++s) {
        const int dx = s / 3, dy = s % 3, tap0 = s * 3;
        __syncthreads();   // previous stage's frags consumed

        // ---- stage A window: 132 rows (128 + dz halo), hi & lo ----
        const long w0 = (long)GUARD + (long)blockIdx.x * 128
                        + (long)(dx - 1) * PXS + (dy - 1) * PYS - 1;
        const uint4* ahi = (const uint4*)SHI + w0 * 8;
        const uint4* alo = (const uint4*)SLO + w0 * 8;
#pragma unroll 2
        for (int i = tid; i < 1056; i += 256) {
            int row = i >> 3, c = i & 7;
            uint32_t d = row * 128 + (((uint32_t)(c ^ (row & 7))) << 4);
            *(uint4*)(dyn + d)         = ahi[i];
            *(uint4*)(dyn + 16896 + d) = alo[i];
        }
        // ---- stage W: 3 taps x 64 couts x 128B, hi & lo ----
#pragma unroll 2
        for (int i = tid; i < 1536; i += 256) {
            int t3 = i >> 9, r = (i >> 3) & 63, c = i & 7;
            int srcu = (tap0 + t3) * 512 + r * 8 + c;
            uint32_t d = t3 * 8192 + r * 128 + (((uint32_t)(c ^ (r & 7))) << 4);
            *(uint4*)(dyn + 33792 + d) = WHI[srcu];
            *(uint4*)(dyn + 58368 + d) = WLO[srcu];
        }
        __syncthreads();

        for (int dz = 0; dz < 3; ++dz) {
#pragma unroll
            for (int kc = 0; kc < 4; ++kc) {
                uint32_t a_hi[2][4], a_lo[2][4], b_hi[4][2], b_lo[4][2];
#pragma unroll
                for (int mt = 0; mt < 2; ++mt) {
                    int row = dz + m0 + mt * 16 + arow_l;
                    uint32_t off = row * 128 +
                        (((uint32_t)((kc * 2 + acsel) ^ (row & 7))) << 4);
                    ldsm_x4(a_hi[mt], S0 + off);
                    ldsm_x4(a_lo[mt], S0 + 16896 + off);
                }
#pragma unroll
                for (int nt = 0; nt < 4; ++nt) {
                    int row = n0 + nt * 8 + nrow_l;
                    uint32_t off = dz * 8192 + row * 128 +
                        (((uint32_t)((kc * 2 + wcsel) ^ (row & 7))) << 4);
                    ldsm_x2(b_hi[nt], S0 + 33792 + off);
                    ldsm_x2(b_lo[nt], S0 + 58368 + off);
                }
#pragma unroll
                for (int mt = 0; mt < 2; ++mt)
#pragma unroll
                    for (int nt = 0; nt < 4; ++nt) {
                        mma16816(acc[mt][nt], a_hi[mt], b_hi[nt]);
                        mma16816(acc[mt][nt], a_hi[mt], b_lo[nt]);
                        mma16816(acc[mt][nt], a_lo[mt], b_hi[nt]);
                    }
            }
        }
    }

    // ---- epilogue: bias + relu + BN; write per c-frag mapping ----
    const int gr = lane >> 2, tig = lane & 3;
#pragma unroll
    for (int mt = 0; mt < 2; ++mt)
#pragma unroll
        for (int half = 0; half < 2; ++half) {
            int rl = m0 + mt * 16 + half * 8 + gr;
            long p = (long)blockIdx.x * 128 + rl;
            bool valid = true;
            if (STAGE == 1) {
                valid = (p < PTOT);
                if (valid) {
                    int x = (int)(p / PXS);
                    int rem = (int)(p - (long)x * PXS);
                    int y = rem / PYS, z = rem - y * PYS;
                    valid = (x >= 1) && (x <= 64) && (y >= 1) && (y <= 64)
                            && (z >= 1) && (z <= 64);
                }
                if (!valid) continue;   // pads must stay zero for conv2
            }
            long base = (GUARD + p) * 64;
#pragma unroll
            for (int nt = 0; nt < 4; ++nt) {
                int col = n0 + nt * 8 + tig * 2;
                float v0 = fmaxf(acc[mt][nt][half * 2 + 0] + s_ep[col], 0.f)
                           * s_ep[64 + col] + s_ep[128 + col];
                float v1 = fmaxf(acc[mt][nt][half * 2 + 1] + s_ep[col + 1], 0.f)
                           * s_ep[64 + col + 1] + s_ep[128 + col + 1];
                if (STAGE == 1) {
                    __nv_bfloat16 h0, l0, h1, l1;
                    bsplit(v0, h0, l0);
                    bsplit(v1, h1, l1);
                    __nv_bfloat162 hv; hv.x = h0; hv.y = h1;
                    __nv_bfloat162 lv; lv.x = l0; lv.y = l1;
                    *(__nv_bfloat162*)&g_Qhi[base + col] = hv;
                    *(__nv_bfloat162*)&g_Qlo[base + col] = lv;
                } else {
                    float2 fv; fv.x = v0; fv.y = v1;
                    *(float2*)&g_h2p[base + col] = fv;
                }
            }
        }
}

// ---------------------------------------------------------------------------
// devoxelize: trilinear gather from padded g_h2p + residual add of g_mlp
// ---------------------------------------------------------------------------
__global__ void gather_kernel(const float* __restrict__ coords,
                              float* __restrict__ out)
{
    int t = blockIdx.x * blockDim.x + threadIdx.x;
    if (t >= N_PTS * 64) return;
    int n = t >> 6, c = t & 63;
    float px = fminf(fmaxf(coords[n * 3 + 0], 0.f), 63.f);
    float py = fminf(fmaxf(coords[n * 3 + 1], 0.f), 63.f);
    float pz = fminf(fmaxf(coords[n * 3 + 2], 0.f), 63.f);
    float fx = floorf(px), fy = floorf(py), fz = floorf(pz);
    int x0 = (int)fx, y0 = (int)fy, z0 = (int)fz;
    int x1 = min(x0 + 1, 63), y1 = min(y0 + 1, 63), z1 = min(z0 + 1, 63);
    float tx = px - fx, ty = py - fy, tz = pz - fz;
    auto at = [&](int x, int y, int z) {
        long row = (long)GUARD + (long)(x + 1) * PXS + (y + 1) * PYS + (z + 1);
        return g_h2p[row * 64 + c];
    };
    float r = g_mlp[t];
    r += (1.f - tx) * (1.f - ty) * (1.f - tz) * at(x0, y0, z0);
    r += (1.f - tx) * (1.f - ty) * tz          * at(x0, y0, z1);
    r += (1.f - tx) * ty          * (1.f - tz) * at(x0, y1, z0);
    r += (1.f - tx) * ty          * tz          * at(x0, y1, z1);
    r += tx          * (1.f - ty) * (1.f - tz) * at(x1, y0, z0);
    r += tx          * (1.f - ty) * tz          * at(x1, y0, z1);
    r += tx          * ty          * (1.f - tz) * at(x1, y1, z0);
    r += tx          * ty          * tz          * at(x1, y1, z1);
    out[t] = r;
}

// ---------------------------------------------------------------------------
extern "C" void kernel_launch(void* const* d_in, const int* in_sizes, int n_in,
                              void* d_out, int out_size)
{
    const float* inputs    = (const float*)d_in[0];
    const float* pt_coords = (const float*)d_in[1];
    const int*   vidx      = (const int*)  d_in[2];
    const float* pinv      = (const float*)d_in[3];
    const float* w_mlp     = (const float*)d_in[4];
    const float* b_mlp     = (const float*)d_in[5];
    const float* g0        = (const float*)d_in[6];
    const float* be0       = (const float*)d_in[7];
    const float* m0        = (const float*)d_in[8];
    const float* v0        = (const float*)d_in[9];
    const float* k1        = (const float*)d_in[10];
    const float* cb1       = (const float*)d_in[11];
    const float* g1        = (const float*)d_in[12];
    const float* be1       = (const float*)d_in[13];
    const float* m1        = (const float*)d_in[14];
    const float* v1        = (const float*)d_in[15];
    const float* k2        = (const float*)d_in[16];
    const float* cb2       = (const float*)d_in[17];
    const float* g2        = (const float*)d_in[18];
    const float* be2       = (const float*)d_in[19];
    const float* m2        = (const float*)d_in[20];
    const float* v2        = (const float*)d_in[21];
    float* out = (float*)d_out;

    const int DSMEM = 82944;
    cudaFuncSetAttribute(conv_mma_kernel<1>,
                         cudaFuncAttributeMaxDynamicSharedMemorySize, DSMEM);
    cudaFuncSetAttribute(conv_mma_kernel<2>,
                         cudaFuncAttributeMaxDynamicSharedMemorySize, DSMEM);

    zero_vox_kernel<<<2048, 256>>>();
    build_W_kernel<<<(27*64*64 + 255) / 256, 256>>>(k1, 0);
    build_W_kernel<<<(27*64*64 + 255) / 256, 256>>>(k2, 1);
    mlp_kernel<<<(N_PTS + 15) / 16, 256>>>(inputs, w_mlp, b_mlp, g0, be0, m0, v0);
    scatter_kernel<<<(N_PTS * 64 + 255) / 256, 256>>>(inputs, vidx);
    build_P_kernel<<<(GRIDVOL * 16 + 255) / 256, 256>>>(pinv);

    conv_mma_kernel<1><<<NTILE, 256, DSMEM>>>(cb1, g1, be1, m1, v1);
    conv_mma_kernel<2><<<NTILE, 256, DSMEM>>>(cb2, g2, be2, m2, v2);

    gather_kernel<<<(N_PTS * 64 + 255) / 256, 256>>>(pt_coords, out);
}

// round 4
// speedup vs baseline: 2.7738x; 1.2129x over previous
#include <cuda_runtime.h>
#include <cstdint>

#define N_PTS 200000
#define GRIDVOL (64*64*64)

// padded 66^3 flat grid + guard rows so every tap-shifted 258-row window
// stays in-bounds.
#define PXS 4356            // x stride (66*66)
#define PYS 66              // y stride
#define PTOT 287496         // 66^3
#define GUARD 4800
#define PROWS (PTOT + 2*GUARD)   // 297096
#define NTILE2 1124         // ceil(PTOT/256)
#define NTILE_M 1563        // ceil(N_PTS/128)

// ---- scratch (allocation-free: __device__ globals, zero-initialized) ----
__device__ float g_vox[GRIDVOL*64];       // scatter accumulation (fp32)
__device__ float g_P[PROWS*64];           // conv1 input, tf32-rounded (pads 0)
__device__ float g_Q[PROWS*64];           // conv2 input, tf32-rounded (pads 0)
__device__ float g_h2p[PROWS*64];         // conv2 output, padded fp32
__device__ float g_mlp[N_PTS*64];         // point branch
__device__ float g_W[2][27*64*64];        // weights [tap][cout][cin], tf32-rounded

// ---------------------------------------------------------------------------
// helpers
// ---------------------------------------------------------------------------
__device__ __forceinline__ uint32_t smem_u32(const void* p) {
    uint32_t a;
    asm("{ .reg .u64 t; cvta.to.shared.u64 t, %1; cvt.u32.u64 %0, t; }"
        : "=r"(a) : "l"(p));
    return a;
}
__device__ __forceinline__ float tf32r(float x) {
    uint32_t u;
    asm("cvt.rna.tf32.f32 %0, %1;" : "=r"(u) : "f"(x));
    return __uint_as_float(u);
}
__device__ __forceinline__ void ldsm_x4(uint32_t* r, uint32_t a) {
    asm volatile("ldmatrix.sync.aligned.m8n8.x4.shared.b16 {%0,%1,%2,%3}, [%4];"
        : "=r"(r[0]), "=r"(r[1]), "=r"(r[2]), "=r"(r[3]) : "r"(a));
}
__device__ __forceinline__ void ldsm_x2(uint32_t* r, uint32_t a) {
    asm volatile("ldmatrix.sync.aligned.m8n8.x2.shared.b16 {%0,%1}, [%2];"
        : "=r"(r[0]), "=r"(r[1]) : "r"(a));
}
__device__ __forceinline__ void mma_tf32(float* c, const uint32_t* a,
                                         const uint32_t* b) {
    asm volatile("mma.sync.aligned.m16n8k8.row.col.f32.tf32.tf32.f32 "
        "{%0,%1,%2,%3}, {%4,%5,%6,%7}, {%8,%9}, {%0,%1,%2,%3};"
        : "+f"(c[0]), "+f"(c[1]), "+f"(c[2]), "+f"(c[3])
        : "r"(a[0]), "r"(a[1]), "r"(a[2]), "r"(a[3]), "r"(b[0]), "r"(b[1]));
}

// ---------------------------------------------------------------------------
__global__ void zero_vox_kernel() {
    float4* p = (float4*)g_vox;
    const int n4 = GRIDVOL * 64 / 4;
    for (int i = blockIdx.x * blockDim.x + threadIdx.x; i < n4;
         i += gridDim.x * blockDim.x)
        p[i] = make_float4(0.f, 0.f, 0.f, 0.f);
}

// ---------------------------------------------------------------------------
// voxelize: scatter-add raw inputs into g_vox
// ---------------------------------------------------------------------------
__global__ void scatter_kernel(const float* __restrict__ in,
                               const int* __restrict__ vidx)
{
    int t = blockIdx.x * blockDim.x + threadIdx.x;
    if (t >= N_PTS * 64) return;
    int n = t >> 6;
    int ix = vidx[n * 3 + 0];
    int iy = vidx[n * 3 + 1];
    int iz = vidx[n * 3 + 2];
    atomicAdd(&g_vox[(((((ix << 6) + iy) << 6) + iz) << 6) + (t & 63)], in[t]);
}

// ---------------------------------------------------------------------------
// weight prep: k [tap][cin][cout] fp32 -> [tap][cout][cin] tf32-rounded fp32
// ---------------------------------------------------------------------------
__global__ void build_W_kernel(const float* __restrict__ k, int stage) {
    int i = blockIdx.x * blockDim.x + threadIdx.x;
    if (i >= 27 * 64 * 64) return;
    int tap = i >> 12, r = i & 4095, cin = r >> 6, cout = r & 63;
    g_W[stage][(tap << 12) + (cout << 6) + cin] = tf32r(k[i]);
}

// ---------------------------------------------------------------------------
// build padded tf32 conv1 input: P = round(g_vox * pinv)
// ---------------------------------------------------------------------------
__global__ void build_P_kernel(const float* __restrict__ pinv) {
    int t = blockIdx.x * blockDim.x + threadIdx.x;
    if (t >= GRIDVOL * 16) return;
    int vox = t >> 4, c4 = (t & 15) << 2;
    float s = pinv[vox];
    float4 v = *(const float4*)&g_vox[(vox << 6) + c4];
    int x = vox >> 12, y = (vox >> 6) & 63, z = vox & 63;
    long p = (long)(x + 1) * PXS + (y + 1) * PYS + (z + 1);
    float4 o;
    o.x = tf32r(v.x * s); o.y = tf32r(v.y * s);
    o.z = tf32r(v.z * s); o.w = tf32r(v.w * s);
    *(float4*)&g_P[(GUARD + p) * 64 + c4] = o;
}

// ---------------------------------------------------------------------------
// MLP as tf32 mma GEMM: CTA = 128 points x 64 couts, 8 warps (32x32 tiles)
// smem: A 128x256B swizzled at 0; W(transposed) 64x256B at 32768
// ---------------------------------------------------------------------------
__global__ __launch_bounds__(256) void mlp_mma_kernel(
    const float* __restrict__ in, const float* __restrict__ w,
    const float* __restrict__ b,
    const float* __restrict__ g0, const float* __restrict__ be0,
    const float* __restrict__ m0v, const float* __restrict__ v0)
{
    extern __shared__ char dyn[];
    __shared__ float s_ep[192];
    const int tid = threadIdx.x, lane = tid & 31, warp = tid >> 5;
    const int m0 = (warp >> 1) * 32, n0 = (warp & 1) * 32;
    const uint32_t S0 = smem_u32(dyn);

    if (tid < 64) {
        float sc = g0[tid] * rsqrtf(v0[tid] + 1e-3f);
        s_ep[tid] = b[tid];
        s_ep[64 + tid] = sc;
        s_ep[128 + tid] = be0[tid] - m0v[tid] * sc;
    }

    // stage A (cvt to tf32)
    const uint4* in4 = (const uint4*)in;
    for (int i = tid; i < 2048; i += 256) {
        int row = i >> 4, c = i & 15;
        long n = (long)blockIdx.x * 128 + row;
        float4 v = make_float4(0.f, 0.f, 0.f, 0.f);
        if (n < N_PTS) {
            uint4 raw = in4[n * 16 + c];
            v.x = tf32r(__uint_as_float(raw.x));
            v.y = tf32r(__uint_as_float(raw.y));
            v.z = tf32r(__uint_as_float(raw.z));
            v.w = tf32r(__uint_as_float(raw.w));
        }
        *(float4*)(dyn + row * 256 + (((uint32_t)(c ^ (row & 7))) << 4)) = v;
    }
    // stage W transposed: w[ci][co] -> smem[co][ci]
    for (int i = tid; i < 4096; i += 256) {
        int ci = i >> 6, co = i & 63;
        uint32_t d = co * 256 + ((((uint32_t)(ci >> 2)) ^ (co & 7)) << 4)
                     + (ci & 3) * 4;
        *(float*)(dyn + 32768 + d) = tf32r(w[i]);
    }
    __syncthreads();

    float acc[2][4][4];
#pragma unroll
    for (int a = 0; a < 2; ++a)
#pragma unroll
        for (int x = 0; x < 4; ++x)
#pragma unroll
            for (int c = 0; c < 4; ++c) acc[a][x][c] = 0.f;

    const int arow = lane & 15, asel = lane >> 4;
    const int brow = lane & 7, bsel = (lane >> 3) & 1;
#pragma unroll
    for (int kc = 0; kc < 8; ++kc) {
        uint32_t af[2][4], bf[4][2];
#pragma unroll
        for (int mt = 0; mt < 2; ++mt) {
            int row = m0 + mt * 16 + arow;
            ldsm_x4(af[mt], S0 + row * 256 +
                    (((uint32_t)((kc * 2 + asel) ^ (row & 7))) << 4));
        }
#pragma unroll
        for (int nt = 0; nt < 4; ++nt) {
            int row = n0 + nt * 8 + brow;
            ldsm_x2(bf[nt], S0 + 32768 + row * 256 +
                    (((uint32_t)((kc * 2 + bsel) ^ (row & 7))) << 4));
        }
#pragma unroll
        for (int mt = 0; mt < 2; ++mt)
#pragma unroll
            for (int nt = 0; nt < 4; ++nt)
                mma_tf32(acc[mt][nt], af[mt], bf[nt]);
    }

    const int gr = lane >> 2, tig = lane & 3;
#pragma unroll
    for (int mt = 0; mt < 2; ++mt)
#pragma unroll
        for (int half = 0; half < 2; ++half) {
            long n = (long)blockIdx.x * 128 + m0 + mt * 16 + half * 8 + gr;
            if (n >= N_PTS) continue;
#pragma unroll
            for (int nt = 0; nt < 4; ++nt) {
                int col = n0 + nt * 8 + tig * 2;
                float v0r = fmaxf(acc[mt][nt][half * 2 + 0] + s_ep[col], 0.f)
                            * s_ep[64 + col] + s_ep[128 + col];
                float v1r = fmaxf(acc[mt][nt][half * 2 + 1] + s_ep[col + 1], 0.f)
                            * s_ep[64 + col + 1] + s_ep[128 + col + 1];
                float2 fv; fv.x = v0r; fv.y = v1r;
                *(float2*)&g_mlp[n * 64 + col] = fv;
            }
        }
}

// ---------------------------------------------------------------------------
// tf32 mma implicit-GEMM conv. CTA = 256 padded rows x 64 couts, 8 warps,
// warp tile 64x32 (4Mx2N warp grid). 9 stages (dx,dy): stage a 258-row A
// window + 3 dz taps of W into swizzled smem (A rows 256B = 64 tf32), then
// 3 dz x 8 kc of m16n8k8 tf32 mma.
// smem: A [0, 66048) (258x256), W [66560 + dz*16384)
// ---------------------------------------------------------------------------
template<int STAGE>
__global__ __launch_bounds__(256) void conv_mma_kernel(
    const float* __restrict__ cb, const float* __restrict__ g,
    const float* __restrict__ be, const float* __restrict__ m,
    const float* __restrict__ v)
{
    extern __shared__ char dyn[];
    __shared__ float s_ep[192];
    const int tid = threadIdx.x, lane = tid & 31, warp = tid >> 5;
    const int m0 = (warp >> 1) * 64, n0 = (warp & 1) * 32;
    const uint32_t S0 = smem_u32(dyn);
    const uint32_t SW = S0 + 66560;

    if (tid < 64) {
        float sc = g[tid] * rsqrtf(v[tid] + 1e-3f);
        s_ep[tid] = cb[tid];
        s_ep[64 + tid] = sc;
        s_ep[128 + tid] = be[tid] - m[tid] * sc;
    }

    const float* __restrict__ SRC = (STAGE == 1) ? g_P : g_Q;
    const uint4* __restrict__ Wsrc = (const uint4*)g_W[STAGE - 1];

    float acc[4][4][4];
#pragma unroll
    for (int a = 0; a < 4; ++a)
#pragma unroll
        for (int x = 0; x < 4; ++x)
#pragma unroll
            for (int c = 0; c < 4; ++c) acc[a][x][c] = 0.f;

    const int arow = lane & 15, asel = lane >> 4;
    const int brow = lane & 7, bsel = (lane >> 3) & 1;

    for (int s = 0; s < 9; ++s) {
        const int dx = s / 3, dy = s % 3, tap0 = s * 3;
        __syncthreads();
        // ---- stage A window: 258 rows x 16 units ----
        const long w0 = (long)GUARD + (long)blockIdx.x * 256
                        + (long)(dx - 1) * PXS + (dy - 1) * PYS - 1;
        const uint4* asrc = (const uint4*)SRC + w0 * 16;
        for (int i = tid; i < 4128; i += 256) {
            int row = i >> 4, c = i & 15;
            *(uint4*)(dyn + row * 256 + (((uint32_t)(c ^ (row & 7))) << 4))
                = asrc[i];
        }
        // ---- stage W: 3 taps x 64 rows x 16 units ----
        for (int i = tid; i < 3072; i += 256) {
            int t3 = i >> 10, r = (i >> 4) & 63, c = i & 15;
            *(uint4*)(dyn + 66560 + t3 * 16384 + r * 256 +
                      (((uint32_t)(c ^ (r & 7))) << 4))
                = Wsrc[(tap0 + t3) * 1024 + r * 16 + c];
        }
        __syncthreads();

        for (int dz = 0; dz < 3; ++dz) {
#pragma unroll
            for (int kc = 0; kc < 8; ++kc) {
                uint32_t af[4][4], bf[4][2];
#pragma unroll
                for (int mt = 0; mt < 4; ++mt) {
                    int row = dz + m0 + mt * 16 + arow;
                    ldsm_x4(af[mt], S0 + row * 256 +
                            (((uint32_t)((kc * 2 + asel) ^ (row & 7))) << 4));
                }
#pragma unroll
                for (int nt = 0; nt < 4; ++nt) {
                    int row = n0 + nt * 8 + brow;
                    ldsm_x2(bf[nt], SW + dz * 16384 + row * 256 +
                            (((uint32_t)((kc * 2 + bsel) ^ (row & 7))) << 4));
                }
#pragma unroll
                for (int mt = 0; mt < 4; ++mt)
#pragma unroll
                    for (int nt = 0; nt < 4; ++nt)
                        mma_tf32(acc[mt][nt], af[mt], bf[nt]);
            }
        }
    }

    // ---- epilogue: bias + relu + BN ----
    const int gr = lane >> 2, tig = lane & 3;
#pragma unroll
    for (int mt = 0; mt < 4; ++mt)
#pragma unroll
        for (int half = 0; half < 2; ++half) {
            int rl = m0 + mt * 16 + half * 8 + gr;
            long p = (long)blockIdx.x * 256 + rl;
            if (STAGE == 1) {
                bool valid = (p < PTOT);
                if (valid) {
                    int x = (int)(p / PXS);
                    int rem = (int)(p - (long)x * PXS);
                    int y = rem / PYS, z = rem - y * PYS;
                    valid = (x >= 1) && (x <= 64) && (y >= 1) && (y <= 64)
                            && (z >= 1) && (z <= 64);
                }
                if (!valid) continue;   // pads of g_Q must stay zero
            }
            long base = (GUARD + p) * 64;
#pragma unroll
            for (int nt = 0; nt < 4; ++nt) {
                int col = n0 + nt * 8 + tig * 2;
                float v0r = fmaxf(acc[mt][nt][half * 2 + 0] + s_ep[col], 0.f)
                            * s_ep[64 + col] + s_ep[128 + col];
                float v1r = fmaxf(acc[mt][nt][half * 2 + 1] + s_ep[col + 1], 0.f)
                            * s_ep[64 + col + 1] + s_ep[128 + col + 1];
                float2 fv;
                if (STAGE == 1) { fv.x = tf32r(v0r); fv.y = tf32r(v1r); }
                else            { fv.x = v0r;        fv.y = v1r; }
                if (STAGE == 1) *(float2*)&g_Q[base + col]   = fv;
                else            *(float2*)&g_h2p[base + col] = fv;
            }
        }
}

// ---------------------------------------------------------------------------
// devoxelize: trilinear gather from padded g_h2p + residual add of g_mlp
// ---------------------------------------------------------------------------
__global__ void gather_kernel(const float* __restrict__ coords,
                              float* __restrict__ out)
{
    int t = blockIdx.x * blockDim.x + threadIdx.x;
    if (t >= N_PTS * 64) return;
    int n = t >> 6, c = t & 63;
    float px = fminf(fmaxf(coords[n * 3 + 0], 0.f), 63.f);
    float py = fminf(fmaxf(coords[n * 3 + 1], 0.f), 63.f);
    float pz = fminf(fmaxf(coords[n * 3 + 2], 0.f), 63.f);
    float fx = floorf(px), fy = floorf(py), fz = floorf(pz);
    int x0 = (int)fx, y0 = (int)fy, z0 = (int)fz;
    int x1 = min(x0 + 1, 63), y1 = min(y0 + 1, 63), z1 = min(z0 + 1, 63);
    float tx = px - fx, ty = py - fy, tz = pz - fz;
    auto at = [&](int x, int y, int z) {
        long row = (long)GUARD + (long)(x + 1) * PXS + (y + 1) * PYS + (z + 1);
        return g_h2p[row * 64 + c];
    };
    float r = g_mlp[t];
    r += (1.f - tx) * (1.f - ty) * (1.f - tz) * at(x0, y0, z0);
    r += (1.f - tx) * (1.f - ty) * tz          * at(x0, y0, z1);
    r += (1.f - tx) * ty          * (1.f - tz) * at(x0, y1, z0);
    r += (1.f - tx) * ty          * tz          * at(x0, y1, z1);
    r += tx          * (1.f - ty) * (1.f - tz) * at(x1, y0, z0);
    r += tx          * (1.f - ty) * tz          * at(x1, y0, z1);
    r += tx          * ty          * (1.f - tz) * at(x1, y1, z0);
    r += tx          * ty          * tz          * at(x1, y1, z1);
    out[t] = r;
}

// ---------------------------------------------------------------------------
extern "C" void kernel_launch(void* const* d_in, const int* in_sizes, int n_in,
                              void* d_out, int out_size)
{
    const float* inputs    = (const float*)d_in[0];
    const float* pt_coords = (const float*)d_in[1];
    const int*   vidx      = (const int*)  d_in[2];
    const float* pinv      = (const float*)d_in[3];
    const float* w_mlp     = (const float*)d_in[4];
    const float* b_mlp     = (const float*)d_in[5];
    const float* g0        = (const float*)d_in[6];
    const float* be0       = (const float*)d_in[7];
    const float* m0        = (const float*)d_in[8];
    const float* v0        = (const float*)d_in[9];
    const float* k1        = (const float*)d_in[10];
    const float* cb1       = (const float*)d_in[11];
    const float* g1        = (const float*)d_in[12];
    const float* be1       = (const float*)d_in[13];
    const float* m1        = (const float*)d_in[14];
    const float* v1        = (const float*)d_in[15];
    const float* k2        = (const float*)d_in[16];
    const float* cb2       = (const float*)d_in[17];
    const float* g2        = (const float*)d_in[18];
    const float* be2       = (const float*)d_in[19];
    const float* m2        = (const float*)d_in[20];
    const float* v2        = (const float*)d_in[21];
    float* out = (float*)d_out;

    const int DSMEM_CONV = 66560 + 3 * 16384;   // 115712
    const int DSMEM_MLP  = 49152;
    cudaFuncSetAttribute(conv_mma_kernel<1>,
                         cudaFuncAttributeMaxDynamicSharedMemorySize, DSMEM_CONV);
    cudaFuncSetAttribute(conv_mma_kernel<2>,
                         cudaFuncAttributeMaxDynamicSharedMemorySize, DSMEM_CONV);
    cudaFuncSetAttribute(mlp_mma_kernel,
                         cudaFuncAttributeMaxDynamicSharedMemorySize, DSMEM_MLP);

    zero_vox_kernel<<<2048, 256>>>();
    build_W_kernel<<<432, 256>>>(k1, 0);
    build_W_kernel<<<432, 256>>>(k2, 1);
    mlp_mma_kernel<<<NTILE_M, 256, DSMEM_MLP>>>(inputs, w_mlp, b_mlp,
                                                g0, be0, m0, v0);
    scatter_kernel<<<(N_PTS * 64 + 255) / 256, 256>>>(inputs, vidx);
    build_P_kernel<<<(GRIDVOL * 16 + 255) / 256, 256>>>(pinv);

    conv_mma_kernel<1><<<NTILE2, 256, DSMEM_CONV>>>(cb1, g1, be1, m1, v1);
    conv_mma_kernel<2><<<NTILE2, 256, DSMEM_CONV>>>(cb2, g2, be2, m2, v2);

    gather_kernel<<<(N_PTS * 64 + 255) / 256, 256>>>(pt_coords, out);
}

// round 6
// speedup vs baseline: 3.4109x; 1.2297x over previous
#include <cuda_runtime.h>
#include <cstdint>

#define N_PTS 200000
#define GRIDVOL (64*64*64)

// padded 66^3 flat grid + guard rows so every tap-shifted 258-row window
// stays in-bounds.
#define PXS 4356            // x stride (66*66)
#define PYS 66              // y stride
#define PTOT 287496         // 66^3
#define GUARD 4800
#define PROWS (PTOT + 2*GUARD)   // 297096
#define NTILE2 1124         // ceil(PTOT/256)
#define NTILE_M 1563        // ceil(N_PTS/128)

// conv smem: per buffer A 258*256 + W 3*16384
#define ABYTES 66048
#define WBYTES 49152
#define BUFBYTES (ABYTES + WBYTES)          // 115200
#define DSMEM_CONV (2 * BUFBYTES)           // 230400

// ---- scratch (allocation-free: __device__ globals, zero-initialized) ----
__device__ float g_vox[GRIDVOL*64];       // scatter accumulation (fp32)
__device__ float g_P[PROWS*64];           // conv1 input, tf32-rounded (pads 0)
__device__ float g_Q[PROWS*64];           // conv2 input, tf32-rounded (pads 0)
__device__ float g_h2p[PROWS*64];         // conv2 output, padded fp32
__device__ float g_mlp[N_PTS*64];         // point branch
__device__ float g_W[2][27*64*64];        // weights [tap][cout][cin], tf32-rounded

// ---------------------------------------------------------------------------
// helpers
// ---------------------------------------------------------------------------
__device__ __forceinline__ uint32_t smem_u32(const void* p) {
    uint32_t a;
    asm("{ .reg .u64 t; cvta.to.shared.u64 t, %1; cvt.u32.u64 %0, t; }"
        : "=r"(a) : "l"(p));
    return a;
}
__device__ __forceinline__ float tf32r(float x) {
    uint32_t u;
    asm("cvt.rna.tf32.f32 %0, %1;" : "=r"(u) : "f"(x));
    return __uint_as_float(u);
}
__device__ __forceinline__ void ldsm_x4(uint32_t* r, uint32_t a) {
    asm volatile("ldmatrix.sync.aligned.m8n8.x4.shared.b16 {%0,%1,%2,%3}, [%4];"
        : "=r"(r[0]), "=r"(r[1]), "=r"(r[2]), "=r"(r[3]) : "r"(a));
}
__device__ __forceinline__ void ldsm_x2(uint32_t* r, uint32_t a) {
    asm volatile("ldmatrix.sync.aligned.m8n8.x2.shared.b16 {%0,%1}, [%2];"
        : "=r"(r[0]), "=r"(r[1]) : "r"(a));
}
__device__ __forceinline__ void mma_tf32(float* c, const uint32_t* a,
                                         const uint32_t* b) {
    asm volatile("mma.sync.aligned.m16n8k8.row.col.f32.tf32.tf32.f32 "
        "{%0,%1,%2,%3}, {%4,%5,%6,%7}, {%8,%9}, {%0,%1,%2,%3};"
        : "+f"(c[0]), "+f"(c[1]), "+f"(c[2]), "+f"(c[3])
        : "r"(a[0]), "r"(a[1]), "r"(a[2]), "r"(a[3]), "r"(b[0]), "r"(b[1]));
}
#define CP_ASYNC16(dst, src) \
    asm volatile("cp.async.cg.shared.global [%0], [%1], 16;" \
        :: "r"(dst), "l"(src) : "memory")
#define CP_COMMIT() asm volatile("cp.async.commit_group;" ::: "memory")
#define CP_WAIT(n)  asm volatile("cp.async.wait_group %0;" :: "n"(n) : "memory")

// ---------------------------------------------------------------------------
__global__ void zero_vox_kernel() {
    float4* p = (float4*)g_vox;
    const int n4 = GRIDVOL * 64 / 4;
    for (int i = blockIdx.x * blockDim.x + threadIdx.x; i < n4;
         i += gridDim.x * blockDim.x)
        p[i] = make_float4(0.f, 0.f, 0.f, 0.f);
}

// ---------------------------------------------------------------------------
// voxelize: scatter-add raw inputs into g_vox
// ---------------------------------------------------------------------------
__global__ void scatter_kernel(const float* __restrict__ in,
                               const int* __restrict__ vidx)
{
    int t = blockIdx.x * blockDim.x + threadIdx.x;
    if (t >= N_PTS * 64) return;
    int n = t >> 6;
    int ix = vidx[n * 3 + 0];
    int iy = vidx[n * 3 + 1];
    int iz = vidx[n * 3 + 2];
    atomicAdd(&g_vox[(((((ix << 6) + iy) << 6) + iz) << 6) + (t & 63)], in[t]);
}

// ---------------------------------------------------------------------------
// weight prep: k [tap][cin][cout] fp32 -> [tap][cout][cin] tf32-rounded fp32
// ---------------------------------------------------------------------------
__global__ void build_W_kernel(const float* __restrict__ k, int stage) {
    int i = blockIdx.x * blockDim.x + threadIdx.x;
    if (i >= 27 * 64 * 64) return;
    int tap = i >> 12, r = i & 4095, cin = r >> 6, cout = r & 63;
    g_W[stage][(tap << 12) + (cout << 6) + cin] = tf32r(k[i]);
}

// ---------------------------------------------------------------------------
// build padded tf32 conv1 input: P = round(g_vox * pinv)
// ---------------------------------------------------------------------------
__global__ void build_P_kernel(const float* __restrict__ pinv) {
    int t = blockIdx.x * blockDim.x + threadIdx.x;
    if (t >= GRIDVOL * 16) return;
    int vox = t >> 4, c4 = (t & 15) << 2;
    float s = pinv[vox];
    float4 v = *(const float4*)&g_vox[(vox << 6) + c4];
    int x = vox >> 12, y = (vox >> 6) & 63, z = vox & 63;
    long p = (long)(x + 1) * PXS + (y + 1) * PYS + (z + 1);
    float4 o;
    o.x = tf32r(v.x * s); o.y = tf32r(v.y * s);
    o.z = tf32r(v.z * s); o.w = tf32r(v.w * s);
    *(float4*)&g_P[(GUARD + p) * 64 + c4] = o;
}

// ---------------------------------------------------------------------------
// MLP as tf32 mma GEMM: CTA = 128 points x 64 couts, 8 warps (32x32 tiles)
// ---------------------------------------------------------------------------
__global__ __launch_bounds__(256) void mlp_mma_kernel(
    const float* __restrict__ in, const float* __restrict__ w,
    const float* __restrict__ b,
    const float* __restrict__ g0, const float* __restrict__ be0,
    const float* __restrict__ m0v, const float* __restrict__ v0)
{
    extern __shared__ char dyn[];
    __shared__ float s_ep[192];
    const int tid = threadIdx.x, lane = tid & 31, warp = tid >> 5;
    const int m0 = (warp >> 1) * 32, n0 = (warp & 1) * 32;
    const uint32_t S0 = smem_u32(dyn);

    if (tid < 64) {
        float sc = g0[tid] * rsqrtf(v0[tid] + 1e-3f);
        s_ep[tid] = b[tid];
        s_ep[64 + tid] = sc;
        s_ep[128 + tid] = be0[tid] - m0v[tid] * sc;
    }

    const uint4* in4 = (const uint4*)in;
    for (int i = tid; i < 2048; i += 256) {
        int row = i >> 4, c = i & 15;
        long n = (long)blockIdx.x * 128 + row;
        float4 v = make_float4(0.f, 0.f, 0.f, 0.f);
        if (n < N_PTS) {
            uint4 raw = in4[n * 16 + c];
            v.x = tf32r(__uint_as_float(raw.x));
            v.y = tf32r(__uint_as_float(raw.y));
            v.z = tf32r(__uint_as_float(raw.z));
            v.w = tf32r(__uint_as_float(raw.w));
        }
        *(float4*)(dyn + row * 256 + (((uint32_t)(c ^ (row & 7))) << 4)) = v;
    }
    for (int i = tid; i < 4096; i += 256) {
        int ci = i >> 6, co = i & 63;
        uint32_t d = co * 256 + ((((uint32_t)(ci >> 2)) ^ (co & 7)) << 4)
                     + (ci & 3) * 4;
        *(float*)(dyn + 32768 + d) = tf32r(w[i]);
    }
    __syncthreads();

    float acc[2][4][4];
#pragma unroll
    for (int a = 0; a < 2; ++a)
#pragma unroll
        for (int x = 0; x < 4; ++x)
#pragma unroll
            for (int c = 0; c < 4; ++c) acc[a][x][c] = 0.f;

    const int arow = lane & 15, asel = lane >> 4;
    const int brow = lane & 7, bsel = (lane >> 3) & 1;
#pragma unroll
    for (int kc = 0; kc < 8; ++kc) {
        uint32_t af[2][4], bf[4][2];
#pragma unroll
        for (int mt = 0; mt < 2; ++mt) {
            int row = m0 + mt * 16 + arow;
            ldsm_x4(af[mt], S0 + row * 256 +
                    (((uint32_t)((kc * 2 + asel) ^ (row & 7))) << 4));
        }
#pragma unroll
        for (int nt = 0; nt < 4; ++nt) {
            int row = n0 + nt * 8 + brow;
            ldsm_x2(bf[nt], S0 + 32768 + row * 256 +
                    (((uint32_t)((kc * 2 + bsel) ^ (row & 7))) << 4));
        }
#pragma unroll
        for (int mt = 0; mt < 2; ++mt)
#pragma unroll
            for (int nt = 0; nt < 4; ++nt)
                mma_tf32(acc[mt][nt], af[mt], bf[nt]);
    }

    const int gr = lane >> 2, tig = lane & 3;
#pragma unroll
    for (int mt = 0; mt < 2; ++mt)
#pragma unroll
        for (int half = 0; half < 2; ++half) {
            long n = (long)blockIdx.x * 128 + m0 + mt * 16 + half * 8 + gr;
            if (n >= N_PTS) continue;
#pragma unroll
            for (int nt = 0; nt < 4; ++nt) {
                int col = n0 + nt * 8 + tig * 2;
                float v0r = fmaxf(acc[mt][nt][half * 2 + 0] + s_ep[col], 0.f)
                            * s_ep[64 + col] + s_ep[128 + col];
                float v1r = fmaxf(acc[mt][nt][half * 2 + 1] + s_ep[col + 1], 0.f)
                            * s_ep[64 + col + 1] + s_ep[128 + col + 1];
                float2 fv; fv.x = v0r; fv.y = v1r;
                *(float2*)&g_mlp[n * 64 + col] = fv;
            }
        }
}

// ---------------------------------------------------------------------------
// Pipelined tf32 mma implicit-GEMM conv.
// CTA = 256 padded rows x 64 couts, 4 warps, warp tile 64x64.
// 9 stages (dx,dy), cp.async double-buffered: stage s+1 loads while stage s
// computes. Per stage: 3 dz x 8 kc x (4 ldsm_x4 A, 8 ldsm_x2 W, 32 mma).
// buffer layout: A [0, 66048) (258 rows x 256B swizzled), W [66048 + dz*16384)
// ---------------------------------------------------------------------------
template<int STAGE>
__device__ __forceinline__ void conv_stage_async(
    uint32_t Sbuf, const float* __restrict__ SRC,
    const uint4* __restrict__ Wsrc, long blockbase, int s, int tid)
{
    const int dx = s / 3, dy = s % 3, tap0 = s * 3;
    const long w0 = (long)GUARD + blockbase
                    + (long)(dx - 1) * PXS + (dy - 1) * PYS - 1;
    const uint4* asrc = (const uint4*)SRC + w0 * 16;
    for (int i = tid; i < 4128; i += 128) {
        int row = i >> 4, c = i & 15;
        uint32_t d = Sbuf + row * 256 + (((uint32_t)(c ^ (row & 7))) << 4);
        CP_ASYNC16(d, asrc + i);
    }
    for (int i = tid; i < 3072; i += 128) {
        int t3 = i >> 10, r = (i >> 4) & 63, c = i & 15;
        uint32_t d = Sbuf + ABYTES + t3 * 16384 + r * 256 +
                     (((uint32_t)(c ^ (r & 7))) << 4);
        CP_ASYNC16(d, Wsrc + (tap0 + t3) * 1024 + r * 16 + c);
    }
}

template<int STAGE>
__global__ __launch_bounds__(128) void conv_mma_kernel(
    const float* __restrict__ cb, const float* __restrict__ g,
    const float* __restrict__ be, const float* __restrict__ m,
    const float* __restrict__ v)
{
    extern __shared__ char dyn[];
    __shared__ float s_ep[192];
    const int tid = threadIdx.x, lane = tid & 31, warp = tid >> 5;
    const int m0 = warp * 64;
    const uint32_t S0 = smem_u32(dyn);

    if (tid < 64) {
        float sc = g[tid] * rsqrtf(v[tid] + 1e-3f);
        s_ep[tid] = cb[tid];
        s_ep[64 + tid] = sc;
        s_ep[128 + tid] = be[tid] - m[tid] * sc;
    }

    const float* __restrict__ SRC = (STAGE == 1) ? g_P : g_Q;
    const uint4* __restrict__ Wsrc = (const uint4*)g_W[STAGE - 1];
    const long blockbase = (long)blockIdx.x * 256;

    float acc[4][8][4];
#pragma unroll
    for (int a = 0; a < 4; ++a)
#pragma unroll
        for (int x = 0; x < 8; ++x)
#pragma unroll
            for (int c = 0; c < 4; ++c) acc[a][x][c] = 0.f;

    const int arow = lane & 15, asel = lane >> 4;
    const int brow = lane & 7, bsel = (lane >> 3) & 1;

    // prologue: stage 0 into buffer 0
    conv_stage_async<STAGE>(S0, SRC, Wsrc, blockbase, 0, tid);
    CP_COMMIT();

    for (int s = 0; s < 9; ++s) {
        if (s < 8) {
            conv_stage_async<STAGE>(S0 + ((s + 1) & 1) * BUFBYTES, SRC, Wsrc,
                                    blockbase, s + 1, tid);
            CP_COMMIT();
            CP_WAIT(1);
        } else {
            CP_WAIT(0);
        }
        __syncthreads();

        const uint32_t SA = S0 + (s & 1) * BUFBYTES;
        const uint32_t SW = SA + ABYTES;
        for (int dz = 0; dz < 3; ++dz) {
#pragma unroll
            for (int kc = 0; kc < 8; ++kc) {
                uint32_t af[4][4], bf[8][2];
#pragma unroll
                for (int mt = 0; mt < 4; ++mt) {
                    int row = dz + m0 + mt * 16 + arow;
                    ldsm_x4(af[mt], SA + row * 256 +
                            (((uint32_t)((kc * 2 + asel) ^ (row & 7))) << 4));
                }
#pragma unroll
                for (int nt = 0; nt < 8; ++nt) {
                    int row = nt * 8 + brow;
                    ldsm_x2(bf[nt], SW + dz * 16384 + row * 256 +
                            (((uint32_t)((kc * 2 + bsel) ^ (row & 7))) << 4));
                }
#pragma unroll
                for (int mt = 0; mt < 4; ++mt)
#pragma unroll
                    for (int nt = 0; nt < 8; ++nt)
                        mma_tf32(acc[mt][nt], af[mt], bf[nt]);
            }
        }
        __syncthreads();   // buffer s&1 free for stage s+2
    }

    // ---- epilogue: bias + relu + BN ----
    const int gr = lane >> 2, tig = lane & 3;
#pragma unroll
    for (int mt = 0; mt < 4; ++mt)
#pragma unroll
        for (int half = 0; half < 2; ++half) {
            int rl = m0 + mt * 16 + half * 8 + gr;
            long p = blockbase + rl;
            if (p >= PTOT) continue;
            if (STAGE == 1) {
                int x = (int)(p / PXS);
                int rem = (int)(p - (long)x * PXS);
                int y = rem / PYS, z = rem - y * PYS;
                bool valid = (x >= 1) && (x <= 64) && (y >= 1) && (y <= 64)
                             && (z >= 1) && (z <= 64);
                if (!valid) continue;   // pads of g_Q must stay zero
            }
            long base = (GUARD + p) * 64;
#pragma unroll
            for (int nt = 0; nt < 8; ++nt) {
                int col = nt * 8 + tig * 2;
                float v0r = fmaxf(acc[mt][nt][half * 2 + 0] + s_ep[col], 0.f)
                            * s_ep[64 + col] + s_ep[128 + col];
                float v1r = fmaxf(acc[mt][nt][half * 2 + 1] + s_ep[col + 1], 0.f)
                            * s_ep[64 + col + 1] + s_ep[128 + col + 1];
                float2 fv;
                if (STAGE == 1) { fv.x = tf32r(v0r); fv.y = tf32r(v1r); }
                else            { fv.x = v0r;        fv.y = v1r; }
                if (STAGE == 1) *(float2*)&g_Q[base + col]   = fv;
                else            *(float2*)&g_h2p[base + col] = fv;
            }
        }
}

// ---------------------------------------------------------------------------
// devoxelize: trilinear gather from padded g_h2p + residual add of g_mlp
// ---------------------------------------------------------------------------
__global__ void gather_kernel(const float* __restrict__ coords,
                              float* __restrict__ out)
{
    int t = blockIdx.x * blockDim.x + threadIdx.x;
    if (t >= N_PTS * 64) return;
    int n = t >> 6, c = t & 63;
    float px = fminf(fmaxf(coords[n * 3 + 0], 0.f), 63.f);
    float py = fminf(fmaxf(coords[n * 3 + 1], 0.f), 63.f);
    float pz = fminf(fmaxf(coords[n * 3 + 2], 0.f), 63.f);
    float fx = floorf(px), fy = floorf(py), fz = floorf(pz);
    int x0 = (int)fx, y0 = (int)fy, z0 = (int)fz;
    int x1 = min(x0 + 1, 63), y1 = min(y0 + 1, 63), z1 = min(z0 + 1, 63);
    float tx = px - fx, ty = py - fy, tz = pz - fz;
    auto at = [&](int x, int y, int z) {
        long row = (long)GUARD + (long)(x + 1) * PXS + (y + 1) * PYS + (z + 1);
        return g_h2p[row * 64 + c];
    };
    float r = g_mlp[t];
    r += (1.f - tx) * (1.f - ty) * (1.f - tz) * at(x0, y0, z0);
    r += (1.f - tx) * (1.f - ty) * tz          * at(x0, y0, z1);
    r += (1.f - tx) * ty          * (1.f - tz) * at(x0, y1, z0);
    r += (1.f - tx) * ty          * tz          * at(x0, y1, z1);
    r += tx          * (1.f - ty) * (1.f - tz) * at(x1, y0, z0);
    r += tx          * (1.f - ty) * tz          * at(x1, y0, z1);
    r += tx          * ty          * (1.f - tz) * at(x1, y1, z0);
    r += tx          * ty          * tz          * at(x1, y1, z1);
    out[t] = r;
}

// ---------------------------------------------------------------------------
extern "C" void kernel_launch(void* const* d_in, const int* in_sizes, int n_in,
                              void* d_out, int out_size)
{
    const float* inputs    = (const float*)d_in[0];
    const float* pt_coords = (const float*)d_in[1];
    const int*   vidx      = (const int*)  d_in[2];
    const float* pinv      = (const float*)d_in[3];
    const float* w_mlp     = (const float*)d_in[4];
    const float* b_mlp     = (const float*)d_in[5];
    const float* g0        = (const float*)d_in[6];
    const float* be0       = (const float*)d_in[7];
    const float* m0        = (const float*)d_in[8];
    const float* v0        = (const float*)d_in[9];
    const float* k1        = (const float*)d_in[10];
    const float* cb1       = (const float*)d_in[11];
    const float* g1        = (const float*)d_in[12];
    const float* be1       = (const float*)d_in[13];
    const float* m1        = (const float*)d_in[14];
    const float* v1        = (const float*)d_in[15];
    const float* k2        = (const float*)d_in[16];
    const float* cb2       = (const float*)d_in[17];
    const float* g2        = (const float*)d_in[18];
    const float* be2       = (const float*)d_in[19];
    const float* m2        = (const float*)d_in[20];
    const float* v2        = (const float*)d_in[21];
    float* out = (float*)d_out;

    const int DSMEM_MLP = 49152;
    cudaFuncSetAttribute(conv_mma_kernel<1>,
                         cudaFuncAttributeMaxDynamicSharedMemorySize, DSMEM_CONV);
    cudaFuncSetAttribute(conv_mma_kernel<2>,
                         cudaFuncAttributeMaxDynamicSharedMemorySize, DSMEM_CONV);
    cudaFuncSetAttribute(mlp_mma_kernel,
                         cudaFuncAttributeMaxDynamicSharedMemorySize, DSMEM_MLP);

    zero_vox_kernel<<<2048, 256>>>();
    build_W_kernel<<<432, 256>>>(k1, 0);
    build_W_kernel<<<432, 256>>>(k2, 1);
    mlp_mma_kernel<<<NTILE_M, 256, DSMEM_MLP>>>(inputs, w_mlp, b_mlp,
                                                g0, be0, m0, v0);
    scatter_kernel<<<(N_PTS * 64 + 255) / 256, 256>>>(inputs, vidx);
    build_P_kernel<<<(GRIDVOL * 16 + 255) / 256, 256>>>(pinv);

    conv_mma_kernel<1><<<NTILE2, 128, DSMEM_CONV>>>(cb1, g1, be1, m1, v1);
    conv_mma_kernel<2><<<NTILE2, 128, DSMEM_CONV>>>(cb2, g2, be2, m2, v2);

    gather_kernel<<<(N_PTS * 64 + 255) / 256, 256>>>(pt_coords, out);
}

// round 7
// speedup vs baseline: 4.9137x; 1.4406x over previous
#include <cuda_runtime.h>
#include <cuda_fp16.h>
#include <cstdint>

#define N_PTS 200000
#define GRIDVOL (64*64*64)

// padded 66^3 flat grid + guard rows so every tap-shifted 258-row window
// stays in-bounds.
#define PXS 4356            // x stride (66*66)
#define PYS 66              // y stride
#define PTOT 287496         // 66^3
#define GUARD 4800
#define PROWS (PTOT + 2*GUARD)   // 297096
#define NTILE2 1124         // ceil(PTOT/256)
#define NTILE_M 1563        // ceil(N_PTS/128)

// conv smem (fp16): per buffer A 258*128 + W 3*8192
#define ABYTES 33024
#define WBYTES 24576
#define BUFBYTES (ABYTES + WBYTES)          // 57600
#define DSMEM_CONV (2 * BUFBYTES)           // 115200

// ---- scratch (allocation-free: __device__ globals, zero-initialized) ----
__device__ float g_vox[GRIDVOL*64];       // scatter accumulation (fp32)
__device__ __half g_P[PROWS*64];          // conv1 input fp16 (pads stay 0)
__device__ __half g_Q[PROWS*64];          // conv2 input fp16 (pads stay 0)
__device__ float g_h2p[PROWS*64];         // conv2 output, padded fp32
__device__ float g_mlp[N_PTS*64];         // point branch
__device__ __half g_W[2][27*64*64];       // weights [tap][cout][cin] fp16

// ---------------------------------------------------------------------------
// helpers
// ---------------------------------------------------------------------------
__device__ __forceinline__ uint32_t smem_u32(const void* p) {
    uint32_t a;
    asm("{ .reg .u64 t; cvta.to.shared.u64 t, %1; cvt.u32.u64 %0, t; }"
        : "=r"(a) : "l"(p));
    return a;
}
__device__ __forceinline__ void ldsm_x4(uint32_t* r, uint32_t a) {
    asm volatile("ldmatrix.sync.aligned.m8n8.x4.shared.b16 {%0,%1,%2,%3}, [%4];"
        : "=r"(r[0]), "=r"(r[1]), "=r"(r[2]), "=r"(r[3]) : "r"(a));
}
__device__ __forceinline__ void ldsm_x2(uint32_t* r, uint32_t a) {
    asm volatile("ldmatrix.sync.aligned.m8n8.x2.shared.b16 {%0,%1}, [%2];"
        : "=r"(r[0]), "=r"(r[1]) : "r"(a));
}
__device__ __forceinline__ void mma_f16(float* c, const uint32_t* a,
                                        const uint32_t* b) {
    asm volatile("mma.sync.aligned.m16n8k16.row.col.f32.f16.f16.f32 "
        "{%0,%1,%2,%3}, {%4,%5,%6,%7}, {%8,%9}, {%0,%1,%2,%3};"
        : "+f"(c[0]), "+f"(c[1]), "+f"(c[2]), "+f"(c[3])
        : "r"(a[0]), "r"(a[1]), "r"(a[2]), "r"(a[3]), "r"(b[0]), "r"(b[1]));
}
#define CP_ASYNC16(dst, src) \
    asm volatile("cp.async.cg.shared.global [%0], [%1], 16;" \
        :: "r"(dst), "l"(src) : "memory")
#define CP_COMMIT() asm volatile("cp.async.commit_group;" ::: "memory")
#define CP_WAIT(n)  asm volatile("cp.async.wait_group %0;" :: "n"(n) : "memory")

// ---------------------------------------------------------------------------
__global__ void zero_vox_kernel() {
    float4* p = (float4*)g_vox;
    const int n4 = GRIDVOL * 64 / 4;
    for (int i = blockIdx.x * blockDim.x + threadIdx.x; i < n4;
         i += gridDim.x * blockDim.x)
        p[i] = make_float4(0.f, 0.f, 0.f, 0.f);
}

// ---------------------------------------------------------------------------
// voxelize: scatter-add raw inputs into g_vox
// ---------------------------------------------------------------------------
__global__ void scatter_kernel(const float* __restrict__ in,
                               const int* __restrict__ vidx)
{
    int t = blockIdx.x * blockDim.x + threadIdx.x;
    if (t >= N_PTS * 64) return;
    int n = t >> 6;
    int ix = vidx[n * 3 + 0];
    int iy = vidx[n * 3 + 1];
    int iz = vidx[n * 3 + 2];
    atomicAdd(&g_vox[(((((ix << 6) + iy) << 6) + iz) << 6) + (t & 63)], in[t]);
}

// ---------------------------------------------------------------------------
// weight prep: k [tap][cin][cout] fp32 -> [tap][cout][cin] fp16
// ---------------------------------------------------------------------------
__global__ void build_W_kernel(const float* __restrict__ k, int stage) {
    int i = blockIdx.x * blockDim.x + threadIdx.x;
    if (i >= 27 * 64 * 64) return;
    int tap = i >> 12, r = i & 4095, cin = r >> 6, cout = r & 63;
    g_W[stage][(tap << 12) + (cout << 6) + cin] = __float2half_rn(k[i]);
}

// ---------------------------------------------------------------------------
// build padded fp16 conv1 input: P = half(g_vox * pinv)
// ---------------------------------------------------------------------------
__global__ void build_P_kernel(const float* __restrict__ pinv) {
    int t = blockIdx.x * blockDim.x + threadIdx.x;
    if (t >= GRIDVOL * 16) return;
    int vox = t >> 4, c4 = (t & 15) << 2;
    float s = pinv[vox];
    float4 v = *(const float4*)&g_vox[(vox << 6) + c4];
    int x = vox >> 12, y = (vox >> 6) & 63, z = vox & 63;
    long p = (long)(x + 1) * PXS + (y + 1) * PYS + (z + 1);
    long idx = (GUARD + p) * 64 + c4;
    __half2 h0, h1;
    h0.x = __float2half_rn(v.x * s); h0.y = __float2half_rn(v.y * s);
    h1.x = __float2half_rn(v.z * s); h1.y = __float2half_rn(v.w * s);
    *(__half2*)&g_P[idx]     = h0;
    *(__half2*)&g_P[idx + 2] = h1;
}

// ---------------------------------------------------------------------------
// MLP as fp16 mma GEMM: CTA = 128 points x 64 couts, 8 warps (32x32 tiles)
// smem: A 128 rows x 128B swizzled at 0; W(transposed) 64 rows x 128B at 16384
// ---------------------------------------------------------------------------
__global__ __launch_bounds__(256) void mlp_mma_kernel(
    const float* __restrict__ in, const float* __restrict__ w,
    const float* __restrict__ b,
    const float* __restrict__ g0, const float* __restrict__ be0,
    const float* __restrict__ m0v, const float* __restrict__ v0)
{
    extern __shared__ char dyn[];
    __shared__ float s_ep[192];
    const int tid = threadIdx.x, lane = tid & 31, warp = tid >> 5;
    const int m0 = (warp >> 1) * 32, n0 = (warp & 1) * 32;
    const uint32_t S0 = smem_u32(dyn);

    if (tid < 64) {
        float sc = g0[tid] * rsqrtf(v0[tid] + 1e-3f);
        s_ep[tid] = b[tid];
        s_ep[64 + tid] = sc;
        s_ep[128 + tid] = be0[tid] - m0v[tid] * sc;
    }

    // stage A: convert fp32 -> fp16, 4 halfs per thread iteration
    const float4* in4 = (const float4*)in;
    for (int i = tid; i < 2048; i += 256) {
        int row = i >> 4, c = i & 15;   // c: 8-byte chunk (4 halfs)
        long n = (long)blockIdx.x * 128 + row;
        __half2 h0, h1;
        h0.x = h0.y = h1.x = h1.y = __float2half_rn(0.f);
        if (n < N_PTS) {
            float4 raw = in4[n * 16 + c];
            h0.x = __float2half_rn(raw.x); h0.y = __float2half_rn(raw.y);
            h1.x = __float2half_rn(raw.z); h1.y = __float2half_rn(raw.w);
        }
        uint32_t d = row * 128 + ((((uint32_t)(c >> 1)) ^ (row & 7)) << 4)
                     + (c & 1) * 8;
        *(__half2*)(dyn + d)     = h0;
        *(__half2*)(dyn + d + 4) = h1;
    }
    // stage W transposed: w[ci][co] -> smem[co][ci] fp16
    for (int i = tid; i < 4096; i += 256) {
        int ci = i >> 6, co = i & 63;
        uint32_t d = co * 128 + ((((uint32_t)(ci >> 3)) ^ (co & 7)) << 4)
                     + (ci & 7) * 2;
        *(__half*)(dyn + 16384 + d) = __float2half_rn(w[i]);
    }
    __syncthreads();

    float acc[2][4][4];
#pragma unroll
    for (int a = 0; a < 2; ++a)
#pragma unroll
        for (int x = 0; x < 4; ++x)
#pragma unroll
            for (int c = 0; c < 4; ++c) acc[a][x][c] = 0.f;

    const int arow = lane & 15, asel = lane >> 4;
    const int brow = lane & 7, bsel = (lane >> 3) & 1;
#pragma unroll
    for (int kc = 0; kc < 4; ++kc) {
        uint32_t af[2][4], bf[4][2];
#pragma unroll
        for (int mt = 0; mt < 2; ++mt) {
            int row = m0 + mt * 16 + arow;
            ldsm_x4(af[mt], S0 + row * 128 +
                    (((uint32_t)((kc * 2 + asel) ^ (row & 7))) << 4));
        }
#pragma unroll
        for (int nt = 0; nt < 4; ++nt) {
            int row = n0 + nt * 8 + brow;
            ldsm_x2(bf[nt], S0 + 16384 + row * 128 +
                    (((uint32_t)((kc * 2 + bsel) ^ (row & 7))) << 4));
        }
#pragma unroll
        for (int mt = 0; mt < 2; ++mt)
#pragma unroll
            for (int nt = 0; nt < 4; ++nt)
                mma_f16(acc[mt][nt], af[mt], bf[nt]);
    }

    const int gr = lane >> 2, tig = lane & 3;
#pragma unroll
    for (int mt = 0; mt < 2; ++mt)
#pragma unroll
        for (int half = 0; half < 2; ++half) {
            long n = (long)blockIdx.x * 128 + m0 + mt * 16 + half * 8 + gr;
            if (n >= N_PTS) continue;
#pragma unroll
            for (int nt = 0; nt < 4; ++nt) {
                int col = n0 + nt * 8 + tig * 2;
                float v0r = fmaxf(acc[mt][nt][half * 2 + 0] + s_ep[col], 0.f)
                            * s_ep[64 + col] + s_ep[128 + col];
                float v1r = fmaxf(acc[mt][nt][half * 2 + 1] + s_ep[col + 1], 0.f)
                            * s_ep[64 + col + 1] + s_ep[128 + col + 1];
                float2 fv; fv.x = v0r; fv.y = v1r;
                *(float2*)&g_mlp[n * 64 + col] = fv;
            }
        }
}

// ---------------------------------------------------------------------------
// Pipelined fp16 mma implicit-GEMM conv.
// CTA = 256 padded rows x 64 couts, 4 warps, warp tile 64x64.
// 9 stages (dx,dy), cp.async double-buffered. Per stage: 3 dz x 4 kc x
// (4 ldsm_x4 A, 8 ldsm_x2 W, 32 m16n8k16 mma) per warp.
// buffer: A [0, 33024) (258 rows x 128B swizzled), W [33024 + dz*8192)
// ---------------------------------------------------------------------------
template<int STAGE>
__device__ __forceinline__ void conv_stage_async(
    uint32_t Sbuf, const __half* __restrict__ SRC,
    const uint4* __restrict__ Wsrc, long blockbase, int s, int tid)
{
    const int dx = s / 3, dy = s % 3, tap0 = s * 3;
    const long w0 = (long)GUARD + blockbase
                    + (long)(dx - 1) * PXS + (dy - 1) * PYS - 1;
    const uint4* asrc = (const uint4*)SRC + w0 * 8;
    for (int i = tid; i < 2064; i += 128) {
        int row = i >> 3, c = i & 7;
        uint32_t d = Sbuf + row * 128 + (((uint32_t)(c ^ (row & 7))) << 4);
        CP_ASYNC16(d, asrc + i);
    }
    for (int i = tid; i < 1536; i += 128) {
        int t3 = i >> 9, r = (i >> 3) & 63, c = i & 7;
        uint32_t d = Sbuf + ABYTES + t3 * 8192 + r * 128 +
                     (((uint32_t)(c ^ (r & 7))) << 4);
        CP_ASYNC16(d, Wsrc + (tap0 + t3) * 512 + r * 8 + c);
    }
}

template<int STAGE>
__global__ __launch_bounds__(128) void conv_mma_kernel(
    const float* __restrict__ cb, const float* __restrict__ g,
    const float* __restrict__ be, const float* __restrict__ m,
    const float* __restrict__ v)
{
    extern __shared__ char dyn[];
    __shared__ float s_ep[192];
    const int tid = threadIdx.x, lane = tid & 31, warp = tid >> 5;
    const int m0 = warp * 64;
    const uint32_t S0 = smem_u32(dyn);

    if (tid < 64) {
        float sc = g[tid] * rsqrtf(v[tid] + 1e-3f);
        s_ep[tid] = cb[tid];
        s_ep[64 + tid] = sc;
        s_ep[128 + tid] = be[tid] - m[tid] * sc;
    }

    const __half* __restrict__ SRC = (STAGE == 1) ? g_P : g_Q;
    const uint4* __restrict__ Wsrc = (const uint4*)g_W[STAGE - 1];
    const long blockbase = (long)blockIdx.x * 256;

    float acc[4][8][4];
#pragma unroll
    for (int a = 0; a < 4; ++a)
#pragma unroll
        for (int x = 0; x < 8; ++x)
#pragma unroll
            for (int c = 0; c < 4; ++c) acc[a][x][c] = 0.f;

    const int arow = lane & 15, asel = lane >> 4;
    const int brow = lane & 7, bsel = (lane >> 3) & 1;

    // prologue: stage 0 into buffer 0
    conv_stage_async<STAGE>(S0, SRC, Wsrc, blockbase, 0, tid);
    CP_COMMIT();

    for (int s = 0; s < 9; ++s) {
        if (s < 8) {
            conv_stage_async<STAGE>(S0 + ((s + 1) & 1) * BUFBYTES, SRC, Wsrc,
                                    blockbase, s + 1, tid);
            CP_COMMIT();
            CP_WAIT(1);
        } else {
            CP_WAIT(0);
        }
        __syncthreads();

        const uint32_t SA = S0 + (s & 1) * BUFBYTES;
        const uint32_t SW = SA + ABYTES;
        for (int dz = 0; dz < 3; ++dz) {
#pragma unroll
            for (int kc = 0; kc < 4; ++kc) {
                uint32_t af[4][4], bf[8][2];
#pragma unroll
                for (int mt = 0; mt < 4; ++mt) {
                    int row = dz + m0 + mt * 16 + arow;
                    ldsm_x4(af[mt], SA + row * 128 +
                            (((uint32_t)((kc * 2 + asel) ^ (row & 7))) << 4));
                }
#pragma unroll
                for (int nt = 0; nt < 8; ++nt) {
                    int row = nt * 8 + brow;
                    ldsm_x2(bf[nt], SW + dz * 8192 + row * 128 +
                            (((uint32_t)((kc * 2 + bsel) ^ (row & 7))) << 4));
                }
#pragma unroll
                for (int mt = 0; mt < 4; ++mt)
#pragma unroll
                    for (int nt = 0; nt < 8; ++nt)
                        mma_f16(acc[mt][nt], af[mt], bf[nt]);
            }
        }
        __syncthreads();   // buffer s&1 free for stage s+2
    }

    // ---- epilogue: bias + relu + BN ----
    const int gr = lane >> 2, tig = lane & 3;
#pragma unroll
    for (int mt = 0; mt < 4; ++mt)
#pragma unroll
        for (int half = 0; half < 2; ++half) {
            int rl = m0 + mt * 16 + half * 8 + gr;
            long p = blockbase + rl;
            if (p >= PTOT) continue;
            if (STAGE == 1) {
                int x = (int)(p / PXS);
                int rem = (int)(p - (long)x * PXS);
                int y = rem / PYS, z = rem - y * PYS;
                bool valid = (x >= 1) && (x <= 64) && (y >= 1) && (y <= 64)
                             && (z >= 1) && (z <= 64);
                if (!valid) continue;   // pads of g_Q must stay zero
            }
            long base = (GUARD + p) * 64;
#pragma unroll
            for (int nt = 0; nt < 8; ++nt) {
                int col = nt * 8 + tig * 2;
                float v0r = fmaxf(acc[mt][nt][half * 2 + 0] + s_ep[col], 0.f)
                            * s_ep[64 + col] + s_ep[128 + col];
                float v1r = fmaxf(acc[mt][nt][half * 2 + 1] + s_ep[col + 1], 0.f)
                            * s_ep[64 + col + 1] + s_ep[128 + col + 1];
                if (STAGE == 1) {
                    __half2 hv;
                    hv.x = __float2half_rn(v0r);
                    hv.y = __float2half_rn(v1r);
                    *(__half2*)&g_Q[base + col] = hv;
                } else {
                    float2 fv; fv.x = v0r; fv.y = v1r;
                    *(float2*)&g_h2p[base + col] = fv;
                }
            }
        }
}

// ---------------------------------------------------------------------------
// devoxelize: trilinear gather from padded g_h2p + residual add of g_mlp
// ---------------------------------------------------------------------------
__global__ void gather_kernel(const float* __restrict__ coords,
                              float* __restrict__ out)
{
    int t = blockIdx.x * blockDim.x + threadIdx.x;
    if (t >= N_PTS * 64) return;
    int n = t >> 6, c = t & 63;
    float px = fminf(fmaxf(coords[n * 3 + 0], 0.f), 63.f);
    float py = fminf(fmaxf(coords[n * 3 + 1], 0.f), 63.f);
    float pz = fminf(fmaxf(coords[n * 3 + 2], 0.f), 63.f);
    float fx = floorf(px), fy = floorf(py), fz = floorf(pz);
    int x0 = (int)fx, y0 = (int)fy, z0 = (int)fz;
    int x1 = min(x0 + 1, 63), y1 = min(y0 + 1, 63), z1 = min(z0 + 1, 63);
    float tx = px - fx, ty = py - fy, tz = pz - fz;
    auto at = [&](int x, int y, int z) {
        long row = (long)GUARD + (long)(x + 1) * PXS + (y + 1) * PYS + (z + 1);
        return g_h2p[row * 64 + c];
    };
    float r = g_mlp[t];
    r += (1.f - tx) * (1.f - ty) * (1.f - tz) * at(x0, y0, z0);
    r += (1.f - tx) * (1.f - ty) * tz          * at(x0, y0, z1);
    r += (1.f - tx) * ty          * (1.f - tz) * at(x0, y1, z0);
    r += (1.f - tx) * ty          * tz          * at(x0, y1, z1);
    r += tx          * (1.f - ty) * (1.f - tz) * at(x1, y0, z0);
    r += tx          * (1.f - ty) * tz          * at(x1, y0, z1);
    r += tx          * ty          * (1.f - tz) * at(x1, y1, z0);
    r += tx          * ty          * tz          * at(x1, y1, z1);
    out[t] = r;
}

// ---------------------------------------------------------------------------
extern "C" void kernel_launch(void* const* d_in, const int* in_sizes, int n_in,
                              void* d_out, int out_size)
{
    const float* inputs    = (const float*)d_in[0];
    const float* pt_coords = (const float*)d_in[1];
    const int*   vidx      = (const int*)  d_in[2];
    const float* pinv      = (const float*)d_in[3];
    const float* w_mlp     = (const float*)d_in[4];
    const float* b_mlp     = (const float*)d_in[5];
    const float* g0        = (const float*)d_in[6];
    const float* be0       = (const float*)d_in[7];
    const float* m0        = (const float*)d_in[8];
    const float* v0        = (const float*)d_in[9];
    const float* k1        = (const float*)d_in[10];
    const float* cb1       = (const float*)d_in[11];
    const float* g1        = (const float*)d_in[12];
    const float* be1       = (const float*)d_in[13];
    const float* m1        = (const float*)d_in[14];
    const float* v1        = (const float*)d_in[15];
    const float* k2        = (const float*)d_in[16];
    const float* cb2       = (const float*)d_in[17];
    const float* g2        = (const float*)d_in[18];
    const float* be2       = (const float*)d_in[19];
    const float* m2        = (const float*)d_in[20];
    const float* v2        = (const float*)d_in[21];
    float* out = (float*)d_out;

    const int DSMEM_MLP = 24576;
    cudaFuncSetAttribute(conv_mma_kernel<1>,
                         cudaFuncAttributeMaxDynamicSharedMemorySize, DSMEM_CONV);
    cudaFuncSetAttribute(conv_mma_kernel<2>,
                         cudaFuncAttributeMaxDynamicSharedMemorySize, DSMEM_CONV);
    cudaFuncSetAttribute(mlp_mma_kernel,
                         cudaFuncAttributeMaxDynamicSharedMemorySize, DSMEM_MLP);

    zero_vox_kernel<<<2048, 256>>>();
    build_W_kernel<<<432, 256>>>(k1, 0);
    build_W_kernel<<<432, 256>>>(k2, 1);
    mlp_mma_kernel<<<NTILE_M, 256, DSMEM_MLP>>>(inputs, w_mlp, b_mlp,
                                                g0, be0, m0, v0);
    scatter_kernel<<<(N_PTS * 64 + 255) / 256, 256>>>(inputs, vidx);
    build_P_kernel<<<(GRIDVOL * 16 + 255) / 256, 256>>>(pinv);

    conv_mma_kernel<1><<<NTILE2, 128, DSMEM_CONV>>>(cb1, g1, be1, m1, v1);
    conv_mma_kernel<2><<<NTILE2, 128, DSMEM_CONV>>>(cb2, g2, be2, m2, v2);

    gather_kernel<<<(N_PTS * 64 + 255) / 256, 256>>>(pt_coords, out);
}

// round 8
// speedup vs baseline: 4.9302x; 1.0034x over previous
#include <cuda_runtime.h>
#include <cuda_fp16.h>
#include <cstdint>

#define N_PTS 200000
#define GRIDVOL (64*64*64)

// padded 66^3 flat grid + guard rows so every tap-shifted 258-row window
// stays in-bounds.
#define PXS 4356            // x stride (66*66)
#define PYS 66              // y stride
#define PTOT 287496         // 66^3
#define GUARD 4800
#define PROWS (PTOT + 2*GUARD)   // 297096
#define NTILE2 1124         // ceil(PTOT/256)
#define NTILE_M 1563        // ceil(N_PTS/128)

// conv smem (fp16): per buffer A 258*128 + W 3*8192
#define ABYTES 33024
#define WBYTES 24576
#define BUFBYTES (ABYTES + WBYTES)          // 57600
#define DSMEM_CONV (2 * BUFBYTES)           // 115200

// ---- scratch (allocation-free: __device__ globals, zero-initialized) ----
__device__ float g_vox[GRIDVOL*64];       // scatter accumulation (fp32)
__device__ __half g_P[PROWS*64];          // conv1 input fp16 (pads stay 0)
__device__ __half g_Q[PROWS*64];          // conv2 input fp16 (pads stay 0)
__device__ float g_h2p[PROWS*64];         // conv2 output, padded fp32
__device__ float g_mlp[N_PTS*64];         // point branch
__device__ __half g_W[2][27*64*64];       // weights [tap][cout][cin] fp16

// ---------------------------------------------------------------------------
// helpers
// ---------------------------------------------------------------------------
__device__ __forceinline__ uint32_t smem_u32(const void* p) {
    uint32_t a;
    asm("{ .reg .u64 t; cvta.to.shared.u64 t, %1; cvt.u32.u64 %0, t; }"
        : "=r"(a) : "l"(p));
    return a;
}
__device__ __forceinline__ void ldsm_x4(uint32_t* r, uint32_t a) {
    asm volatile("ldmatrix.sync.aligned.m8n8.x4.shared.b16 {%0,%1,%2,%3}, [%4];"
        : "=r"(r[0]), "=r"(r[1]), "=r"(r[2]), "=r"(r[3]) : "r"(a));
}
__device__ __forceinline__ void ldsm_x2(uint32_t* r, uint32_t a) {
    asm volatile("ldmatrix.sync.aligned.m8n8.x2.shared.b16 {%0,%1}, [%2];"
        : "=r"(r[0]), "=r"(r[1]) : "r"(a));
}
__device__ __forceinline__ void mma_f16(float* c, const uint32_t* a,
                                        const uint32_t* b) {
    asm volatile("mma.sync.aligned.m16n8k16.row.col.f32.f16.f16.f32 "
        "{%0,%1,%2,%3}, {%4,%5,%6,%7}, {%8,%9}, {%0,%1,%2,%3};"
        : "+f"(c[0]), "+f"(c[1]), "+f"(c[2]), "+f"(c[3])
        : "r"(a[0]), "r"(a[1]), "r"(a[2]), "r"(a[3]), "r"(b[0]), "r"(b[1]));
}
#define CP_ASYNC16(dst, src) \
    asm volatile("cp.async.cg.shared.global [%0], [%1], 16;" \
        :: "r"(dst), "l"(src) : "memory")
#define CP_COMMIT() asm volatile("cp.async.commit_group;" ::: "memory")
#define CP_WAIT(n)  asm volatile("cp.async.wait_group %0;" :: "n"(n) : "memory")

// ---------------------------------------------------------------------------
__global__ void zero_vox_kernel() {
    float4* p = (float4*)g_vox;
    const int n4 = GRIDVOL * 64 / 4;
    for (int i = blockIdx.x * blockDim.x + threadIdx.x; i < n4;
         i += gridDim.x * blockDim.x)
        p[i] = make_float4(0.f, 0.f, 0.f, 0.f);
}

// ---------------------------------------------------------------------------
// voxelize: scatter-add raw inputs into g_vox
// ---------------------------------------------------------------------------
__global__ void scatter_kernel(const float* __restrict__ in,
                               const int* __restrict__ vidx)
{
    int t = blockIdx.x * blockDim.x + threadIdx.x;
    if (t >= N_PTS * 64) return;
    int n = t >> 6;
    int ix = vidx[n * 3 + 0];
    int iy = vidx[n * 3 + 1];
    int iz = vidx[n * 3 + 2];
    atomicAdd(&g_vox[(((((ix << 6) + iy) << 6) + iz) << 6) + (t & 63)], in[t]);
}

// ---------------------------------------------------------------------------
// weight prep: k [tap][cin][cout] fp32 -> [tap][cout][cin] fp16
// ---------------------------------------------------------------------------
__global__ void build_W_kernel(const float* __restrict__ k, int stage) {
    int i = blockIdx.x * blockDim.x + threadIdx.x;
    if (i >= 27 * 64 * 64) return;
    int tap = i >> 12, r = i & 4095, cin = r >> 6, cout = r & 63;
    g_W[stage][(tap << 12) + (cout << 6) + cin] = __float2half_rn(k[i]);
}

// ---------------------------------------------------------------------------
// build padded fp16 conv1 input: P = half(g_vox * pinv)
// ---------------------------------------------------------------------------
__global__ void build_P_kernel(const float* __restrict__ pinv) {
    int t = blockIdx.x * blockDim.x + threadIdx.x;
    if (t >= GRIDVOL * 16) return;
    int vox = t >> 4, c4 = (t & 15) << 2;
    float s = pinv[vox];
    float4 v = *(const float4*)&g_vox[(vox << 6) + c4];
    int x = vox >> 12, y = (vox >> 6) & 63, z = vox & 63;
    long p = (long)(x + 1) * PXS + (y + 1) * PYS + (z + 1);
    long idx = (GUARD + p) * 64 + c4;
    __half2 h0, h1;
    h0.x = __float2half_rn(v.x * s); h0.y = __float2half_rn(v.y * s);
    h1.x = __float2half_rn(v.z * s); h1.y = __float2half_rn(v.w * s);
    *(__half2*)&g_P[idx]     = h0;
    *(__half2*)&g_P[idx + 2] = h1;
}

// ---------------------------------------------------------------------------
// MLP as fp16 mma GEMM: CTA = 128 points x 64 couts, 8 warps (32x32 tiles)
// smem: A 128 rows x 128B swizzled at 0; W(transposed) 64 rows x 128B at 16384
// ---------------------------------------------------------------------------
__global__ __launch_bounds__(256) void mlp_mma_kernel(
    const float* __restrict__ in, const float* __restrict__ w,
    const float* __restrict__ b,
    const float* __restrict__ g0, const float* __restrict__ be0,
    const float* __restrict__ m0v, const float* __restrict__ v0)
{
    extern __shared__ char dyn[];
    __shared__ float s_ep[192];
    const int tid = threadIdx.x, lane = tid & 31, warp = tid >> 5;
    const int m0 = (warp >> 1) * 32, n0 = (warp & 1) * 32;
    const uint32_t S0 = smem_u32(dyn);

    if (tid < 64) {
        float sc = g0[tid] * rsqrtf(v0[tid] + 1e-3f);
        s_ep[tid] = b[tid];
        s_ep[64 + tid] = sc;
        s_ep[128 + tid] = be0[tid] - m0v[tid] * sc;
    }

    // stage A: convert fp32 -> fp16, 4 halfs per thread iteration
    const float4* in4 = (const float4*)in;
    for (int i = tid; i < 2048; i += 256) {
        int row = i >> 4, c = i & 15;   // c: 8-byte chunk (4 halfs)
        long n = (long)blockIdx.x * 128 + row;
        __half2 h0, h1;
        h0.x = h0.y = h1.x = h1.y = __float2half_rn(0.f);
        if (n < N_PTS) {
            float4 raw = in4[n * 16 + c];
            h0.x = __float2half_rn(raw.x); h0.y = __float2half_rn(raw.y);
            h1.x = __float2half_rn(raw.z); h1.y = __float2half_rn(raw.w);
        }
        uint32_t d = row * 128 + ((((uint32_t)(c >> 1)) ^ (row & 7)) << 4)
                     + (c & 1) * 8;
        *(__half2*)(dyn + d)     = h0;
        *(__half2*)(dyn + d + 4) = h1;
    }
    // stage W transposed: w[ci][co] -> smem[co][ci] fp16
    for (int i = tid; i < 4096; i += 256) {
        int ci = i >> 6, co = i & 63;
        uint32_t d = co * 128 + ((((uint32_t)(ci >> 3)) ^ (co & 7)) << 4)
                     + (ci & 7) * 2;
        *(__half*)(dyn + 16384 + d) = __float2half_rn(w[i]);
    }
    __syncthreads();

    float acc[2][4][4];
#pragma unroll
    for (int a = 0; a < 2; ++a)
#pragma unroll
        for (int x = 0; x < 4; ++x)
#pragma unroll
            for (int c = 0; c < 4; ++c) acc[a][x][c] = 0.f;

    const int arow = lane & 15, asel = lane >> 4;
    const int brow = lane & 7, bsel = (lane >> 3) & 1;
#pragma unroll
    for (int kc = 0; kc < 4; ++kc) {
        uint32_t af[2][4], bf[4][2];
#pragma unroll
        for (int mt = 0; mt < 2; ++mt) {
            int row = m0 + mt * 16 + arow;
            ldsm_x4(af[mt], S0 + row * 128 +
                    (((uint32_t)((kc * 2 + asel) ^ (row & 7))) << 4));
        }
#pragma unroll
        for (int nt = 0; nt < 4; ++nt) {
            int row = n0 + nt * 8 + brow;
            ldsm_x2(bf[nt], S0 + 16384 + row * 128 +
                    (((uint32_t)((kc * 2 + bsel) ^ (row & 7))) << 4));
        }
#pragma unroll
        for (int mt = 0; mt < 2; ++mt)
#pragma unroll
            for (int nt = 0; nt < 4; ++nt)
                mma_f16(acc[mt][nt], af[mt], bf[nt]);
    }

    const int gr = lane >> 2, tig = lane & 3;
#pragma unroll
    for (int mt = 0; mt < 2; ++mt)
#pragma unroll
        for (int half = 0; half < 2; ++half) {
            long n = (long)blockIdx.x * 128 + m0 + mt * 16 + half * 8 + gr;
            if (n >= N_PTS) continue;
#pragma unroll
            for (int nt = 0; nt < 4; ++nt) {
                int col = n0 + nt * 8 + tig * 2;
                float v0r = fmaxf(acc[mt][nt][half * 2 + 0] + s_ep[col], 0.f)
                            * s_ep[64 + col] + s_ep[128 + col];
                float v1r = fmaxf(acc[mt][nt][half * 2 + 1] + s_ep[col + 1], 0.f)
                            * s_ep[64 + col + 1] + s_ep[128 + col + 1];
                float2 fv; fv.x = v0r; fv.y = v1r;
                *(float2*)&g_mlp[n * 64 + col] = fv;
            }
        }
}

// ---------------------------------------------------------------------------
// Pipelined fp16 mma implicit-GEMM conv.
// CTA = 256 padded rows x 64 couts, 4 warps, warp tile 64x64.
// 9 stages (dx,dy), cp.async double-buffered. Per stage: 3 dz x 4 kc x
// (4 ldsm_x4 A, 8 ldsm_x2 W, 32 m16n8k16 mma) per warp.
// buffer: A [0, 33024) (258 rows x 128B swizzled), W [33024 + dz*8192)
// ---------------------------------------------------------------------------
template<int STAGE>
__device__ __forceinline__ void conv_stage_async(
    uint32_t Sbuf, const __half* __restrict__ SRC,
    const uint4* __restrict__ Wsrc, long blockbase, int s, int tid)
{
    const int dx = s / 3, dy = s % 3, tap0 = s * 3;
    const long w0 = (long)GUARD + blockbase
                    + (long)(dx - 1) * PXS + (dy - 1) * PYS - 1;
    const uint4* asrc = (const uint4*)SRC + w0 * 8;
    for (int i = tid; i < 2064; i += 128) {
        int row = i >> 3, c = i & 7;
        uint32_t d = Sbuf + row * 128 + (((uint32_t)(c ^ (row & 7))) << 4);
        CP_ASYNC16(d, asrc + i);
    }
    for (int i = tid; i < 1536; i += 128) {
        int t3 = i >> 9, r = (i >> 3) & 63, c = i & 7;
        uint32_t d = Sbuf + ABYTES + t3 * 8192 + r * 128 +
                     (((uint32_t)(c ^ (r & 7))) << 4);
        CP_ASYNC16(d, Wsrc + (tap0 + t3) * 512 + r * 8 + c);
    }
}

template<int STAGE>
__global__ __launch_bounds__(128) void conv_mma_kernel(
    const float* __restrict__ cb, const float* __restrict__ g,
    const float* __restrict__ be, const float* __restrict__ m,
    const float* __restrict__ v)
{
    extern __shared__ char dyn[];
    __shared__ float s_ep[192];
    const int tid = threadIdx.x, lane = tid & 31, warp = tid >> 5;
    const int m0 = warp * 64;
    const uint32_t S0 = smem_u32(dyn);

    if (tid < 64) {
        float sc = g[tid] * rsqrtf(v[tid] + 1e-3f);
        s_ep[tid] = cb[tid];
        s_ep[64 + tid] = sc;
        s_ep[128 + tid] = be[tid] - m[tid] * sc;
    }

    const __half* __restrict__ SRC = (STAGE == 1) ? g_P : g_Q;
    const uint4* __restrict__ Wsrc = (const uint4*)g_W[STAGE - 1];
    const long blockbase = (long)blockIdx.x * 256;

    float acc[4][8][4];
#pragma unroll
    for (int a = 0; a < 4; ++a)
#pragma unroll
        for (int x = 0; x < 8; ++x)
#pragma unroll
            for (int c = 0; c < 4; ++c) acc[a][x][c] = 0.f;

    const int arow = lane & 15, asel = lane >> 4;
    const int brow = lane & 7, bsel = (lane >> 3) & 1;

    // prologue: stage 0 into buffer 0
    conv_stage_async<STAGE>(S0, SRC, Wsrc, blockbase, 0, tid);
    CP_COMMIT();

    for (int s = 0; s < 9; ++s) {
        if (s < 8) {
            conv_stage_async<STAGE>(S0 + ((s + 1) & 1) * BUFBYTES, SRC, Wsrc,
                                    blockbase, s + 1, tid);
            CP_COMMIT();
            CP_WAIT(1);
        } else {
            CP_WAIT(0);
        }
        __syncthreads();

        const uint32_t SA = S0 + (s & 1) * BUFBYTES;
        const uint32_t SW = SA + ABYTES;
        for (int dz = 0; dz < 3; ++dz) {
#pragma unroll
            for (int kc = 0; kc < 4; ++kc) {
                uint32_t af[4][4], bf[8][2];
#pragma unroll
                for (int mt = 0; mt < 4; ++mt) {
                    int row = dz + m0 + mt * 16 + arow;
                    ldsm_x4(af[mt], SA + row * 128 +
                            (((uint32_t)((kc * 2 + asel) ^ (row & 7))) << 4));
                }
#pragma unroll
                for (int nt = 0; nt < 8; ++nt) {
                    int row = nt * 8 + brow;
                    ldsm_x2(bf[nt], SW + dz * 8192 + row * 128 +
                            (((uint32_t)((kc * 2 + bsel) ^ (row & 7))) << 4));
                }
#pragma unroll
                for (int mt = 0; mt < 4; ++mt)
#pragma unroll
                    for (int nt = 0; nt < 8; ++nt)
                        mma_f16(acc[mt][nt], af[mt], bf[nt]);
            }
        }
        __syncthreads();   // buffer s&1 free for stage s+2
    }

    // ---- epilogue: bias + relu + BN ----
    const int gr = lane >> 2, tig = lane & 3;
#pragma unroll
    for (int mt = 0; mt < 4; ++mt)
#pragma unroll
        for (int half = 0; half < 2; ++half) {
            int rl = m0 + mt * 16 + half * 8 + gr;
            long p = blockbase + rl;
            if (p >= PTOT) continue;
            if (STAGE == 1) {
                int x = (int)(p / PXS);
                int rem = (int)(p - (long)x * PXS);
                int y = rem / PYS, z = rem - y * PYS;
                bool valid = (x >= 1) && (x <= 64) && (y >= 1) && (y <= 64)
                             && (z >= 1) && (z <= 64);
                if (!valid) continue;   // pads of g_Q must stay zero
            }
            long base = (GUARD + p) * 64;
#pragma unroll
            for (int nt = 0; nt < 8; ++nt) {
                int col = nt * 8 + tig * 2;
                float v0r = fmaxf(acc[mt][nt][half * 2 + 0] + s_ep[col], 0.f)
                            * s_ep[64 + col] + s_ep[128 + col];
                float v1r = fmaxf(acc[mt][nt][half * 2 + 1] + s_ep[col + 1], 0.f)
                            * s_ep[64 + col + 1] + s_ep[128 + col + 1];
                if (STAGE == 1) {
                    __half2 hv;
                    hv.x = __float2half_rn(v0r);
                    hv.y = __float2half_rn(v1r);
                    *(__half2*)&g_Q[base + col] = hv;
                } else {
                    float2 fv; fv.x = v0r; fv.y = v1r;
                    *(float2*)&g_h2p[base + col] = fv;
                }
            }
        }
}

// ---------------------------------------------------------------------------
// devoxelize: trilinear gather from padded g_h2p + residual add of g_mlp
// ---------------------------------------------------------------------------
__global__ void gather_kernel(const float* __restrict__ coords,
                              float* __restrict__ out)
{
    int t = blockIdx.x * blockDim.x + threadIdx.x;
    if (t >= N_PTS * 64) return;
    int n = t >> 6, c = t & 63;
    float px = fminf(fmaxf(coords[n * 3 + 0], 0.f), 63.f);
    float py = fminf(fmaxf(coords[n * 3 + 1], 0.f), 63.f);
    float pz = fminf(fmaxf(coords[n * 3 + 2], 0.f), 63.f);
    float fx = floorf(px), fy = floorf(py), fz = floorf(pz);
    int x0 = (int)fx, y0 = (int)fy, z0 = (int)fz;
    int x1 = min(x0 + 1, 63), y1 = min(y0 + 1, 63), z1 = min(z0 + 1, 63);
    float tx = px - fx, ty = py - fy, tz = pz - fz;
    auto at = [&](int x, int y, int z) {
        long row = (long)GUARD + (long)(x + 1) * PXS + (y + 1) * PYS + (z + 1);
        return g_h2p[row * 64 + c];
    };
    float r = g_mlp[t];
    r += (1.f - tx) * (1.f - ty) * (1.f - tz) * at(x0, y0, z0);
    r += (1.f - tx) * (1.f - ty) * tz          * at(x0, y0, z1);
    r += (1.f - tx) * ty          * (1.f - tz) * at(x0, y1, z0);
    r += (1.f - tx) * ty          * tz          * at(x0, y1, z1);
    r += tx          * (1.f - ty) * (1.f - tz) * at(x1, y0, z0);
    r += tx          * (1.f - ty) * tz          * at(x1, y0, z1);
    r += tx          * ty          * (1.f - tz) * at(x1, y1, z0);
    r += tx          * ty          * tz          * at(x1, y1, z1);
    out[t] = r;
}

// ---------------------------------------------------------------------------
extern "C" void kernel_launch(void* const* d_in, const int* in_sizes, int n_in,
                              void* d_out, int out_size)
{
    const float* inputs    = (const float*)d_in[0];
    const float* pt_coords = (const float*)d_in[1];
    const int*   vidx      = (const int*)  d_in[2];
    const float* pinv      = (const float*)d_in[3];
    const float* w_mlp     = (const float*)d_in[4];
    const float* b_mlp     = (const float*)d_in[5];
    const float* g0        = (const float*)d_in[6];
    const float* be0       = (const float*)d_in[7];
    const float* m0        = (const float*)d_in[8];
    const float* v0        = (const float*)d_in[9];
    const float* k1        = (const float*)d_in[10];
    const float* cb1       = (const float*)d_in[11];
    const float* g1        = (const float*)d_in[12];
    const float* be1       = (const float*)d_in[13];
    const float* m1        = (const float*)d_in[14];
    const float* v1        = (const float*)d_in[15];
    const float* k2        = (const float*)d_in[16];
    const float* cb2       = (const float*)d_in[17];
    const float* g2        = (const float*)d_in[18];
    const float* be2       = (const float*)d_in[19];
    const float* m2        = (const float*)d_in[20];
    const float* v2        = (const float*)d_in[21];
    float* out = (float*)d_out;

    const int DSMEM_MLP = 24576;
    cudaFuncSetAttribute(conv_mma_kernel<1>,
                         cudaFuncAttributeMaxDynamicSharedMemorySize, DSMEM_CONV);
    cudaFuncSetAttribute(conv_mma_kernel<2>,
                         cudaFuncAttributeMaxDynamicSharedMemorySize, DSMEM_CONV);
    cudaFuncSetAttribute(mlp_mma_kernel,
                         cudaFuncAttributeMaxDynamicSharedMemorySize, DSMEM_MLP);

    zero_vox_kernel<<<2048, 256>>>();
    build_W_kernel<<<432, 256>>>(k1, 0);
    build_W_kernel<<<432, 256>>>(k2, 1);
    mlp_mma_kernel<<<NTILE_M, 256, DSMEM_MLP>>>(inputs, w_mlp, b_mlp,
                                                g0, be0, m0, v0);
    scatter_kernel<<<(N_PTS * 64 + 255) / 256, 256>>>(inputs, vidx);
    build_P_kernel<<<(GRIDVOL * 16 + 255) / 256, 256>>>(pinv);

    conv_mma_kernel<1><<<NTILE2, 128, DSMEM_CONV>>>(cb1, g1, be1, m1, v1);
    conv_mma_kernel<2><<<NTILE2, 128, DSMEM_CONV>>>(cb2, g2, be2, m2, v2);

    gather_kernel<<<(N_PTS * 64 + 255) / 256, 256>>>(pt_coords, out);
}

// round 9
// speedup vs baseline: 5.1925x; 1.0532x over previous
#include <cuda_runtime.h>
#include <cuda_fp16.h>
#include <cstdint>

#define N_PTS 200000
#define GRIDVOL (64*64*64)

// padded 66^3 flat grid + guard rows so every tap-shifted 258-row window
// stays in-bounds.
#define PXS 4356            // x stride (66*66)
#define PYS 66              // y stride
#define PTOT 287496         // 66^3
#define GUARD 4800
#define PROWS (PTOT + 2*GUARD)   // 297096
#define NTILE2 1124         // ceil(PTOT/256)
#define NTILE_M 1563        // ceil(N_PTS/128)

// conv smem (fp16): per buffer A 258*128 + W 3*8192
#define ABYTES 33024
#define WBYTES 24576
#define BUFBYTES (ABYTES + WBYTES)          // 57600
#define DSMEM_CONV (2 * BUFBYTES)           // 115200

// ---- scratch (allocation-free: __device__ globals, zero-initialized) ----
__device__ float g_vox[GRIDVOL*64];       // scatter accumulation (fp32)
__device__ __half g_P[PROWS*64];          // conv1 input fp16 (pads stay 0)
__device__ __half g_Q[PROWS*64];          // conv2 input fp16 (pads stay 0)
__device__ __half g_h2p[PROWS*64];        // conv2 output fp16, padded
__device__ float g_mlp[N_PTS*64];         // point branch
__device__ __half g_W[2][27*64*64];       // weights [tap][cout][cin] fp16

// ---------------------------------------------------------------------------
// helpers
// ---------------------------------------------------------------------------
__device__ __forceinline__ uint32_t smem_u32(const void* p) {
    uint32_t a;
    asm("{ .reg .u64 t; cvta.to.shared.u64 t, %1; cvt.u32.u64 %0, t; }"
        : "=r"(a) : "l"(p));
    return a;
}
__device__ __forceinline__ void ldsm_x4(uint32_t* r, uint32_t a) {
    asm volatile("ldmatrix.sync.aligned.m8n8.x4.shared.b16 {%0,%1,%2,%3}, [%4];"
        : "=r"(r[0]), "=r"(r[1]), "=r"(r[2]), "=r"(r[3]) : "r"(a));
}
__device__ __forceinline__ void ldsm_x2(uint32_t* r, uint32_t a) {
    asm volatile("ldmatrix.sync.aligned.m8n8.x2.shared.b16 {%0,%1}, [%2];"
        : "=r"(r[0]), "=r"(r[1]) : "r"(a));
}
__device__ __forceinline__ void mma_f16(float* c, const uint32_t* a,
                                        const uint32_t* b) {
    asm volatile("mma.sync.aligned.m16n8k16.row.col.f32.f16.f16.f32 "
        "{%0,%1,%2,%3}, {%4,%5,%6,%7}, {%8,%9}, {%0,%1,%2,%3};"
        : "+f"(c[0]), "+f"(c[1]), "+f"(c[2]), "+f"(c[3])
        : "r"(a[0]), "r"(a[1]), "r"(a[2]), "r"(a[3]), "r"(b[0]), "r"(b[1]));
}
#define CP_ASYNC16(dst, src) \
    asm volatile("cp.async.cg.shared.global [%0], [%1], 16;" \
        :: "r"(dst), "l"(src) : "memory")
#define CP_COMMIT() asm volatile("cp.async.commit_group;" ::: "memory")
#define CP_WAIT(n)  asm volatile("cp.async.wait_group %0;" :: "n"(n) : "memory")

// ---------------------------------------------------------------------------
__global__ void zero_vox_kernel() {
    float4* p = (float4*)g_vox;
    const int n4 = GRIDVOL * 64 / 4;
    for (int i = blockIdx.x * blockDim.x + threadIdx.x; i < n4;
         i += gridDim.x * blockDim.x)
        p[i] = make_float4(0.f, 0.f, 0.f, 0.f);
}

// ---------------------------------------------------------------------------
// voxelize: scatter-add raw inputs into g_vox
// ---------------------------------------------------------------------------
__global__ void scatter_kernel(const float* __restrict__ in,
                               const int* __restrict__ vidx)
{
    int t = blockIdx.x * blockDim.x + threadIdx.x;
    if (t >= N_PTS * 64) return;
    int n = t >> 6;
    int ix = vidx[n * 3 + 0];
    int iy = vidx[n * 3 + 1];
    int iz = vidx[n * 3 + 2];
    atomicAdd(&g_vox[(((((ix << 6) + iy) << 6) + iz) << 6) + (t & 63)], in[t]);
}

// ---------------------------------------------------------------------------
// weight prep: k [tap][cin][cout] fp32 -> [tap][cout][cin] fp16
// ---------------------------------------------------------------------------
__global__ void build_W_kernel(const float* __restrict__ k, int stage) {
    int i = blockIdx.x * blockDim.x + threadIdx.x;
    if (i >= 27 * 64 * 64) return;
    int tap = i >> 12, r = i & 4095, cin = r >> 6, cout = r & 63;
    g_W[stage][(tap << 12) + (cout << 6) + cin] = __float2half_rn(k[i]);
}

// ---------------------------------------------------------------------------
// build padded fp16 conv1 input: P = half(g_vox * pinv)
// ---------------------------------------------------------------------------
__global__ void build_P_kernel(const float* __restrict__ pinv) {
    int t = blockIdx.x * blockDim.x + threadIdx.x;
    if (t >= GRIDVOL * 16) return;
    int vox = t >> 4, c4 = (t & 15) << 2;
    float s = pinv[vox];
    float4 v = *(const float4*)&g_vox[(vox << 6) + c4];
    int x = vox >> 12, y = (vox >> 6) & 63, z = vox & 63;
    long p = (long)(x + 1) * PXS + (y + 1) * PYS + (z + 1);
    long idx = (GUARD + p) * 64 + c4;
    __half2 h0, h1;
    h0.x = __float2half_rn(v.x * s); h0.y = __float2half_rn(v.y * s);
    h1.x = __float2half_rn(v.z * s); h1.y = __float2half_rn(v.w * s);
    *(__half2*)&g_P[idx]     = h0;
    *(__half2*)&g_P[idx + 2] = h1;
}

// ---------------------------------------------------------------------------
// MLP as fp16 mma GEMM: CTA = 128 points x 64 couts, 8 warps (32x32 tiles)
// ---------------------------------------------------------------------------
__global__ __launch_bounds__(256) void mlp_mma_kernel(
    const float* __restrict__ in, const float* __restrict__ w,
    const float* __restrict__ b,
    const float* __restrict__ g0, const float* __restrict__ be0,
    const float* __restrict__ m0v, const float* __restrict__ v0)
{
    extern __shared__ char dyn[];
    __shared__ float s_ep[192];
    const int tid = threadIdx.x, lane = tid & 31, warp = tid >> 5;
    const int m0 = (warp >> 1) * 32, n0 = (warp & 1) * 32;
    const uint32_t S0 = smem_u32(dyn);

    if (tid < 64) {
        float sc = g0[tid] * rsqrtf(v0[tid] + 1e-3f);
        s_ep[tid] = b[tid];
        s_ep[64 + tid] = sc;
        s_ep[128 + tid] = be0[tid] - m0v[tid] * sc;
    }

    const float4* in4 = (const float4*)in;
    for (int i = tid; i < 2048; i += 256) {
        int row = i >> 4, c = i & 15;
        long n = (long)blockIdx.x * 128 + row;
        __half2 h0, h1;
        h0.x = h0.y = h1.x = h1.y = __float2half_rn(0.f);
        if (n < N_PTS) {
            float4 raw = in4[n * 16 + c];
            h0.x = __float2half_rn(raw.x); h0.y = __float2half_rn(raw.y);
            h1.x = __float2half_rn(raw.z); h1.y = __float2half_rn(raw.w);
        }
        uint32_t d = row * 128 + ((((uint32_t)(c >> 1)) ^ (row & 7)) << 4)
                     + (c & 1) * 8;
        *(__half2*)(dyn + d)     = h0;
        *(__half2*)(dyn + d + 4) = h1;
    }
    for (int i = tid; i < 4096; i += 256) {
        int ci = i >> 6, co = i & 63;
        uint32_t d = co * 128 + ((((uint32_t)(ci >> 3)) ^ (co & 7)) << 4)
                     + (ci & 7) * 2;
        *(__half*)(dyn + 16384 + d) = __float2half_rn(w[i]);
    }
    __syncthreads();

    float acc[2][4][4];
#pragma unroll
    for (int a = 0; a < 2; ++a)
#pragma unroll
        for (int x = 0; x < 4; ++x)
#pragma unroll
            for (int c = 0; c < 4; ++c) acc[a][x][c] = 0.f;

    const int arow = lane & 15, asel = lane >> 4;
    const int brow = lane & 7, bsel = (lane >> 3) & 1;
#pragma unroll
    for (int kc = 0; kc < 4; ++kc) {
        uint32_t af[2][4], bf[4][2];
#pragma unroll
        for (int mt = 0; mt < 2; ++mt) {
            int row = m0 + mt * 16 + arow;
            ldsm_x4(af[mt], S0 + row * 128 +
                    (((uint32_t)((kc * 2 + asel) ^ (row & 7))) << 4));
        }
#pragma unroll
        for (int nt = 0; nt < 4; ++nt) {
            int row = n0 + nt * 8 + brow;
            ldsm_x2(bf[nt], S0 + 16384 + row * 128 +
                    (((uint32_t)((kc * 2 + bsel) ^ (row & 7))) << 4));
        }
#pragma unroll
        for (int mt = 0; mt < 2; ++mt)
#pragma unroll
            for (int nt = 0; nt < 4; ++nt)
                mma_f16(acc[mt][nt], af[mt], bf[nt]);
    }

    const int gr = lane >> 2, tig = lane & 3;
#pragma unroll
    for (int mt = 0; mt < 2; ++mt)
#pragma unroll
        for (int half = 0; half < 2; ++half) {
            long n = (long)blockIdx.x * 128 + m0 + mt * 16 + half * 8 + gr;
            if (n >= N_PTS) continue;
#pragma unroll
            for (int nt = 0; nt < 4; ++nt) {
                int col = n0 + nt * 8 + tig * 2;
                float v0r = fmaxf(acc[mt][nt][half * 2 + 0] + s_ep[col], 0.f)
                            * s_ep[64 + col] + s_ep[128 + col];
                float v1r = fmaxf(acc[mt][nt][half * 2 + 1] + s_ep[col + 1], 0.f)
                            * s_ep[64 + col + 1] + s_ep[128 + col + 1];
                float2 fv; fv.x = v0r; fv.y = v1r;
                *(float2*)&g_mlp[n * 64 + col] = fv;
            }
        }
}

// ---------------------------------------------------------------------------
// Pipelined fp16 mma implicit-GEMM conv (unchanged core from R8).
// ---------------------------------------------------------------------------
template<int STAGE>
__device__ __forceinline__ void conv_stage_async(
    uint32_t Sbuf, const __half* __restrict__ SRC,
    const uint4* __restrict__ Wsrc, long blockbase, int s, int tid)
{
    const int dx = s / 3, dy = s % 3, tap0 = s * 3;
    const long w0 = (long)GUARD + blockbase
                    + (long)(dx - 1) * PXS + (dy - 1) * PYS - 1;
    const uint4* asrc = (const uint4*)SRC + w0 * 8;
    for (int i = tid; i < 2064; i += 128) {
        int row = i >> 3, c = i & 7;
        uint32_t d = Sbuf + row * 128 + (((uint32_t)(c ^ (row & 7))) << 4);
        CP_ASYNC16(d, asrc + i);
    }
    for (int i = tid; i < 1536; i += 128) {
        int t3 = i >> 9, r = (i >> 3) & 63, c = i & 7;
        uint32_t d = Sbuf + ABYTES + t3 * 8192 + r * 128 +
                     (((uint32_t)(c ^ (r & 7))) << 4);
        CP_ASYNC16(d, Wsrc + (tap0 + t3) * 512 + r * 8 + c);
    }
}

template<int STAGE>
__global__ __launch_bounds__(128) void conv_mma_kernel(
    const float* __restrict__ cb, const float* __restrict__ g,
    const float* __restrict__ be, const float* __restrict__ m,
    const float* __restrict__ v)
{
    extern __shared__ char dyn[];
    __shared__ float s_ep[192];
    const int tid = threadIdx.x, lane = tid & 31, warp = tid >> 5;
    const int m0 = warp * 64;
    const uint32_t S0 = smem_u32(dyn);

    if (tid < 64) {
        float sc = g[tid] * rsqrtf(v[tid] + 1e-3f);
        s_ep[tid] = cb[tid];
        s_ep[64 + tid] = sc;
        s_ep[128 + tid] = be[tid] - m[tid] * sc;
    }

    const __half* __restrict__ SRC = (STAGE == 1) ? g_P : g_Q;
    const uint4* __restrict__ Wsrc = (const uint4*)g_W[STAGE - 1];
    const long blockbase = (long)blockIdx.x * 256;

    float acc[4][8][4];
#pragma unroll
    for (int a = 0; a < 4; ++a)
#pragma unroll
        for (int x = 0; x < 8; ++x)
#pragma unroll
            for (int c = 0; c < 4; ++c) acc[a][x][c] = 0.f;

    const int arow = lane & 15, asel = lane >> 4;
    const int brow = lane & 7, bsel = (lane >> 3) & 1;

    conv_stage_async<STAGE>(S0, SRC, Wsrc, blockbase, 0, tid);
    CP_COMMIT();

    for (int s = 0; s < 9; ++s) {
        if (s < 8) {
            conv_stage_async<STAGE>(S0 + ((s + 1) & 1) * BUFBYTES, SRC, Wsrc,
                                    blockbase, s + 1, tid);
            CP_COMMIT();
            CP_WAIT(1);
        } else {
            CP_WAIT(0);
        }
        __syncthreads();

        const uint32_t SA = S0 + (s & 1) * BUFBYTES;
        const uint32_t SW = SA + ABYTES;
        for (int dz = 0; dz < 3; ++dz) {
#pragma unroll
            for (int kc = 0; kc < 4; ++kc) {
                uint32_t af[4][4], bf[8][2];
#pragma unroll
                for (int mt = 0; mt < 4; ++mt) {
                    int row = dz + m0 + mt * 16 + arow;
                    ldsm_x4(af[mt], SA + row * 128 +
                            (((uint32_t)((kc * 2 + asel) ^ (row & 7))) << 4));
                }
#pragma unroll
                for (int nt = 0; nt < 8; ++nt) {
                    int row = nt * 8 + brow;
                    ldsm_x2(bf[nt], SW + dz * 8192 + row * 128 +
                            (((uint32_t)((kc * 2 + bsel) ^ (row & 7))) << 4));
                }
#pragma unroll
                for (int mt = 0; mt < 4; ++mt)
#pragma unroll
                    for (int nt = 0; nt < 8; ++nt)
                        mma_f16(acc[mt][nt], af[mt], bf[nt]);
            }
        }
        __syncthreads();
    }

    // ---- epilogue: bias + relu + BN ----
    const int gr = lane >> 2, tig = lane & 3;
#pragma unroll
    for (int mt = 0; mt < 4; ++mt)
#pragma unroll
        for (int half = 0; half < 2; ++half) {
            int rl = m0 + mt * 16 + half * 8 + gr;
            long p = blockbase + rl;
            if (p >= PTOT) continue;
            if (STAGE == 1) {
                int x = (int)(p / PXS);
                int rem = (int)(p - (long)x * PXS);
                int y = rem / PYS, z = rem - y * PYS;
                bool valid = (x >= 1) && (x <= 64) && (y >= 1) && (y <= 64)
                             && (z >= 1) && (z <= 64);
                if (!valid) continue;   // pads of g_Q must stay zero
            }
            long base = (GUARD + p) * 64;
#pragma unroll
            for (int nt = 0; nt < 8; ++nt) {
                int col = nt * 8 + tig * 2;
                float v0r = fmaxf(acc[mt][nt][half * 2 + 0] + s_ep[col], 0.f)
                            * s_ep[64 + col] + s_ep[128 + col];
                float v1r = fmaxf(acc[mt][nt][half * 2 + 1] + s_ep[col + 1], 0.f)
                            * s_ep[64 + col + 1] + s_ep[128 + col + 1];
                __half2 hv;
                hv.x = __float2half_rn(v0r);
                hv.y = __float2half_rn(v1r);
                if (STAGE == 1) *(__half2*)&g_Q[base + col]   = hv;
                else            *(__half2*)&g_h2p[base + col] = hv;
            }
        }
}

// ---------------------------------------------------------------------------
// devoxelize: trilinear gather from fp16 g_h2p + residual add of g_mlp.
// thread = (point, 2 channels): 32 threads per point, half2 corner reads.
// ---------------------------------------------------------------------------
__global__ void gather_kernel(const float* __restrict__ coords,
                              float* __restrict__ out)
{
    int t = blockIdx.x * blockDim.x + threadIdx.x;
    if (t >= N_PTS * 32) return;
    int n = t >> 5, c2 = (t & 31) << 1;

    float px = fminf(fmaxf(coords[n * 3 + 0], 0.f), 63.f);
    float py = fminf(fmaxf(coords[n * 3 + 1], 0.f), 63.f);
    float pz = fminf(fmaxf(coords[n * 3 + 2], 0.f), 63.f);
    float fx = floorf(px), fy = floorf(py), fz = floorf(pz);
    int x0 = (int)fx, y0 = (int)fy, z0 = (int)fz;
    int x1 = min(x0 + 1, 63), y1 = min(y0 + 1, 63), z1 = min(z0 + 1, 63);
    float tx = px - fx, ty = py - fy, tz = pz - fz;

    auto at = [&](int x, int y, int z) {
        long row = (long)GUARD + (long)(x + 1) * PXS + (y + 1) * PYS + (z + 1);
        __half2 h = *(const __half2*)&g_h2p[row * 64 + c2];
        return __half22float2(h);
    };
    float2 r = *(const float2*)&g_mlp[n * 64 + c2];
    float2 f;
    float w;
    w = (1.f - tx) * (1.f - ty) * (1.f - tz); f = at(x0, y0, z0); r.x += w * f.x; r.y += w * f.y;
    w = (1.f - tx) * (1.f - ty) * tz;          f = at(x0, y0, z1); r.x += w * f.x; r.y += w * f.y;
    w = (1.f - tx) * ty          * (1.f - tz); f = at(x0, y1, z0); r.x += w * f.x; r.y += w * f.y;
    w = (1.f - tx) * ty          * tz;          f = at(x0, y1, z1); r.x += w * f.x; r.y += w * f.y;
    w = tx          * (1.f - ty) * (1.f - tz); f = at(x1, y0, z0); r.x += w * f.x; r.y += w * f.y;
    w = tx          * (1.f - ty) * tz;          f = at(x1, y0, z1); r.x += w * f.x; r.y += w * f.y;
    w = tx          * ty          * (1.f - tz); f = at(x1, y1, z0); r.x += w * f.x; r.y += w * f.y;
    w = tx          * ty          * tz;          f = at(x1, y1, z1); r.x += w * f.x; r.y += w * f.y;

    *(float2*)&out[n * 64 + c2] = r;
}

// ---------------------------------------------------------------------------
extern "C" void kernel_launch(void* const* d_in, const int* in_sizes, int n_in,
                              void* d_out, int out_size)
{
    const float* inputs    = (const float*)d_in[0];
    const float* pt_coords = (const float*)d_in[1];
    const int*   vidx      = (const int*)  d_in[2];
    const float* pinv      = (const float*)d_in[3];
    const float* w_mlp     = (const float*)d_in[4];
    const float* b_mlp     = (const float*)d_in[5];
    const float* g0        = (const float*)d_in[6];
    const float* be0       = (const float*)d_in[7];
    const float* m0        = (const float*)d_in[8];
    const float* v0        = (const float*)d_in[9];
    const float* k1        = (const float*)d_in[10];
    const float* cb1       = (const float*)d_in[11];
    const float* g1        = (const float*)d_in[12];
    const float* be1       = (const float*)d_in[13];
    const float* m1        = (const float*)d_in[14];
    const float* v1        = (const float*)d_in[15];
    const float* k2        = (const float*)d_in[16];
    const float* cb2       = (const float*)d_in[17];
    const float* g2        = (const float*)d_in[18];
    const float* be2       = (const float*)d_in[19];
    const float* m2        = (const float*)d_in[20];
    const float* v2        = (const float*)d_in[21];
    float* out = (float*)d_out;

    // one-time host-side resource setup (no device memory involved)
    static cudaStream_t s2 = nullptr;
    static cudaEvent_t evFork = nullptr, evJoin = nullptr;
    if (s2 == nullptr) {
        cudaStreamCreateWithFlags(&s2, cudaStreamNonBlocking);
        cudaEventCreateWithFlags(&evFork, cudaEventDisableTiming);
        cudaEventCreateWithFlags(&evJoin, cudaEventDisableTiming);
    }

    const int DSMEM_MLP = 24576;
    cudaFuncSetAttribute(conv_mma_kernel<1>,
                         cudaFuncAttributeMaxDynamicSharedMemorySize, DSMEM_CONV);
    cudaFuncSetAttribute(conv_mma_kernel<2>,
                         cudaFuncAttributeMaxDynamicSharedMemorySize, DSMEM_CONV);
    cudaFuncSetAttribute(mlp_mma_kernel,
                         cudaFuncAttributeMaxDynamicSharedMemorySize, DSMEM_MLP);

    // fork: mlp runs on s2, overlapped with the voxel chain
    cudaEventRecord(evFork, 0);
    cudaStreamWaitEvent(s2, evFork, 0);
    mlp_mma_kernel<<<NTILE_M, 256, DSMEM_MLP, s2>>>(inputs, w_mlp, b_mlp,
                                                    g0, be0, m0, v0);
    cudaEventRecord(evJoin, s2);

    // voxel chain on the capture stream; conv1 is the 6th launch overall
    zero_vox_kernel<<<2048, 256>>>();
    scatter_kernel<<<(N_PTS * 64 + 255) / 256, 256>>>(inputs, vidx);
    build_P_kernel<<<(GRIDVOL * 16 + 255) / 256, 256>>>(pinv);
    build_W_kernel<<<432, 256>>>(k1, 0);
    build_W_kernel<<<432, 256>>>(k2, 1);
    conv_mma_kernel<1><<<NTILE2, 128, DSMEM_CONV>>>(cb1, g1, be1, m1, v1);
    conv_mma_kernel<2><<<NTILE2, 128, DSMEM_CONV>>>(cb2, g2, be2, m2, v2);

    // join: gather needs both conv2 (stream 0) and mlp (s2)
    cudaStreamWaitEvent(0, evJoin, 0);
    gather_kernel<<<(N_PTS * 32 + 255) / 256, 256>>>(pt_coords, out);
}

// round 11
// speedup vs baseline: 5.5581x; 1.0704x over previous
#include <cuda_runtime.h>
#include <cuda_fp16.h>
#include <cstdint>

#define N_PTS 200000
#define GRIDVOL (64*64*64)

// padded 66^3 flat grid + guard rows so every tap-shifted 258-row window
// stays in-bounds.
#define PXS 4356            // x stride (66*66)
#define PYS 66              // y stride
#define PTOT 287496         // 66^3
#define GUARD 4800
#define PROWS (PTOT + 2*GUARD)   // 297096
#define NTILE2 1124         // ceil(PTOT/256)
#define NTILE_M 1563        // ceil(N_PTS/128)

// conv smem (fp16): per buffer A 258*128 + W 3*8192
#define ABYTES 33024
#define WBYTES 24576
#define BUFBYTES (ABYTES + WBYTES)          // 57600
#define DSMEM_CONV (2 * BUFBYTES)           // 115200

// ---- scratch (allocation-free: __device__ globals, zero-initialized) ----
__device__ __half g_P[PROWS*64];          // conv1 input fp16: scatter target
                                          // (pre-scaled by pinv; pads stay 0)
__device__ __half g_Q[PROWS*64];          // conv2 input fp16 (pads stay 0)
__device__ __half g_h2p[PROWS*64];        // conv2 output fp16, padded
__device__ float g_mlp[N_PTS*64];         // point branch
__device__ __half g_W[2][27*64*64];       // weights [tap][cout][cin] fp16

// ---------------------------------------------------------------------------
// helpers
// ---------------------------------------------------------------------------
__device__ __forceinline__ uint32_t smem_u32(const void* p) {
    uint32_t a;
    asm("{ .reg .u64 t; cvta.to.shared.u64 t, %1; cvt.u32.u64 %0, t; }"
        : "=r"(a) : "l"(p));
    return a;
}
__device__ __forceinline__ void ldsm_x4(uint32_t* r, uint32_t a) {
    asm volatile("ldmatrix.sync.aligned.m8n8.x4.shared.b16 {%0,%1,%2,%3}, [%4];"
        : "=r"(r[0]), "=r"(r[1]), "=r"(r[2]), "=r"(r[3]) : "r"(a));
}
__device__ __forceinline__ void ldsm_x2(uint32_t* r, uint32_t a) {
    asm volatile("ldmatrix.sync.aligned.m8n8.x2.shared.b16 {%0,%1}, [%2];"
        : "=r"(r[0]), "=r"(r[1]) : "r"(a));
}
__device__ __forceinline__ void mma_f16(float* c, const uint32_t* a,
                                        const uint32_t* b) {
    asm volatile("mma.sync.aligned.m16n8k16.row.col.f32.f16.f16.f32 "
        "{%0,%1,%2,%3}, {%4,%5,%6,%7}, {%8,%9}, {%0,%1,%2,%3};"
        : "+f"(c[0]), "+f"(c[1]), "+f"(c[2]), "+f"(c[3])
        : "r"(a[0]), "r"(a[1]), "r"(a[2]), "r"(a[3]), "r"(b[0]), "r"(b[1]));
}
#define CP_ASYNC16(dst, src) \
    asm volatile("cp.async.cg.shared.global [%0], [%1], 16;" \
        :: "r"(dst), "l"(src) : "memory")
#define CP_COMMIT() asm volatile("cp.async.commit_group;" ::: "memory")
#define CP_WAIT(n)  asm volatile("cp.async.wait_group %0;" :: "n"(n) : "memory")

// ---------------------------------------------------------------------------
// voxelize fused: atomicAdd half2 of (in * pinv) directly into padded g_P.
// thread = (point, 2 channels); warp covers one point's 64 channels.
// ---------------------------------------------------------------------------
__global__ void scatter_kernel(const float* __restrict__ in,
                               const int* __restrict__ vidx,
                               const float* __restrict__ pinv)
{
    int t = blockIdx.x * blockDim.x + threadIdx.x;
    if (t >= N_PTS * 32) return;
    int n = t >> 5, c2 = t & 31;
    int ix = vidx[n * 3 + 0];
    int iy = vidx[n * 3 + 1];
    int iz = vidx[n * 3 + 2];
    int vox = (((ix << 6) + iy) << 6) + iz;
    float s = pinv[vox];
    float2 v = ((const float2*)in)[n * 32 + c2];
    __half2 h;
    h.x = __float2half_rn(v.x * s);
    h.y = __float2half_rn(v.y * s);
    long p = (long)(ix + 1) * PXS + (iy + 1) * PYS + (iz + 1);
    atomicAdd((__half2*)&g_P[(GUARD + p) * 64 + c2 * 2], h);
}

// ---------------------------------------------------------------------------
// re-zero g_P's real-voxel region for the next graph replay
// (runs on stream 2 after conv1 finished reading g_P, concurrent with conv2)
// ---------------------------------------------------------------------------
__global__ void zero_P_kernel() {
    float4* p = (float4*)&g_P[(long)GUARD * 64];
    const long n4 = (long)PTOT * 64 / 8;   // halfs -> float4 units
    for (long i = blockIdx.x * blockDim.x + threadIdx.x; i < n4;
         i += (long)gridDim.x * blockDim.x)
        p[i] = make_float4(0.f, 0.f, 0.f, 0.f);
}

// ---------------------------------------------------------------------------
// weight prep (both conv stages in one launch):
// k [tap][cin][cout] fp32 -> [tap][cout][cin] fp16
// ---------------------------------------------------------------------------
__global__ void build_W_kernel(const float* __restrict__ k1,
                               const float* __restrict__ k2) {
    int i = blockIdx.x * blockDim.x + threadIdx.x;
    const int n = 27 * 64 * 64;
    if (i >= 2 * n) return;
    int stage = (i >= n);
    int j = i - stage * n;
    const float* k = stage ? k2 : k1;
    int tap = j >> 12, r = j & 4095, cin = r >> 6, cout = r & 63;
    g_W[stage][(tap << 12) + (cout << 6) + cin] = __float2half_rn(k[j]);
}

// ---------------------------------------------------------------------------
// MLP as fp16 mma GEMM: CTA = 128 points x 64 couts, 8 warps (32x32 tiles)
// ---------------------------------------------------------------------------
__global__ __launch_bounds__(256) void mlp_mma_kernel(
    const float* __restrict__ in, const float* __restrict__ w,
    const float* __restrict__ b,
    const float* __restrict__ g0, const float* __restrict__ be0,
    const float* __restrict__ m0v, const float* __restrict__ v0)
{
    extern __shared__ char dyn[];
    __shared__ float s_ep[192];
    const int tid = threadIdx.x, lane = tid & 31, warp = tid >> 5;
    const int m0 = (warp >> 1) * 32, n0 = (warp & 1) * 32;
    const uint32_t S0 = smem_u32(dyn);

    if (tid < 64) {
        float sc = g0[tid] * rsqrtf(v0[tid] + 1e-3f);
        s_ep[tid] = b[tid];
        s_ep[64 + tid] = sc;
        s_ep[128 + tid] = be0[tid] - m0v[tid] * sc;
    }

    const float4* in4 = (const float4*)in;
    for (int i = tid; i < 2048; i += 256) {
        int row = i >> 4, c = i & 15;
        long n = (long)blockIdx.x * 128 + row;
        __half2 h0, h1;
        h0.x = h0.y = h1.x = h1.y = __float2half_rn(0.f);
        if (n < N_PTS) {
            float4 raw = in4[n * 16 + c];
            h0.x = __float2half_rn(raw.x); h0.y = __float2half_rn(raw.y);
            h1.x = __float2half_rn(raw.z); h1.y = __float2half_rn(raw.w);
        }
        uint32_t d = row * 128 + ((((uint32_t)(c >> 1)) ^ (row & 7)) << 4)
                     + (c & 1) * 8;
        *(__half2*)(dyn + d)     = h0;
        *(__half2*)(dyn + d + 4) = h1;
    }
    for (int i = tid; i < 4096; i += 256) {
        int ci = i >> 6, co = i & 63;
        uint32_t d = co * 128 + ((((uint32_t)(ci >> 3)) ^ (co & 7)) << 4)
                     + (ci & 7) * 2;
        *(__half*)(dyn + 16384 + d) = __float2half_rn(w[i]);
    }
    __syncthreads();

    float acc[2][4][4];
#pragma unroll
    for (int a = 0; a < 2; ++a)
#pragma unroll
        for (int x = 0; x < 4; ++x)
#pragma unroll
            for (int c = 0; c < 4; ++c) acc[a][x][c] = 0.f;

    const int arow = lane & 15, asel = lane >> 4;
    const int brow = lane & 7, bsel = (lane >> 3) & 1;
#pragma unroll
    for (int kc = 0; kc < 4; ++kc) {
        uint32_t af[2][4], bf[4][2];
#pragma unroll
        for (int mt = 0; mt < 2; ++mt) {
            int row = m0 + mt * 16 + arow;
            ldsm_x4(af[mt], S0 + row * 128 +
                    (((uint32_t)((kc * 2 + asel) ^ (row & 7))) << 4));
        }
#pragma unroll
        for (int nt = 0; nt < 4; ++nt) {
            int row = n0 + nt * 8 + brow;
            ldsm_x2(bf[nt], S0 + 16384 + row * 128 +
                    (((uint32_t)((kc * 2 + bsel) ^ (row & 7))) << 4));
        }
#pragma unroll
        for (int mt = 0; mt < 2; ++mt)
#pragma unroll
            for (int nt = 0; nt < 4; ++nt)
                mma_f16(acc[mt][nt], af[mt], bf[nt]);
    }

    const int gr = lane >> 2, tig = lane & 3;
#pragma unroll
    for (int mt = 0; mt < 2; ++mt)
#pragma unroll
        for (int half = 0; half < 2; ++half) {
            long n = (long)blockIdx.x * 128 + m0 + mt * 16 + half * 8 + gr;
            if (n >= N_PTS) continue;
#pragma unroll
            for (int nt = 0; nt < 4; ++nt) {
                int col = n0 + nt * 8 + tig * 2;
                float v0r = fmaxf(acc[mt][nt][half * 2 + 0] + s_ep[col], 0.f)
                            * s_ep[64 + col] + s_ep[128 + col];
                float v1r = fmaxf(acc[mt][nt][half * 2 + 1] + s_ep[col + 1], 0.f)
                            * s_ep[64 + col + 1] + s_ep[128 + col + 1];
                float2 fv; fv.x = v0r; fv.y = v1r;
                *(float2*)&g_mlp[n * 64 + col] = fv;
            }
        }
}

// ---------------------------------------------------------------------------
// Pipelined fp16 mma implicit-GEMM conv (unchanged core from R8/R9).
// ---------------------------------------------------------------------------
template<int STAGE>
__device__ __forceinline__ void conv_stage_async(
    uint32_t Sbuf, const __half* __restrict__ SRC,
    const uint4* __restrict__ Wsrc, long blockbase, int s, int tid)
{
    const int dx = s / 3, dy = s % 3, tap0 = s * 3;
    const long w0 = (long)GUARD + blockbase
                    + (long)(dx - 1) * PXS + (dy - 1) * PYS - 1;
    const uint4* asrc = (const uint4*)SRC + w0 * 8;
    for (int i = tid; i < 2064; i += 128) {
        int row = i >> 3, c = i & 7;
        uint32_t d = Sbuf + row * 128 + (((uint32_t)(c ^ (row & 7))) << 4);
        CP_ASYNC16(d, asrc + i);
    }
    for (int i = tid; i < 1536; i += 128) {
        int t3 = i >> 9, r = (i >> 3) & 63, c = i & 7;
        uint32_t d = Sbuf + ABYTES + t3 * 8192 + r * 128 +
                     (((uint32_t)(c ^ (r & 7))) << 4);
        CP_ASYNC16(d, Wsrc + (tap0 + t3) * 512 + r * 8 + c);
    }
}

template<int STAGE>
__global__ __launch_bounds__(128) void conv_mma_kernel(
    const float* __restrict__ cb, const float* __restrict__ g,
    const float* __restrict__ be, const float* __restrict__ m,
    const float* __restrict__ v)
{
    extern __shared__ char dyn[];
    __shared__ float s_ep[192];
    const int tid = threadIdx.x, lane = tid & 31, warp = tid >> 5;
    const int m0 = warp * 64;
    const uint32_t S0 = smem_u32(dyn);

    if (tid < 64) {
        float sc = g[tid] * rsqrtf(v[tid] + 1e-3f);
        s_ep[tid] = cb[tid];
        s_ep[64 + tid] = sc;
        s_ep[128 + tid] = be[tid] - m[tid] * sc;
    }

    const __half* __restrict__ SRC = (STAGE == 1) ? g_P : g_Q;
    const uint4* __restrict__ Wsrc = (const uint4*)g_W[STAGE - 1];
    const long blockbase = (long)blockIdx.x * 256;

    float acc[4][8][4];
#pragma unroll
    for (int a = 0; a < 4; ++a)
#pragma unroll
        for (int x = 0; x < 8; ++x)
#pragma unroll
            for (int c = 0; c < 4; ++c) acc[a][x][c] = 0.f;

    const int arow = lane & 15, asel = lane >> 4;
    const int brow = lane & 7, bsel = (lane >> 3) & 1;

    conv_stage_async<STAGE>(S0, SRC, Wsrc, blockbase, 0, tid);
    CP_COMMIT();

    for (int s = 0; s < 9; ++s) {
        if (s < 8) {
            conv_stage_async<STAGE>(S0 + ((s + 1) & 1) * BUFBYTES, SRC, Wsrc,
                                    blockbase, s + 1, tid);
            CP_COMMIT();
            CP_WAIT(1);
        } else {
            CP_WAIT(0);
        }
        __syncthreads();

        const uint32_t SA = S0 + (s & 1) * BUFBYTES;
        const uint32_t SW = SA + ABYTES;
        for (int dz = 0; dz < 3; ++dz) {
#pragma unroll
            for (int kc = 0; kc < 4; ++kc) {
                uint32_t af[4][4], bf[8][2];
#pragma unroll
                for (int mt = 0; mt < 4; ++mt) {
                    int row = dz + m0 + mt * 16 + arow;
                    ldsm_x4(af[mt], SA + row * 128 +
                            (((uint32_t)((kc * 2 + asel) ^ (row & 7))) << 4));
                }
#pragma unroll
                for (int nt = 0; nt < 8; ++nt) {
                    int row = nt * 8 + brow;
                    ldsm_x2(bf[nt], SW + dz * 8192 + row * 128 +
                            (((uint32_t)((kc * 2 + bsel) ^ (row & 7))) << 4));
                }
#pragma unroll
                for (int mt = 0; mt < 4; ++mt)
#pragma unroll
                    for (int nt = 0; nt < 8; ++nt)
                        mma_f16(acc[mt][nt], af[mt], bf[nt]);
            }
        }
        __syncthreads();
    }

    // ---- epilogue: bias + relu + BN ----
    const int gr = lane >> 2, tig = lane & 3;
#pragma unroll
    for (int mt = 0; mt < 4; ++mt)
#pragma unroll
        for (int half = 0; half < 2; ++half) {
            int rl = m0 + mt * 16 + half * 8 + gr;
            long p = blockbase + rl;
            if (p >= PTOT) continue;
            if (STAGE == 1) {
                int x = (int)(p / PXS);
                int rem = (int)(p - (long)x * PXS);
                int y = rem / PYS, z = rem - y * PYS;
                bool valid = (x >= 1) && (x <= 64) && (y >= 1) && (y <= 64)
                             && (z >= 1) && (z <= 64);
                if (!valid) continue;   // pads of g_Q must stay zero
            }
            long base = (GUARD + p) * 64;
#pragma unroll
            for (int nt = 0; nt < 8; ++nt) {
                int col = nt * 8 + tig * 2;
                float v0r = fmaxf(acc[mt][nt][half * 2 + 0] + s_ep[col], 0.f)
                            * s_ep[64 + col] + s_ep[128 + col];
                float v1r = fmaxf(acc[mt][nt][half * 2 + 1] + s_ep[col + 1], 0.f)
                            * s_ep[64 + col + 1] + s_ep[128 + col + 1];
                __half2 hv;
                hv.x = __float2half_rn(v0r);
                hv.y = __float2half_rn(v1r);
                if (STAGE == 1) *(__half2*)&g_Q[base + col]   = hv;
                else            *(__half2*)&g_h2p[base + col] = hv;
            }
        }
}

// ---------------------------------------------------------------------------
// devoxelize: trilinear gather from fp16 g_h2p + residual add of g_mlp.
// thread = (point, 2 channels): 32 threads per point, half2 corner reads.
// ---------------------------------------------------------------------------
__global__ void gather_kernel(const float* __restrict__ coords,
                              float* __restrict__ out)
{
    int t = blockIdx.x * blockDim.x + threadIdx.x;
    if (t >= N_PTS * 32) return;
    int n = t >> 5, c2 = (t & 31) << 1;

    float px = fminf(fmaxf(coords[n * 3 + 0], 0.f), 63.f);
    float py = fminf(fmaxf(coords[n * 3 + 1], 0.f), 63.f);
    float pz = fminf(fmaxf(coords[n * 3 + 2], 0.f), 63.f);
    float fx = floorf(px), fy = floorf(py), fz = floorf(pz);
    int x0 = (int)fx, y0 = (int)fy, z0 = (int)fz;
    int x1 = min(x0 + 1, 63), y1 = min(y0 + 1, 63), z1 = min(z0 + 1, 63);
    float tx = px - fx, ty = py - fy, tz = pz - fz;

    auto at = [&](int x, int y, int z) {
        long row = (long)GUARD + (long)(x + 1) * PXS + (y + 1) * PYS + (z + 1);
        __half2 h = *(const __half2*)&g_h2p[row * 64 + c2];
        return __half22float2(h);
    };
    float2 r = *(const float2*)&g_mlp[n * 64 + c2];
    float2 f;
    float w;
    w = (1.f - tx) * (1.f - ty) * (1.f - tz); f = at(x0, y0, z0); r.x += w * f.x; r.y += w * f.y;
    w = (1.f - tx) * (1.f - ty) * tz;          f = at(x0, y0, z1); r.x += w * f.x; r.y += w * f.y;
    w = (1.f - tx) * ty          * (1.f - tz); f = at(x0, y1, z0); r.x += w * f.x; r.y += w * f.y;
    w = (1.f - tx) * ty          * tz;          f = at(x0, y1, z1); r.x += w * f.x; r.y += w * f.y;
    w = tx          * (1.f - ty) * (1.f - tz); f = at(x1, y0, z0); r.x += w * f.x; r.y += w * f.y;
    w = tx          * (1.f - ty) * tz;          f = at(x1, y0, z1); r.x += w * f.x; r.y += w * f.y;
    w = tx          * ty          * (1.f - tz); f = at(x1, y1, z0); r.x += w * f.x; r.y += w * f.y;
    w = tx          * ty          * tz;          f = at(x1, y1, z1); r.x += w * f.x; r.y += w * f.y;

    *(float2*)&out[n * 64 + c2] = r;
}

// ---------------------------------------------------------------------------
extern "C" void kernel_launch(void* const* d_in, const int* in_sizes, int n_in,
                              void* d_out, int out_size)
{
    const float* inputs    = (const float*)d_in[0];
    const float* pt_coords = (const float*)d_in[1];
    const int*   vidx      = (const int*)  d_in[2];
    const float* pinv      = (const float*)d_in[3];
    const float* w_mlp     = (const float*)d_in[4];
    const float* b_mlp     = (const float*)d_in[5];
    const float* g0        = (const float*)d_in[6];
    const float* be0       = (const float*)d_in[7];
    const float* m0        = (const float*)d_in[8];
    const float* v0        = (const float*)d_in[9];
    const float* k1        = (const float*)d_in[10];
    const float* cb1       = (const float*)d_in[11];
    const float* g1        = (const float*)d_in[12];
    const float* be1       = (const float*)d_in[13];
    const float* m1        = (const float*)d_in[14];
    const float* v1        = (const float*)d_in[15];
    const float* k2        = (const float*)d_in[16];
    const float* cb2       = (const float*)d_in[17];
    const float* g2        = (const float*)d_in[18];
    const float* be2       = (const float*)d_in[19];
    const float* m2        = (const float*)d_in[20];
    const float* v2        = (const float*)d_in[21];
    float* out = (float*)d_out;

    // one-time host-side resource setup (no device memory involved)
    static cudaStream_t s2 = nullptr;
    static cudaEvent_t evFork = nullptr, evJoin = nullptr;
    static cudaEvent_t evC1 = nullptr, evZ = nullptr;
    if (s2 == nullptr) {
        cudaStreamCreateWithFlags(&s2, cudaStreamNonBlocking);
        cudaEventCreateWithFlags(&evFork, cudaEventDisableTiming);
        cudaEventCreateWithFlags(&evJoin, cudaEventDisableTiming);
        cudaEventCreateWithFlags(&evC1, cudaEventDisableTiming);
        cudaEventCreateWithFlags(&evZ, cudaEventDisableTiming);
    }

    const int DSMEM_MLP = 24576;
    cudaFuncSetAttribute(conv_mma_kernel<1>,
                         cudaFuncAttributeMaxDynamicSharedMemorySize, DSMEM_CONV);
    cudaFuncSetAttribute(conv_mma_kernel<2>,
                         cudaFuncAttributeMaxDynamicSharedMemorySize, DSMEM_CONV);
    cudaFuncSetAttribute(mlp_mma_kernel,
                         cudaFuncAttributeMaxDynamicSharedMemorySize, DSMEM_MLP);

    cudaEventRecord(evFork, 0);
    cudaStreamWaitEvent(s2, evFork, 0);

    // main stream: scatter (fused voxelize+scale) then weights then conv1
    scatter_kernel<<<(N_PTS * 32 + 255) / 256, 256>>>(inputs, vidx, pinv);
    build_W_kernel<<<(2 * 27 * 64 * 64 + 255) / 256, 256>>>(k1, k2);

    // s2: point branch, independent of the voxel chain
    mlp_mma_kernel<<<NTILE_M, 256, DSMEM_MLP, s2>>>(inputs, w_mlp, b_mlp,
                                                    g0, be0, m0, v0);
    cudaEventRecord(evJoin, s2);

    conv_mma_kernel<1><<<NTILE2, 128, DSMEM_CONV>>>(cb1, g1, be1, m1, v1);
    cudaEventRecord(evC1, 0);

    // s2: re-zero g_P for the next replay, concurrent with conv2
    cudaStreamWaitEvent(s2, evC1, 0);
    zero_P_kernel<<<2048, 256, 0, s2>>>();
    cudaEventRecord(evZ, s2);

    conv_mma_kernel<2><<<NTILE2, 128, DSMEM_CONV>>>(cb2, g2, be2, m2, v2);

    // join: gather needs conv2 (stream 0), mlp and zero_P (s2)
    cudaStreamWaitEvent(0, evJoin, 0);
    cudaStreamWaitEvent(0, evZ, 0);
    gather_kernel<<<(N_PTS * 32 + 255) / 256, 256>>>(pt_coords, out);
}

// round 12
// speedup vs baseline: 5.7972x; 1.0430x over previous
#include <cuda_runtime.h>
#include <cuda_fp16.h>
#include <cstdint>

#define N_PTS 200000
#define GRIDVOL (64*64*64)

// padded 66^3 flat grid + guard rows so every tap-shifted 258-row window
// stays in-bounds.
#define PXS 4356            // x stride (66*66)
#define PYS 66              // y stride
#define PTOT 287496         // 66^3
#define GUARD 4800
#define PROWS (PTOT + 2*GUARD)   // 297096
#define NTILE2 1124         // ceil(PTOT/256)
#define NTILE_M 1563        // ceil(N_PTS/128)

// conv smem (fp16): per buffer A 258*128 + W 3*8192
#define ABYTES 33024
#define WBYTES 24576
#define BUFBYTES (ABYTES + WBYTES)          // 57600
#define DSMEM_CONV (2 * BUFBYTES)           // 115200

// ---- scratch (allocation-free: __device__ globals, zero-initialized) ----
__device__ __half g_P[PROWS*64];          // conv1 input fp16: scatter target
                                          // (pre-scaled by pinv; pads stay 0)
__device__ __half g_Q[PROWS*64];          // conv2 input fp16 (pads stay 0)
__device__ __half g_h2p[PROWS*64];        // conv2 output fp16, padded
__device__ float g_mlp[N_PTS*64];         // point branch
__device__ __half g_W[2][27*64*64];       // weights [tap][cout][cin] fp16

// ---------------------------------------------------------------------------
// helpers
// ---------------------------------------------------------------------------
__device__ __forceinline__ uint32_t smem_u32(const void* p) {
    uint32_t a;
    asm("{ .reg .u64 t; cvta.to.shared.u64 t, %1; cvt.u32.u64 %0, t; }"
        : "=r"(a) : "l"(p));
    return a;
}
__device__ __forceinline__ void ldsm_x4(uint32_t* r, uint32_t a) {
    asm volatile("ldmatrix.sync.aligned.m8n8.x4.shared.b16 {%0,%1,%2,%3}, [%4];"
        : "=r"(r[0]), "=r"(r[1]), "=r"(r[2]), "=r"(r[3]) : "r"(a));
}
__device__ __forceinline__ void ldsm_x2(uint32_t* r, uint32_t a) {
    asm volatile("ldmatrix.sync.aligned.m8n8.x2.shared.b16 {%0,%1}, [%2];"
        : "=r"(r[0]), "=r"(r[1]) : "r"(a));
}
__device__ __forceinline__ void mma_f16(float* c, const uint32_t* a,
                                        const uint32_t* b) {
    asm volatile("mma.sync.aligned.m16n8k16.row.col.f32.f16.f16.f32 "
        "{%0,%1,%2,%3}, {%4,%5,%6,%7}, {%8,%9}, {%0,%1,%2,%3};"
        : "+f"(c[0]), "+f"(c[1]), "+f"(c[2]), "+f"(c[3])
        : "r"(a[0]), "r"(a[1]), "r"(a[2]), "r"(a[3]), "r"(b[0]), "r"(b[1]));
}
#define CP_ASYNC16(dst, src) \
    asm volatile("cp.async.cg.shared.global [%0], [%1], 16;" \
        :: "r"(dst), "l"(src) : "memory")
#define CP_COMMIT() asm volatile("cp.async.commit_group;" ::: "memory")
#define CP_WAIT(n)  asm volatile("cp.async.wait_group %0;" :: "n"(n) : "memory")

// ---------------------------------------------------------------------------
// voxelize fused: atomicAdd half2 of (in * pinv) directly into padded g_P.
// ---------------------------------------------------------------------------
__global__ void scatter_kernel(const float* __restrict__ in,
                               const int* __restrict__ vidx,
                               const float* __restrict__ pinv)
{
    int t = blockIdx.x * blockDim.x + threadIdx.x;
    if (t >= N_PTS * 32) return;
    int n = t >> 5, c2 = t & 31;
    int ix = vidx[n * 3 + 0];
    int iy = vidx[n * 3 + 1];
    int iz = vidx[n * 3 + 2];
    int vox = (((ix << 6) + iy) << 6) + iz;
    float s = pinv[vox];
    float2 v = ((const float2*)in)[n * 32 + c2];
    __half2 h;
    h.x = __float2half_rn(v.x * s);
    h.y = __float2half_rn(v.y * s);
    long p = (long)(ix + 1) * PXS + (iy + 1) * PYS + (iz + 1);
    atomicAdd((__half2*)&g_P[(GUARD + p) * 64 + c2 * 2], h);
}

// ---------------------------------------------------------------------------
// re-zero g_P's real-voxel region for the next graph replay
// ---------------------------------------------------------------------------
__global__ void zero_P_kernel() {
    float4* p = (float4*)&g_P[(long)GUARD * 64];
    const long n4 = (long)PTOT * 64 / 8;   // halfs -> float4 units
    for (long i = blockIdx.x * blockDim.x + threadIdx.x; i < n4;
         i += (long)gridDim.x * blockDim.x)
        p[i] = make_float4(0.f, 0.f, 0.f, 0.f);
}

// ---------------------------------------------------------------------------
// weight prep (both conv stages in one launch):
// k [tap][cin][cout] fp32 -> [tap][cout][cin] fp16
// ---------------------------------------------------------------------------
__global__ void build_W_kernel(const float* __restrict__ k1,
                               const float* __restrict__ k2) {
    int i = blockIdx.x * blockDim.x + threadIdx.x;
    const int n = 27 * 64 * 64;
    if (i >= 2 * n) return;
    int stage = (i >= n);
    int j = i - stage * n;
    const float* k = stage ? k2 : k1;
    int tap = j >> 12, r = j & 4095, cin = r >> 6, cout = r & 63;
    g_W[stage][(tap << 12) + (cout << 6) + cin] = __float2half_rn(k[j]);
}

// ---------------------------------------------------------------------------
// MLP as fp16 mma GEMM: CTA = 128 points x 64 couts, 8 warps (32x32 tiles)
// ---------------------------------------------------------------------------
__global__ __launch_bounds__(256) void mlp_mma_kernel(
    const float* __restrict__ in, const float* __restrict__ w,
    const float* __restrict__ b,
    const float* __restrict__ g0, const float* __restrict__ be0,
    const float* __restrict__ m0v, const float* __restrict__ v0)
{
    extern __shared__ char dyn[];
    __shared__ float s_ep[192];
    const int tid = threadIdx.x, lane = tid & 31, warp = tid >> 5;
    const int m0 = (warp >> 1) * 32, n0 = (warp & 1) * 32;
    const uint32_t S0 = smem_u32(dyn);

    if (tid < 64) {
        float sc = g0[tid] * rsqrtf(v0[tid] + 1e-3f);
        s_ep[tid] = b[tid];
        s_ep[64 + tid] = sc;
        s_ep[128 + tid] = be0[tid] - m0v[tid] * sc;
    }

    const float4* in4 = (const float4*)in;
    for (int i = tid; i < 2048; i += 256) {
        int row = i >> 4, c = i & 15;
        long n = (long)blockIdx.x * 128 + row;
        __half2 h0, h1;
        h0.x = h0.y = h1.x = h1.y = __float2half_rn(0.f);
        if (n < N_PTS) {
            float4 raw = in4[n * 16 + c];
            h0.x = __float2half_rn(raw.x); h0.y = __float2half_rn(raw.y);
            h1.x = __float2half_rn(raw.z); h1.y = __float2half_rn(raw.w);
        }
        uint32_t d = row * 128 + ((((uint32_t)(c >> 1)) ^ (row & 7)) << 4)
                     + (c & 1) * 8;
        *(__half2*)(dyn + d)     = h0;
        *(__half2*)(dyn + d + 4) = h1;
    }
    for (int i = tid; i < 4096; i += 256) {
        int ci = i >> 6, co = i & 63;
        uint32_t d = co * 128 + ((((uint32_t)(ci >> 3)) ^ (co & 7)) << 4)
                     + (ci & 7) * 2;
        *(__half*)(dyn + 16384 + d) = __float2half_rn(w[i]);
    }
    __syncthreads();

    float acc[2][4][4];
#pragma unroll
    for (int a = 0; a < 2; ++a)
#pragma unroll
        for (int x = 0; x < 4; ++x)
#pragma unroll
            for (int c = 0; c < 4; ++c) acc[a][x][c] = 0.f;

    const int arow = lane & 15, asel = lane >> 4;
    const int brow = lane & 7, bsel = (lane >> 3) & 1;
#pragma unroll
    for (int kc = 0; kc < 4; ++kc) {
        uint32_t af[2][4], bf[4][2];
#pragma unroll
        for (int mt = 0; mt < 2; ++mt) {
            int row = m0 + mt * 16 + arow;
            ldsm_x4(af[mt], S0 + row * 128 +
                    (((uint32_t)((kc * 2 + asel) ^ (row & 7))) << 4));
        }
#pragma unroll
        for (int nt = 0; nt < 4; ++nt) {
            int row = n0 + nt * 8 + brow;
            ldsm_x2(bf[nt], S0 + 16384 + row * 128 +
                    (((uint32_t)((kc * 2 + bsel) ^ (row & 7))) << 4));
        }
#pragma unroll
        for (int mt = 0; mt < 2; ++mt)
#pragma unroll
            for (int nt = 0; nt < 4; ++nt)
                mma_f16(acc[mt][nt], af[mt], bf[nt]);
    }

    const int gr = lane >> 2, tig = lane & 3;
#pragma unroll
    for (int mt = 0; mt < 2; ++mt)
#pragma unroll
        for (int half = 0; half < 2; ++half) {
            long n = (long)blockIdx.x * 128 + m0 + mt * 16 + half * 8 + gr;
            if (n >= N_PTS) continue;
#pragma unroll
            for (int nt = 0; nt < 4; ++nt) {
                int col = n0 + nt * 8 + tig * 2;
                float v0r = fmaxf(acc[mt][nt][half * 2 + 0] + s_ep[col], 0.f)
                            * s_ep[64 + col] + s_ep[128 + col];
                float v1r = fmaxf(acc[mt][nt][half * 2 + 1] + s_ep[col + 1], 0.f)
                            * s_ep[64 + col + 1] + s_ep[128 + col + 1];
                float2 fv; fv.x = v0r; fv.y = v1r;
                *(float2*)&g_mlp[n * 64 + col] = fv;
            }
        }
}

// ---------------------------------------------------------------------------
// Pipelined fp16 mma implicit-GEMM conv.
// CTA = 256 padded rows x 64 couts, 8 warps (256 threads), warp tile 64x32
// (warp grid 4M x 2N) -> 2 warps per SMSP for latency hiding.
// 9 stages (dx,dy), cp.async double-buffered. Per stage per warp:
// 3 dz x 4 kc x (4 ldsm_x4 A, 4 ldsm_x2 W, 16 m16n8k16 mma).
// buffer: A [0, 33024) (258 rows x 128B swizzled), W [33024 + dz*8192)
// ---------------------------------------------------------------------------
template<int STAGE>
__device__ __forceinline__ void conv_stage_async(
    uint32_t Sbuf, const __half* __restrict__ SRC,
    const uint4* __restrict__ Wsrc, long blockbase, int s, int tid)
{
    const int dx = s / 3, dy = s % 3, tap0 = s * 3;
    const long w0 = (long)GUARD + blockbase
                    + (long)(dx - 1) * PXS + (dy - 1) * PYS - 1;
    const uint4* asrc = (const uint4*)SRC + w0 * 8;
    for (int i = tid; i < 2064; i += 256) {
        int row = i >> 3, c = i & 7;
        uint32_t d = Sbuf + row * 128 + (((uint32_t)(c ^ (row & 7))) << 4);
        CP_ASYNC16(d, asrc + i);
    }
    for (int i = tid; i < 1536; i += 256) {
        int t3 = i >> 9, r = (i >> 3) & 63, c = i & 7;
        uint32_t d = Sbuf + ABYTES + t3 * 8192 + r * 128 +
                     (((uint32_t)(c ^ (r & 7))) << 4);
        CP_ASYNC16(d, Wsrc + (tap0 + t3) * 512 + r * 8 + c);
    }
}

template<int STAGE>
__global__ __launch_bounds__(256) void conv_mma_kernel(
    const float* __restrict__ cb, const float* __restrict__ g,
    const float* __restrict__ be, const float* __restrict__ m,
    const float* __restrict__ v)
{
    extern __shared__ char dyn[];
    __shared__ float s_ep[192];
    const int tid = threadIdx.x, lane = tid & 31, warp = tid >> 5;
    const int m0 = (warp >> 1) * 64;   // 4 m-groups of 64 rows
    const int n0 = (warp & 1) * 32;    // 2 n-halves of 32 couts
    const uint32_t S0 = smem_u32(dyn);

    if (tid < 64) {
        float sc = g[tid] * rsqrtf(v[tid] + 1e-3f);
        s_ep[tid] = cb[tid];
        s_ep[64 + tid] = sc;
        s_ep[128 + tid] = be[tid] - m[tid] * sc;
    }

    const __half* __restrict__ SRC = (STAGE == 1) ? g_P : g_Q;
    const uint4* __restrict__ Wsrc = (const uint4*)g_W[STAGE - 1];
    const long blockbase = (long)blockIdx.x * 256;

    float acc[4][4][4];
#pragma unroll
    for (int a = 0; a < 4; ++a)
#pragma unroll
        for (int x = 0; x < 4; ++x)
#pragma unroll
            for (int c = 0; c < 4; ++c) acc[a][x][c] = 0.f;

    const int arow = lane & 15, asel = lane >> 4;
    const int brow = lane & 7, bsel = (lane >> 3) & 1;

    conv_stage_async<STAGE>(S0, SRC, Wsrc, blockbase, 0, tid);
    CP_COMMIT();

    for (int s = 0; s < 9; ++s) {
        if (s < 8) {
            conv_stage_async<STAGE>(S0 + ((s + 1) & 1) * BUFBYTES, SRC, Wsrc,
                                    blockbase, s + 1, tid);
            CP_COMMIT();
            CP_WAIT(1);
        } else {
            CP_WAIT(0);
        }
        __syncthreads();

        const uint32_t SA = S0 + (s & 1) * BUFBYTES;
        const uint32_t SW = SA + ABYTES;
        for (int dz = 0; dz < 3; ++dz) {
#pragma unroll
            for (int kc = 0; kc < 4; ++kc) {
                uint32_t af[4][4], bf[4][2];
#pragma unroll
                for (int mt = 0; mt < 4; ++mt) {
                    int row = dz + m0 + mt * 16 + arow;
                    ldsm_x4(af[mt], SA + row * 128 +
                            (((uint32_t)((kc * 2 + asel) ^ (row & 7))) << 4));
                }
#pragma unroll
                for (int nt = 0; nt < 4; ++nt) {
                    int row = n0 + nt * 8 + brow;
                    ldsm_x2(bf[nt], SW + dz * 8192 + row * 128 +
                            (((uint32_t)((kc * 2 + bsel) ^ (row & 7))) << 4));
                }
#pragma unroll
                for (int mt = 0; mt < 4; ++mt)
#pragma unroll
                    for (int nt = 0; nt < 4; ++nt)
                        mma_f16(acc[mt][nt], af[mt], bf[nt]);
            }
        }
        __syncthreads();
    }

    // ---- epilogue: bias + relu + BN ----
    const int gr = lane >> 2, tig = lane & 3;
#pragma unroll
    for (int mt = 0; mt < 4; ++mt)
#pragma unroll
        for (int half = 0; half < 2; ++half) {
            int rl = m0 + mt * 16 + half * 8 + gr;
            long p = blockbase + rl;
            if (p >= PTOT) continue;
            if (STAGE == 1) {
                int x = (int)(p / PXS);
                int rem = (int)(p - (long)x * PXS);
                int y = rem / PYS, z = rem - y * PYS;
                bool valid = (x >= 1) && (x <= 64) && (y >= 1) && (y <= 64)
                             && (z >= 1) && (z <= 64);
                if (!valid) continue;   // pads of g_Q must stay zero
            }
            long base = (GUARD + p) * 64;
#pragma unroll
            for (int nt = 0; nt < 4; ++nt) {
                int col = n0 + nt * 8 + tig * 2;
                float v0r = fmaxf(acc[mt][nt][half * 2 + 0] + s_ep[col], 0.f)
                            * s_ep[64 + col] + s_ep[128 + col];
                float v1r = fmaxf(acc[mt][nt][half * 2 + 1] + s_ep[col + 1], 0.f)
                            * s_ep[64 + col + 1] + s_ep[128 + col + 1];
                __half2 hv;
                hv.x = __float2half_rn(v0r);
                hv.y = __float2half_rn(v1r);
                if (STAGE == 1) *(__half2*)&g_Q[base + col]   = hv;
                else            *(__half2*)&g_h2p[base + col] = hv;
            }
        }
}

// ---------------------------------------------------------------------------
// devoxelize: trilinear gather from fp16 g_h2p + residual add of g_mlp.
// ---------------------------------------------------------------------------
__global__ void gather_kernel(const float* __restrict__ coords,
                              float* __restrict__ out)
{
    int t = blockIdx.x * blockDim.x + threadIdx.x;
    if (t >= N_PTS * 32) return;
    int n = t >> 5, c2 = (t & 31) << 1;

    float px = fminf(fmaxf(coords[n * 3 + 0], 0.f), 63.f);
    float py = fminf(fmaxf(coords[n * 3 + 1], 0.f), 63.f);
    float pz = fminf(fmaxf(coords[n * 3 + 2], 0.f), 63.f);
    float fx = floorf(px), fy = floorf(py), fz = floorf(pz);
    int x0 = (int)fx, y0 = (int)fy, z0 = (int)fz;
    int x1 = min(x0 + 1, 63), y1 = min(y0 + 1, 63), z1 = min(z0 + 1, 63);
    float tx = px - fx, ty = py - fy, tz = pz - fz;

    auto at = [&](int x, int y, int z) {
        long row = (long)GUARD + (long)(x + 1) * PXS + (y + 1) * PYS + (z + 1);
        __half2 h = *(const __half2*)&g_h2p[row * 64 + c2];
        return __half22float2(h);
    };
    float2 r = *(const float2*)&g_mlp[n * 64 + c2];
    float2 f;
    float w;
    w = (1.f - tx) * (1.f - ty) * (1.f - tz); f = at(x0, y0, z0); r.x += w * f.x; r.y += w * f.y;
    w = (1.f - tx) * (1.f - ty) * tz;          f = at(x0, y0, z1); r.x += w * f.x; r.y += w * f.y;
    w = (1.f - tx) * ty          * (1.f - tz); f = at(x0, y1, z0); r.x += w * f.x; r.y += w * f.y;
    w = (1.f - tx) * ty          * tz;          f = at(x0, y1, z1); r.x += w * f.x; r.y += w * f.y;
    w = tx          * (1.f - ty) * (1.f - tz); f = at(x1, y0, z0); r.x += w * f.x; r.y += w * f.y;
    w = tx          * (1.f - ty) * tz;          f = at(x1, y0, z1); r.x += w * f.x; r.y += w * f.y;
    w = tx          * ty          * (1.f - tz); f = at(x1, y1, z0); r.x += w * f.x; r.y += w * f.y;
    w = tx          * ty          * tz;          f = at(x1, y1, z1); r.x += w * f.x; r.y += w * f.y;

    *(float2*)&out[n * 64 + c2] = r;
}

// ---------------------------------------------------------------------------
extern "C" void kernel_launch(void* const* d_in, const int* in_sizes, int n_in,
                              void* d_out, int out_size)
{
    const float* inputs    = (const float*)d_in[0];
    const float* pt_coords = (const float*)d_in[1];
    const int*   vidx      = (const int*)  d_in[2];
    const float* pinv      = (const float*)d_in[3];
    const float* w_mlp     = (const float*)d_in[4];
    const float* b_mlp     = (const float*)d_in[5];
    const float* g0        = (const float*)d_in[6];
    const float* be0       = (const float*)d_in[7];
    const float* m0        = (const float*)d_in[8];
    const float* v0        = (const float*)d_in[9];
    const float* k1        = (const float*)d_in[10];
    const float* cb1       = (const float*)d_in[11];
    const float* g1        = (const float*)d_in[12];
    const float* be1       = (const float*)d_in[13];
    const float* m1        = (const float*)d_in[14];
    const float* v1        = (const float*)d_in[15];
    const float* k2        = (const float*)d_in[16];
    const float* cb2       = (const float*)d_in[17];
    const float* g2        = (const float*)d_in[18];
    const float* be2       = (const float*)d_in[19];
    const float* m2        = (const float*)d_in[20];
    const float* v2        = (const float*)d_in[21];
    float* out = (float*)d_out;

    // one-time host-side resource setup (no device memory involved)
    static cudaStream_t s2 = nullptr;
    static cudaEvent_t evFork = nullptr, evJoin = nullptr;
    static cudaEvent_t evC1 = nullptr, evZ = nullptr;
    if (s2 == nullptr) {
        cudaStreamCreateWithFlags(&s2, cudaStreamNonBlocking);
        cudaEventCreateWithFlags(&evFork, cudaEventDisableTiming);
        cudaEventCreateWithFlags(&evJoin, cudaEventDisableTiming);
        cudaEventCreateWithFlags(&evC1, cudaEventDisableTiming);
        cudaEventCreateWithFlags(&evZ, cudaEventDisableTiming);
    }

    const int DSMEM_MLP = 24576;
    cudaFuncSetAttribute(conv_mma_kernel<1>,
                         cudaFuncAttributeMaxDynamicSharedMemorySize, DSMEM_CONV);
    cudaFuncSetAttribute(conv_mma_kernel<2>,
                         cudaFuncAttributeMaxDynamicSharedMemorySize, DSMEM_CONV);
    cudaFuncSetAttribute(mlp_mma_kernel,
                         cudaFuncAttributeMaxDynamicSharedMemorySize, DSMEM_MLP);

    cudaEventRecord(evFork, 0);
    cudaStreamWaitEvent(s2, evFork, 0);

    // main stream: scatter (fused voxelize+scale) then weights then conv1
    scatter_kernel<<<(N_PTS * 32 + 255) / 256, 256>>>(inputs, vidx, pinv);
    build_W_kernel<<<(2 * 27 * 64 * 64 + 255) / 256, 256>>>(k1, k2);

    // s2: point branch, independent of the voxel chain
    mlp_mma_kernel<<<NTILE_M, 256, DSMEM_MLP, s2>>>(inputs, w_mlp, b_mlp,
                                                    g0, be0, m0, v0);
    cudaEventRecord(evJoin, s2);

    conv_mma_kernel<1><<<NTILE2, 256, DSMEM_CONV>>>(cb1, g1, be1, m1, v1);
    cudaEventRecord(evC1, 0);

    // s2: re-zero g_P for the next replay, concurrent with conv2
    cudaStreamWaitEvent(s2, evC1, 0);
    zero_P_kernel<<<2048, 256, 0, s2>>>();
    cudaEventRecord(evZ, s2);

    conv_mma_kernel<2><<<NTILE2, 256, DSMEM_CONV>>>(cb2, g2, be2, m2, v2);

    // join: gather needs conv2 (stream 0), mlp and zero_P (s2)
    cudaStreamWaitEvent(0, evJoin, 0);
    cudaStreamWaitEvent(0, evZ, 0);
    gather_kernel<<<(N_PTS * 32 + 255) / 256, 256>>>(pt_coords, out);
}

// round 13
// speedup vs baseline: 6.4238x; 1.1081x over previous
#include <cuda_runtime.h>
#include <cuda_fp16.h>
#include <cstdint>

#define N_PTS 200000
#define GRIDVOL (64*64*64)

// padded 66^3 flat grid + guard rows so every tap-shifted 514-row window
// stays in-bounds.
#define PXS 4356            // x stride (66*66)
#define PYS 66              // y stride
#define PTOT 287496         // 66^3
#define GUARD 4800
#define PROWS (PTOT + 2*GUARD)   // 297096
#define MTILE 512
#define NTILE2 562          // ceil(PTOT/512)
#define NTILE_M 1563        // ceil(N_PTS/128)

// conv smem (fp16): per buffer A 514*128 + W 3*8192
#define ABYTES 65792
#define WBYTES 24576
#define BUFBYTES (ABYTES + WBYTES)          // 90368
#define DSMEM_CONV (2 * BUFBYTES)           // 180736

// ---- scratch (allocation-free: __device__ globals, zero-initialized) ----
__device__ __half g_P[PROWS*64];          // conv1 input fp16: scatter target
                                          // (pre-scaled by pinv; pads stay 0)
__device__ __half g_Q[PROWS*64];          // conv2 input fp16 (pads stay 0)
__device__ __half g_h2p[PROWS*64];        // conv2 output fp16, padded
__device__ float g_mlp[N_PTS*64];         // point branch
__device__ __half g_W[2][27*64*64];       // weights [tap][cout][cin] fp16

// ---------------------------------------------------------------------------
// helpers
// ---------------------------------------------------------------------------
__device__ __forceinline__ uint32_t smem_u32(const void* p) {
    uint32_t a;
    asm("{ .reg .u64 t; cvta.to.shared.u64 t, %1; cvt.u32.u64 %0, t; }"
        : "=r"(a) : "l"(p));
    return a;
}
__device__ __forceinline__ void ldsm_x4(uint32_t* r, uint32_t a) {
    asm volatile("ldmatrix.sync.aligned.m8n8.x4.shared.b16 {%0,%1,%2,%3}, [%4];"
        : "=r"(r[0]), "=r"(r[1]), "=r"(r[2]), "=r"(r[3]) : "r"(a));
}
__device__ __forceinline__ void ldsm_x2(uint32_t* r, uint32_t a) {
    asm volatile("ldmatrix.sync.aligned.m8n8.x2.shared.b16 {%0,%1}, [%2];"
        : "=r"(r[0]), "=r"(r[1]) : "r"(a));
}
__device__ __forceinline__ void mma_f16(float* c, const uint32_t* a,
                                        const uint32_t* b) {
    asm volatile("mma.sync.aligned.m16n8k16.row.col.f32.f16.f16.f32 "
        "{%0,%1,%2,%3}, {%4,%5,%6,%7}, {%8,%9}, {%0,%1,%2,%3};"
        : "+f"(c[0]), "+f"(c[1]), "+f"(c[2]), "+f"(c[3])
        : "r"(a[0]), "r"(a[1]), "r"(a[2]), "r"(a[3]), "r"(b[0]), "r"(b[1]));
}
#define CP_ASYNC16(dst, src) \
    asm volatile("cp.async.cg.shared.global [%0], [%1], 16;" \
        :: "r"(dst), "l"(src) : "memory")
#define CP_COMMIT() asm volatile("cp.async.commit_group;" ::: "memory")
#define CP_WAIT(n)  asm volatile("cp.async.wait_group %0;" :: "n"(n) : "memory")

// ---------------------------------------------------------------------------
// voxelize fused: atomicAdd half2 of (in * pinv) directly into padded g_P.
// ---------------------------------------------------------------------------
__global__ void scatter_kernel(const float* __restrict__ in,
                               const int* __restrict__ vidx,
                               const float* __restrict__ pinv)
{
    int t = blockIdx.x * blockDim.x + threadIdx.x;
    if (t >= N_PTS * 32) return;
    int n = t >> 5, c2 = t & 31;
    int ix = vidx[n * 3 + 0];
    int iy = vidx[n * 3 + 1];
    int iz = vidx[n * 3 + 2];
    int vox = (((ix << 6) + iy) << 6) + iz;
    float s = pinv[vox];
    float2 v = ((const float2*)in)[n * 32 + c2];
    __half2 h;
    h.x = __float2half_rn(v.x * s);
    h.y = __float2half_rn(v.y * s);
    long p = (long)(ix + 1) * PXS + (iy + 1) * PYS + (iz + 1);
    atomicAdd((__half2*)&g_P[(GUARD + p) * 64 + c2 * 2], h);
}

// ---------------------------------------------------------------------------
// re-zero g_P's real-voxel region for the next graph replay
// ---------------------------------------------------------------------------
__global__ void zero_P_kernel() {
    float4* p = (float4*)&g_P[(long)GUARD * 64];
    const long n4 = (long)PTOT * 64 / 8;   // halfs -> float4 units
    for (long i = blockIdx.x * blockDim.x + threadIdx.x; i < n4;
         i += (long)gridDim.x * blockDim.x)
        p[i] = make_float4(0.f, 0.f, 0.f, 0.f);
}

// ---------------------------------------------------------------------------
// weight prep (both conv stages in one launch):
// k [tap][cin][cout] fp32 -> [tap][cout][cin] fp16
// ---------------------------------------------------------------------------
__global__ void build_W_kernel(const float* __restrict__ k1,
                               const float* __restrict__ k2) {
    int i = blockIdx.x * blockDim.x + threadIdx.x;
    const int n = 27 * 64 * 64;
    if (i >= 2 * n) return;
    int stage = (i >= n);
    int j = i - stage * n;
    const float* k = stage ? k2 : k1;
    int tap = j >> 12, r = j & 4095, cin = r >> 6, cout = r & 63;
    g_W[stage][(tap << 12) + (cout << 6) + cin] = __float2half_rn(k[j]);
}

// ---------------------------------------------------------------------------
// MLP as fp16 mma GEMM: CTA = 128 points x 64 couts, 8 warps (32x32 tiles)
// ---------------------------------------------------------------------------
__global__ __launch_bounds__(256) void mlp_mma_kernel(
    const float* __restrict__ in, const float* __restrict__ w,
    const float* __restrict__ b,
    const float* __restrict__ g0, const float* __restrict__ be0,
    const float* __restrict__ m0v, const float* __restrict__ v0)
{
    extern __shared__ char dyn[];
    __shared__ float s_ep[192];
    const int tid = threadIdx.x, lane = tid & 31, warp = tid >> 5;
    const int m0 = (warp >> 1) * 32, n0 = (warp & 1) * 32;
    const uint32_t S0 = smem_u32(dyn);

    if (tid < 64) {
        float sc = g0[tid] * rsqrtf(v0[tid] + 1e-3f);
        s_ep[tid] = b[tid];
        s_ep[64 + tid] = sc;
        s_ep[128 + tid] = be0[tid] - m0v[tid] * sc;
    }

    const float4* in4 = (const float4*)in;
    for (int i = tid; i < 2048; i += 256) {
        int row = i >> 4, c = i & 15;
        long n = (long)blockIdx.x * 128 + row;
        __half2 h0, h1;
        h0.x = h0.y = h1.x = h1.y = __float2half_rn(0.f);
        if (n < N_PTS) {
            float4 raw = in4[n * 16 + c];
            h0.x = __float2half_rn(raw.x); h0.y = __float2half_rn(raw.y);
            h1.x = __float2half_rn(raw.z); h1.y = __float2half_rn(raw.w);
        }
        uint32_t d = row * 128 + ((((uint32_t)(c >> 1)) ^ (row & 7)) << 4)
                     + (c & 1) * 8;
        *(__half2*)(dyn + d)     = h0;
        *(__half2*)(dyn + d + 4) = h1;
    }
    for (int i = tid; i < 4096; i += 256) {
        int ci = i >> 6, co = i & 63;
        uint32_t d = co * 128 + ((((uint32_t)(ci >> 3)) ^ (co & 7)) << 4)
                     + (ci & 7) * 2;
        *(__half*)(dyn + 16384 + d) = __float2half_rn(w[i]);
    }
    __syncthreads();

    float acc[2][4][4];
#pragma unroll
    for (int a = 0; a < 2; ++a)
#pragma unroll
        for (int x = 0; x < 4; ++x)
#pragma unroll
            for (int c = 0; c < 4; ++c) acc[a][x][c] = 0.f;

    const int arow = lane & 15, asel = lane >> 4;
    const int brow = lane & 7, bsel = (lane >> 3) & 1;
#pragma unroll
    for (int kc = 0; kc < 4; ++kc) {
        uint32_t af[2][4], bf[4][2];
#pragma unroll
        for (int mt = 0; mt < 2; ++mt) {
            int row = m0 + mt * 16 + arow;
            ldsm_x4(af[mt], S0 + row * 128 +
                    (((uint32_t)((kc * 2 + asel) ^ (row & 7))) << 4));
        }
#pragma unroll
        for (int nt = 0; nt < 4; ++nt) {
            int row = n0 + nt * 8 + brow;
            ldsm_x2(bf[nt], S0 + 16384 + row * 128 +
                    (((uint32_t)((kc * 2 + bsel) ^ (row & 7))) << 4));
        }
#pragma unroll
        for (int mt = 0; mt < 2; ++mt)
#pragma unroll
            for (int nt = 0; nt < 4; ++nt)
                mma_f16(acc[mt][nt], af[mt], bf[nt]);
    }

    const int gr = lane >> 2, tig = lane & 3;
#pragma unroll
    for (int mt = 0; mt < 2; ++mt)
#pragma unroll
        for (int half = 0; half < 2; ++half) {
            long n = (long)blockIdx.x * 128 + m0 + mt * 16 + half * 8 + gr;
            if (n >= N_PTS) continue;
#pragma unroll
            for (int nt = 0; nt < 4; ++nt) {
                int col = n0 + nt * 8 + tig * 2;
                float v0r = fmaxf(acc[mt][nt][half * 2 + 0] + s_ep[col], 0.f)
                            * s_ep[64 + col] + s_ep[128 + col];
                float v1r = fmaxf(acc[mt][nt][half * 2 + 1] + s_ep[col + 1], 0.f)
                            * s_ep[64 + col + 1] + s_ep[128 + col + 1];
                float2 fv; fv.x = v0r; fv.y = v1r;
                *(float2*)&g_mlp[n * 64 + col] = fv;
            }
        }
}

// ---------------------------------------------------------------------------
// Pipelined fp16 mma implicit-GEMM conv.
// CTA = 512 padded rows x 64 couts, 16 warps (512 threads), warp tile 64x32
// (warp grid 8M x 2N) -> 4 warps per SMSP for latency hiding.
// 9 stages (dx,dy), cp.async double-buffered. Per stage per warp:
// 3 dz x 4 kc x (4 ldsm_x4 A, 4 ldsm_x2 W, 16 m16n8k16 mma).
// buffer: A [0, 65792) (514 rows x 128B swizzled), W [65792 + dz*8192)
// ---------------------------------------------------------------------------
template<int STAGE>
__device__ __forceinline__ void conv_stage_async(
    uint32_t Sbuf, const __half* __restrict__ SRC,
    const uint4* __restrict__ Wsrc, long blockbase, int s, int tid)
{
    const int dx = s / 3, dy = s % 3, tap0 = s * 3;
    const long w0 = (long)GUARD + blockbase
                    + (long)(dx - 1) * PXS + (dy - 1) * PYS - 1;
    const uint4* asrc = (const uint4*)SRC + w0 * 8;
    for (int i = tid; i < 4112; i += 512) {
        int row = i >> 3, c = i & 7;
        uint32_t d = Sbuf + row * 128 + (((uint32_t)(c ^ (row & 7))) << 4);
        CP_ASYNC16(d, asrc + i);
    }
    for (int i = tid; i < 1536; i += 512) {
        int t3 = i >> 9, r = (i >> 3) & 63, c = i & 7;
        uint32_t d = Sbuf + ABYTES + t3 * 8192 + r * 128 +
                     (((uint32_t)(c ^ (r & 7))) << 4);
        CP_ASYNC16(d, Wsrc + (tap0 + t3) * 512 + r * 8 + c);
    }
}

template<int STAGE>
__global__ __launch_bounds__(512, 1) void conv_mma_kernel(
    const float* __restrict__ cb, const float* __restrict__ g,
    const float* __restrict__ be, const float* __restrict__ m,
    const float* __restrict__ v)
{
    extern __shared__ char dyn[];
    __shared__ float s_ep[192];
    const int tid = threadIdx.x, lane = tid & 31, warp = tid >> 5;
    const int m0 = (warp >> 1) * 64;   // 8 m-groups of 64 rows
    const int n0 = (warp & 1) * 32;    // 2 n-halves of 32 couts
    const uint32_t S0 = smem_u32(dyn);

    if (tid < 64) {
        float sc = g[tid] * rsqrtf(v[tid] + 1e-3f);
        s_ep[tid] = cb[tid];
        s_ep[64 + tid] = sc;
        s_ep[128 + tid] = be[tid] - m[tid] * sc;
    }

    const __half* __restrict__ SRC = (STAGE == 1) ? g_P : g_Q;
    const uint4* __restrict__ Wsrc = (const uint4*)g_W[STAGE - 1];
    const long blockbase = (long)blockIdx.x * MTILE;

    float acc[4][4][4];
#pragma unroll
    for (int a = 0; a < 4; ++a)
#pragma unroll
        for (int x = 0; x < 4; ++x)
#pragma unroll
            for (int c = 0; c < 4; ++c) acc[a][x][c] = 0.f;

    const int arow = lane & 15, asel = lane >> 4;
    const int brow = lane & 7, bsel = (lane >> 3) & 1;

    conv_stage_async<STAGE>(S0, SRC, Wsrc, blockbase, 0, tid);
    CP_COMMIT();

    for (int s = 0; s < 9; ++s) {
        if (s < 8) {
            conv_stage_async<STAGE>(S0 + ((s + 1) & 1) * BUFBYTES, SRC, Wsrc,
                                    blockbase, s + 1, tid);
            CP_COMMIT();
            CP_WAIT(1);
        } else {
            CP_WAIT(0);
        }
        __syncthreads();

        const uint32_t SA = S0 + (s & 1) * BUFBYTES;
        const uint32_t SW = SA + ABYTES;
        for (int dz = 0; dz < 3; ++dz) {
#pragma unroll
            for (int kc = 0; kc < 4; ++kc) {
                uint32_t af[4][4], bf[4][2];
#pragma unroll
                for (int mt = 0; mt < 4; ++mt) {
                    int row = dz + m0 + mt * 16 + arow;
                    ldsm_x4(af[mt], SA + row * 128 +
                            (((uint32_t)((kc * 2 + asel) ^ (row & 7))) << 4));
                }
#pragma unroll
                for (int nt = 0; nt < 4; ++nt) {
                    int row = n0 + nt * 8 + brow;
                    ldsm_x2(bf[nt], SW + dz * 8192 + row * 128 +
                            (((uint32_t)((kc * 2 + bsel) ^ (row & 7))) << 4));
                }
#pragma unroll
                for (int mt = 0; mt < 4; ++mt)
#pragma unroll
                    for (int nt = 0; nt < 4; ++nt)
                        mma_f16(acc[mt][nt], af[mt], bf[nt]);
            }
        }
        __syncthreads();
    }

    // ---- epilogue: bias + relu + BN ----
    const int gr = lane >> 2, tig = lane & 3;
#pragma unroll
    for (int mt = 0; mt < 4; ++mt)
#pragma unroll
        for (int half = 0; half < 2; ++half) {
            int rl = m0 + mt * 16 + half * 8 + gr;
            long p = blockbase + rl;
            if (p >= PTOT) continue;
            if (STAGE == 1) {
                int x = (int)(p / PXS);
                int rem = (int)(p - (long)x * PXS);
                int y = rem / PYS, z = rem - y * PYS;
                bool valid = (x >= 1) && (x <= 64) && (y >= 1) && (y <= 64)
                             && (z >= 1) && (z <= 64);
                if (!valid) continue;   // pads of g_Q must stay zero
            }
            long base = (GUARD + p) * 64;
#pragma unroll
            for (int nt = 0; nt < 4; ++nt) {
                int col = n0 + nt * 8 + tig * 2;
                float v0r = fmaxf(acc[mt][nt][half * 2 + 0] + s_ep[col], 0.f)
                            * s_ep[64 + col] + s_ep[128 + col];
                float v1r = fmaxf(acc[mt][nt][half * 2 + 1] + s_ep[col + 1], 0.f)
                            * s_ep[64 + col + 1] + s_ep[128 + col + 1];
                __half2 hv;
                hv.x = __float2half_rn(v0r);
                hv.y = __float2half_rn(v1r);
                if (STAGE == 1) *(__half2*)&g_Q[base + col]   = hv;
                else            *(__half2*)&g_h2p[base + col] = hv;
            }
        }
}

// ---------------------------------------------------------------------------
// devoxelize: trilinear gather from fp16 g_h2p + residual add of g_mlp.
// ---------------------------------------------------------------------------
__global__ void gather_kernel(const float* __restrict__ coords,
                              float* __restrict__ out)
{
    int t = blockIdx.x * blockDim.x + threadIdx.x;
    if (t >= N_PTS * 32) return;
    int n = t >> 5, c2 = (t & 31) << 1;

    float px = fminf(fmaxf(coords[n * 3 + 0], 0.f), 63.f);
    float py = fminf(fmaxf(coords[n * 3 + 1], 0.f), 63.f);
    float pz = fminf(fmaxf(coords[n * 3 + 2], 0.f), 63.f);
    float fx = floorf(px), fy = floorf(py), fz = floorf(pz);
    int x0 = (int)fx, y0 = (int)fy, z0 = (int)fz;
    int x1 = min(x0 + 1, 63), y1 = min(y0 + 1, 63), z1 = min(z0 + 1, 63);
    float tx = px - fx, ty = py - fy, tz = pz - fz;

    auto at = [&](int x, int y, int z) {
        long row = (long)GUARD + (long)(x + 1) * PXS + (y + 1) * PYS + (z + 1);
        __half2 h = *(const __half2*)&g_h2p[row * 64 + c2];
        return __half22float2(h);
    };
    float2 r = *(const float2*)&g_mlp[n * 64 + c2];
    float2 f;
    float w;
    w = (1.f - tx) * (1.f - ty) * (1.f - tz); f = at(x0, y0, z0); r.x += w * f.x; r.y += w * f.y;
    w = (1.f - tx) * (1.f - ty) * tz;          f = at(x0, y0, z1); r.x += w * f.x; r.y += w * f.y;
    w = (1.f - tx) * ty          * (1.f - tz); f = at(x0, y1, z0); r.x += w * f.x; r.y += w * f.y;
    w = (1.f - tx) * ty          * tz;          f = at(x0, y1, z1); r.x += w * f.x; r.y += w * f.y;
    w = tx          * (1.f - ty) * (1.f - tz); f = at(x1, y0, z0); r.x += w * f.x; r.y += w * f.y;
    w = tx          * (1.f - ty) * tz;          f = at(x1, y0, z1); r.x += w * f.x; r.y += w * f.y;
    w = tx          * ty          * (1.f - tz); f = at(x1, y1, z0); r.x += w * f.x; r.y += w * f.y;
    w = tx          * ty          * tz;          f = at(x1, y1, z1); r.x += w * f.x; r.y += w * f.y;

    *(float2*)&out[n * 64 + c2] = r;
}

// ---------------------------------------------------------------------------
extern "C" void kernel_launch(void* const* d_in, const int* in_sizes, int n_in,
                              void* d_out, int out_size)
{
    const float* inputs    = (const float*)d_in[0];
    const float* pt_coords = (const float*)d_in[1];
    const int*   vidx      = (const int*)  d_in[2];
    const float* pinv      = (const float*)d_in[3];
    const float* w_mlp     = (const float*)d_in[4];
    const float* b_mlp     = (const float*)d_in[5];
    const float* g0        = (const float*)d_in[6];
    const float* be0       = (const float*)d_in[7];
    const float* m0        = (const float*)d_in[8];
    const float* v0        = (const float*)d_in[9];
    const float* k1        = (const float*)d_in[10];
    const float* cb1       = (const float*)d_in[11];
    const float* g1        = (const float*)d_in[12];
    const float* be1       = (const float*)d_in[13];
    const float* m1        = (const float*)d_in[14];
    const float* v1        = (const float*)d_in[15];
    const float* k2        = (const float*)d_in[16];
    const float* cb2       = (const float*)d_in[17];
    const float* g2        = (const float*)d_in[18];
    const float* be2       = (const float*)d_in[19];
    const float* m2        = (const float*)d_in[20];
    const float* v2        = (const float*)d_in[21];
    float* out = (float*)d_out;

    // one-time host-side resource setup (no device memory involved)
    static cudaStream_t s2 = nullptr;
    static cudaEvent_t evFork = nullptr, evJoin = nullptr;
    static cudaEvent_t evC1 = nullptr, evZ = nullptr;
    if (s2 == nullptr) {
        cudaStreamCreateWithFlags(&s2, cudaStreamNonBlocking);
        cudaEventCreateWithFlags(&evFork, cudaEventDisableTiming);
        cudaEventCreateWithFlags(&evJoin, cudaEventDisableTiming);
        cudaEventCreateWithFlags(&evC1, cudaEventDisableTiming);
        cudaEventCreateWithFlags(&evZ, cudaEventDisableTiming);
    }

    const int DSMEM_MLP = 24576;
    cudaFuncSetAttribute(conv_mma_kernel<1>,
                         cudaFuncAttributeMaxDynamicSharedMemorySize, DSMEM_CONV);
    cudaFuncSetAttribute(conv_mma_kernel<2>,
                         cudaFuncAttributeMaxDynamicSharedMemorySize, DSMEM_CONV);
    cudaFuncSetAttribute(mlp_mma_kernel,
                         cudaFuncAttributeMaxDynamicSharedMemorySize, DSMEM_MLP);

    cudaEventRecord(evFork, 0);
    cudaStreamWaitEvent(s2, evFork, 0);

    // main stream: scatter (fused voxelize+scale) then weights then conv1
    scatter_kernel<<<(N_PTS * 32 + 255) / 256, 256>>>(inputs, vidx, pinv);
    build_W_kernel<<<(2 * 27 * 64 * 64 + 255) / 256, 256>>>(k1, k2);

    // s2: point branch, independent of the voxel chain
    mlp_mma_kernel<<<NTILE_M, 256, DSMEM_MLP, s2>>>(inputs, w_mlp, b_mlp,
                                                    g0, be0, m0, v0);
    cudaEventRecord(evJoin, s2);

    conv_mma_kernel<1><<<NTILE2, 512, DSMEM_CONV>>>(cb1, g1, be1, m1, v1);
    cudaEventRecord(evC1, 0);

    // s2: re-zero g_P for the next replay, concurrent with conv2
    cudaStreamWaitEvent(s2, evC1, 0);
    zero_P_kernel<<<2048, 256, 0, s2>>>();
    cudaEventRecord(evZ, s2);

    conv_mma_kernel<2><<<NTILE2, 512, DSMEM_CONV>>>(cb2, g2, be2, m2, v2);

    // join: gather needs conv2 (stream 0), mlp and zero_P (s2)
    cudaStreamWaitEvent(0, evJoin, 0);
    cudaStreamWaitEvent(0, evZ, 0);
    gather_kernel<<<(N_PTS * 32 + 255) / 256, 256>>>(pt_coords, out);
}

// round 14
// speedup vs baseline: 6.4799x; 1.0087x over previous
#include <cuda_runtime.h>
#include <cuda_fp16.h>
#include <cstdint>

#define N_PTS 200000
#define GRIDVOL (64*64*64)

// padded 66^3 flat grid + guard rows so every tap-shifted 514-row window
// stays in-bounds.
#define PXS 4356            // x stride (66*66)
#define PYS 66              // y stride
#define PTOT 287496         // 66^3
#define GUARD 4800
#define PROWS (PTOT + 2*GUARD)   // 297096
#define MTILE 512
#define NTILE2 562          // ceil(PTOT/512)
#define NTILE_M 1563        // ceil(N_PTS/128)

// conv smem (fp16): per buffer A 514*128 + W 3*8192
#define ABYTES 65792
#define WBYTES 24576
#define BUFBYTES (ABYTES + WBYTES)          // 90368
#define DSMEM_CONV (2 * BUFBYTES)           // 180736

// ---- scratch (allocation-free: __device__ globals, zero-initialized) ----
__device__ __half g_P[PROWS*64];          // conv1 input fp16: scatter target
                                          // (pre-scaled by pinv; pads stay 0)
__device__ __half g_Q[PROWS*64];          // conv2 input fp16 (pads stay 0)
__device__ __half g_h2p[PROWS*64];        // conv2 output fp16, padded
__device__ float g_mlp[N_PTS*64];         // point branch
__device__ __half g_W[2][27*64*64];       // weights [tap][cout][cin] fp16

// ---------------------------------------------------------------------------
// helpers
// ---------------------------------------------------------------------------
__device__ __forceinline__ uint32_t smem_u32(const void* p) {
    uint32_t a;
    asm("{ .reg .u64 t; cvta.to.shared.u64 t, %1; cvt.u32.u64 %0, t; }"
        : "=r"(a) : "l"(p));
    return a;
}
__device__ __forceinline__ void ldsm_x4(uint32_t* r, uint32_t a) {
    asm volatile("ldmatrix.sync.aligned.m8n8.x4.shared.b16 {%0,%1,%2,%3}, [%4];"
        : "=r"(r[0]), "=r"(r[1]), "=r"(r[2]), "=r"(r[3]) : "r"(a));
}
__device__ __forceinline__ void ldsm_x2(uint32_t* r, uint32_t a) {
    asm volatile("ldmatrix.sync.aligned.m8n8.x2.shared.b16 {%0,%1}, [%2];"
        : "=r"(r[0]), "=r"(r[1]) : "r"(a));
}
__device__ __forceinline__ void mma_f16(float* c, const uint32_t* a,
                                        const uint32_t* b) {
    asm volatile("mma.sync.aligned.m16n8k16.row.col.f32.f16.f16.f32 "
        "{%0,%1,%2,%3}, {%4,%5,%6,%7}, {%8,%9}, {%0,%1,%2,%3};"
        : "+f"(c[0]), "+f"(c[1]), "+f"(c[2]), "+f"(c[3])
        : "r"(a[0]), "r"(a[1]), "r"(a[2]), "r"(a[3]), "r"(b[0]), "r"(b[1]));
}
#define CP_ASYNC16(dst, src) \
    asm volatile("cp.async.cg.shared.global [%0], [%1], 16;" \
        :: "r"(dst), "l"(src) : "memory")
#define CP_COMMIT() asm volatile("cp.async.commit_group;" ::: "memory")
#define CP_WAIT(n)  asm volatile("cp.async.wait_group %0;" :: "n"(n) : "memory")

// ---------------------------------------------------------------------------
// voxelize fused: atomicAdd half2 of (in * pinv) directly into padded g_P.
// ---------------------------------------------------------------------------
__global__ void scatter_kernel(const float* __restrict__ in,
                               const int* __restrict__ vidx,
                               const float* __restrict__ pinv)
{
    int t = blockIdx.x * blockDim.x + threadIdx.x;
    if (t >= N_PTS * 32) return;
    int n = t >> 5, c2 = t & 31;
    int ix = vidx[n * 3 + 0];
    int iy = vidx[n * 3 + 1];
    int iz = vidx[n * 3 + 2];
    int vox = (((ix << 6) + iy) << 6) + iz;
    float s = pinv[vox];
    float2 v = ((const float2*)in)[n * 32 + c2];
    __half2 h;
    h.x = __float2half_rn(v.x * s);
    h.y = __float2half_rn(v.y * s);
    long p = (long)(ix + 1) * PXS + (iy + 1) * PYS + (iz + 1);
    atomicAdd((__half2*)&g_P[(GUARD + p) * 64 + c2 * 2], h);
}

// ---------------------------------------------------------------------------
// re-zero g_P's real-voxel region for the next graph replay
// ---------------------------------------------------------------------------
__global__ void zero_P_kernel() {
    float4* p = (float4*)&g_P[(long)GUARD * 64];
    const long n4 = (long)PTOT * 64 / 8;   // halfs -> float4 units
    for (long i = blockIdx.x * blockDim.x + threadIdx.x; i < n4;
         i += (long)gridDim.x * blockDim.x)
        p[i] = make_float4(0.f, 0.f, 0.f, 0.f);
}

// ---------------------------------------------------------------------------
// weight prep (both conv stages in one launch):
// k [tap][cin][cout] fp32 -> [tap][cout][cin] fp16
// ---------------------------------------------------------------------------
__global__ void build_W_kernel(const float* __restrict__ k1,
                               const float* __restrict__ k2) {
    int i = blockIdx.x * blockDim.x + threadIdx.x;
    const int n = 27 * 64 * 64;
    if (i >= 2 * n) return;
    int stage = (i >= n);
    int j = i - stage * n;
    const float* k = stage ? k2 : k1;
    int tap = j >> 12, r = j & 4095, cin = r >> 6, cout = r & 63;
    g_W[stage][(tap << 12) + (cout << 6) + cin] = __float2half_rn(k[j]);
}

// ---------------------------------------------------------------------------
// MLP as fp16 mma GEMM: CTA = 128 points x 64 couts, 8 warps (32x32 tiles)
// ---------------------------------------------------------------------------
__global__ __launch_bounds__(256) void mlp_mma_kernel(
    const float* __restrict__ in, const float* __restrict__ w,
    const float* __restrict__ b,
    const float* __restrict__ g0, const float* __restrict__ be0,
    const float* __restrict__ m0v, const float* __restrict__ v0)
{
    extern __shared__ char dyn[];
    __shared__ float s_ep[192];
    const int tid = threadIdx.x, lane = tid & 31, warp = tid >> 5;
    const int m0 = (warp >> 1) * 32, n0 = (warp & 1) * 32;
    const uint32_t S0 = smem_u32(dyn);

    if (tid < 64) {
        float sc = g0[tid] * rsqrtf(v0[tid] + 1e-3f);
        s_ep[tid] = b[tid];
        s_ep[64 + tid] = sc;
        s_ep[128 + tid] = be0[tid] - m0v[tid] * sc;
    }

    const float4* in4 = (const float4*)in;
    for (int i = tid; i < 2048; i += 256) {
        int row = i >> 4, c = i & 15;
        long n = (long)blockIdx.x * 128 + row;
        __half2 h0, h1;
        h0.x = h0.y = h1.x = h1.y = __float2half_rn(0.f);
        if (n < N_PTS) {
            float4 raw = in4[n * 16 + c];
            h0.x = __float2half_rn(raw.x); h0.y = __float2half_rn(raw.y);
            h1.x = __float2half_rn(raw.z); h1.y = __float2half_rn(raw.w);
        }
        uint32_t d = row * 128 + ((((uint32_t)(c >> 1)) ^ (row & 7)) << 4)
                     + (c & 1) * 8;
        *(__half2*)(dyn + d)     = h0;
        *(__half2*)(dyn + d + 4) = h1;
    }
    for (int i = tid; i < 4096; i += 256) {
        int ci = i >> 6, co = i & 63;
        uint32_t d = co * 128 + ((((uint32_t)(ci >> 3)) ^ (co & 7)) << 4)
                     + (ci & 7) * 2;
        *(__half*)(dyn + 16384 + d) = __float2half_rn(w[i]);
    }
    __syncthreads();

    float acc[2][4][4];
#pragma unroll
    for (int a = 0; a < 2; ++a)
#pragma unroll
        for (int x = 0; x < 4; ++x)
#pragma unroll
            for (int c = 0; c < 4; ++c) acc[a][x][c] = 0.f;

    const int arow = lane & 15, asel = lane >> 4;
    const int brow = lane & 7, bsel = (lane >> 3) & 1;
#pragma unroll
    for (int kc = 0; kc < 4; ++kc) {
        uint32_t af[2][4], bf[4][2];
#pragma unroll
        for (int mt = 0; mt < 2; ++mt) {
            int row = m0 + mt * 16 + arow;
            ldsm_x4(af[mt], S0 + row * 128 +
                    (((uint32_t)((kc * 2 + asel) ^ (row & 7))) << 4));
        }
#pragma unroll
        for (int nt = 0; nt < 4; ++nt) {
            int row = n0 + nt * 8 + brow;
            ldsm_x2(bf[nt], S0 + 16384 + row * 128 +
                    (((uint32_t)((kc * 2 + bsel) ^ (row & 7))) << 4));
        }
#pragma unroll
        for (int mt = 0; mt < 2; ++mt)
#pragma unroll
            for (int nt = 0; nt < 4; ++nt)
                mma_f16(acc[mt][nt], af[mt], bf[nt]);
    }

    const int gr = lane >> 2, tig = lane & 3;
#pragma unroll
    for (int mt = 0; mt < 2; ++mt)
#pragma unroll
        for (int half = 0; half < 2; ++half) {
            long n = (long)blockIdx.x * 128 + m0 + mt * 16 + half * 8 + gr;
            if (n >= N_PTS) continue;
#pragma unroll
            for (int nt = 0; nt < 4; ++nt) {
                int col = n0 + nt * 8 + tig * 2;
                float v0r = fmaxf(acc[mt][nt][half * 2 + 0] + s_ep[col], 0.f)
                            * s_ep[64 + col] + s_ep[128 + col];
                float v1r = fmaxf(acc[mt][nt][half * 2 + 1] + s_ep[col + 1], 0.f)
                            * s_ep[64 + col + 1] + s_ep[128 + col + 1];
                float2 fv; fv.x = v0r; fv.y = v1r;
                *(float2*)&g_mlp[n * 64 + col] = fv;
            }
        }
}

// ---------------------------------------------------------------------------
// Pipelined fp16 mma implicit-GEMM conv.
// CTA = 512 padded rows x 64 couts, 8 warps (256 threads), warp tile 64x64
// (warp grid 8M x 1N). Fragment double-buffering: iteration i+1's ldsm are
// issued before iteration i's mma chain, hiding the ldsm->mma latency.
// 9 stages (dx,dy), cp.async double-buffered. Per stage per warp: 12 its
// (dz,kc), each 4 ldsm_x4 A + 8 ldsm_x2 W + 32 m16n8k16 mma.
// buffer: A [0, 65792) (514 rows x 128B swizzled), W [65792 + dz*8192)
// ---------------------------------------------------------------------------
template<int STAGE>
__device__ __forceinline__ void conv_stage_async(
    uint32_t Sbuf, const __half* __restrict__ SRC,
    const uint4* __restrict__ Wsrc, long blockbase, int s, int tid)
{
    const int dx = s / 3, dy = s % 3, tap0 = s * 3;
    const long w0 = (long)GUARD + blockbase
                    + (long)(dx - 1) * PXS + (dy - 1) * PYS - 1;
    const uint4* asrc = (const uint4*)SRC + w0 * 8;
    for (int i = tid; i < 4112; i += 256) {
        int row = i >> 3, c = i & 7;
        uint32_t d = Sbuf + row * 128 + (((uint32_t)(c ^ (row & 7))) << 4);
        CP_ASYNC16(d, asrc + i);
    }
    for (int i = tid; i < 1536; i += 256) {
        int t3 = i >> 9, r = (i >> 3) & 63, c = i & 7;
        uint32_t d = Sbuf + ABYTES + t3 * 8192 + r * 128 +
                     (((uint32_t)(c ^ (r & 7))) << 4);
        CP_ASYNC16(d, Wsrc + (tap0 + t3) * 512 + r * 8 + c);
    }
}

template<int STAGE>
__global__ __launch_bounds__(256, 1) void conv_mma_kernel(
    const float* __restrict__ cb, const float* __restrict__ g,
    const float* __restrict__ be, const float* __restrict__ m,
    const float* __restrict__ v)
{
    extern __shared__ char dyn[];
    __shared__ float s_ep[192];
    const int tid = threadIdx.x, lane = tid & 31, warp = tid >> 5;
    const int m0 = warp * 64;   // 8 m-groups of 64 rows, full 64 couts
    const uint32_t S0 = smem_u32(dyn);

    if (tid < 64) {
        float sc = g[tid] * rsqrtf(v[tid] + 1e-3f);
        s_ep[tid] = cb[tid];
        s_ep[64 + tid] = sc;
        s_ep[128 + tid] = be[tid] - m[tid] * sc;
    }

    const __half* __restrict__ SRC = (STAGE == 1) ? g_P : g_Q;
    const uint4* __restrict__ Wsrc = (const uint4*)g_W[STAGE - 1];
    const long blockbase = (long)blockIdx.x * MTILE;

    float acc[4][8][4];
#pragma unroll
    for (int a = 0; a < 4; ++a)
#pragma unroll
        for (int x = 0; x < 8; ++x)
#pragma unroll
            for (int c = 0; c < 4; ++c) acc[a][x][c] = 0.f;

    const int arow = lane & 15, asel = lane >> 4;
    const int brow = lane & 7, bsel = (lane >> 3) & 1;

    conv_stage_async<STAGE>(S0, SRC, Wsrc, blockbase, 0, tid);
    CP_COMMIT();

    uint32_t afb[2][4][4], bfb[2][8][2];

    for (int s = 0; s < 9; ++s) {
        if (s < 8) {
            conv_stage_async<STAGE>(S0 + ((s + 1) & 1) * BUFBYTES, SRC, Wsrc,
                                    blockbase, s + 1, tid);
            CP_COMMIT();
            CP_WAIT(1);
        } else {
            CP_WAIT(0);
        }
        __syncthreads();

        const uint32_t SA = S0 + (s & 1) * BUFBYTES;
        const uint32_t SW = SA + ABYTES;

        // prologue fragment load: iteration 0 (dz=0, kc=0)
#pragma unroll
        for (int mt = 0; mt < 4; ++mt) {
            int row = 0 + m0 + mt * 16 + arow;
            ldsm_x4(afb[0][mt], SA + row * 128 +
                    (((uint32_t)((0 * 2 + asel) ^ (row & 7))) << 4));
        }
#pragma unroll
        for (int nt = 0; nt < 8; ++nt) {
            int row = nt * 8 + brow;
            ldsm_x2(bfb[0][nt], SW + 0 * 8192 + row * 128 +
                    (((uint32_t)((0 * 2 + bsel) ^ (row & 7))) << 4));
        }

#pragma unroll
        for (int it = 0; it < 12; ++it) {
            const int cur = it & 1;
            if (it < 11) {
                const int nit = it + 1;
                const int ndz = nit >> 2, nkc = nit & 3;
                const int nxt = nit & 1;
#pragma unroll
                for (int mt = 0; mt < 4; ++mt) {
                    int row = ndz + m0 + mt * 16 + arow;
                    ldsm_x4(afb[nxt][mt], SA + row * 128 +
                            (((uint32_t)((nkc * 2 + asel) ^ (row & 7))) << 4));
                }
#pragma unroll
                for (int nt = 0; nt < 8; ++nt) {
                    int row = nt * 8 + brow;
                    ldsm_x2(bfb[nxt][nt], SW + ndz * 8192 + row * 128 +
                            (((uint32_t)((nkc * 2 + bsel) ^ (row & 7))) << 4));
                }
            }
#pragma unroll
            for (int mt = 0; mt < 4; ++mt)
#pragma unroll
                for (int nt = 0; nt < 8; ++nt)
                    mma_f16(acc[mt][nt], afb[cur][mt], bfb[cur][nt]);
        }
        __syncthreads();
    }

    // ---- epilogue: bias + relu + BN ----
    const int gr = lane >> 2, tig = lane & 3;
#pragma unroll
    for (int mt = 0; mt < 4; ++mt)
#pragma unroll
        for (int half = 0; half < 2; ++half) {
            int rl = m0 + mt * 16 + half * 8 + gr;
            long p = blockbase + rl;
            if (p >= PTOT) continue;
            if (STAGE == 1) {
                int x = (int)(p / PXS);
                int rem = (int)(p - (long)x * PXS);
                int y = rem / PYS, z = rem - y * PYS;
                bool valid = (x >= 1) && (x <= 64) && (y >= 1) && (y <= 64)
                             && (z >= 1) && (z <= 64);
                if (!valid) continue;   // pads of g_Q must stay zero
            }
            long base = (GUARD + p) * 64;
#pragma unroll
            for (int nt = 0; nt < 8; ++nt) {
                int col = nt * 8 + tig * 2;
                float v0r = fmaxf(acc[mt][nt][half * 2 + 0] + s_ep[col], 0.f)
                            * s_ep[64 + col] + s_ep[128 + col];
                float v1r = fmaxf(acc[mt][nt][half * 2 + 1] + s_ep[col + 1], 0.f)
                            * s_ep[64 + col + 1] + s_ep[128 + col + 1];
                __half2 hv;
                hv.x = __float2half_rn(v0r);
                hv.y = __float2half_rn(v1r);
                if (STAGE == 1) *(__half2*)&g_Q[base + col]   = hv;
                else            *(__half2*)&g_h2p[base + col] = hv;
            }
        }
}

// ---------------------------------------------------------------------------
// devoxelize: trilinear gather from fp16 g_h2p + residual add of g_mlp.
// ---------------------------------------------------------------------------
__global__ void gather_kernel(const float* __restrict__ coords,
                              float* __restrict__ out)
{
    int t = blockIdx.x * blockDim.x + threadIdx.x;
    if (t >= N_PTS * 32) return;
    int n = t >> 5, c2 = (t & 31) << 1;

    float px = fminf(fmaxf(coords[n * 3 + 0], 0.f), 63.f);
    float py = fminf(fmaxf(coords[n * 3 + 1], 0.f), 63.f);
    float pz = fminf(fmaxf(coords[n * 3 + 2], 0.f), 63.f);
    float fx = floorf(px), fy = floorf(py), fz = floorf(pz);
    int x0 = (int)fx, y0 = (int)fy, z0 = (int)fz;
    int x1 = min(x0 + 1, 63), y1 = min(y0 + 1, 63), z1 = min(z0 + 1, 63);
    float tx = px - fx, ty = py - fy, tz = pz - fz;

    auto at = [&](int x, int y, int z) {
        long row = (long)GUARD + (long)(x + 1) * PXS + (y + 1) * PYS + (z + 1);
        __half2 h = *(const __half2*)&g_h2p[row * 64 + c2];
        return __half22float2(h);
    };
    float2 r = *(const float2*)&g_mlp[n * 64 + c2];
    float2 f;
    float w;
    w = (1.f - tx) * (1.f - ty) * (1.f - tz); f = at(x0, y0, z0); r.x += w * f.x; r.y += w * f.y;
    w = (1.f - tx) * (1.f - ty) * tz;          f = at(x0, y0, z1); r.x += w * f.x; r.y += w * f.y;
    w = (1.f - tx) * ty          * (1.f - tz); f = at(x0, y1, z0); r.x += w * f.x; r.y += w * f.y;
    w = (1.f - tx) * ty          * tz;          f = at(x0, y1, z1); r.x += w * f.x; r.y += w * f.y;
    w = tx          * (1.f - ty) * (1.f - tz); f = at(x1, y0, z0); r.x += w * f.x; r.y += w * f.y;
    w = tx          * (1.f - ty) * tz;          f = at(x1, y0, z1); r.x += w * f.x; r.y += w * f.y;
    w = tx          * ty          * (1.f - tz); f = at(x1, y1, z0); r.x += w * f.x; r.y += w * f.y;
    w = tx          * ty          * tz;          f = at(x1, y1, z1); r.x += w * f.x; r.y += w * f.y;

    *(float2*)&out[n * 64 + c2] = r;
}

// ---------------------------------------------------------------------------
extern "C" void kernel_launch(void* const* d_in, const int* in_sizes, int n_in,
                              void* d_out, int out_size)
{
    const float* inputs    = (const float*)d_in[0];
    const float* pt_coords = (const float*)d_in[1];
    const int*   vidx      = (const int*)  d_in[2];
    const float* pinv      = (const float*)d_in[3];
    const float* w_mlp     = (const float*)d_in[4];
    const float* b_mlp     = (const float*)d_in[5];
    const float* g0        = (const float*)d_in[6];
    const float* be0       = (const float*)d_in[7];
    const float* m0        = (const float*)d_in[8];
    const float* v0        = (const float*)d_in[9];
    const float* k1        = (const float*)d_in[10];
    const float* cb1       = (const float*)d_in[11];
    const float* g1        = (const float*)d_in[12];
    const float* be1       = (const float*)d_in[13];
    const float* m1        = (const float*)d_in[14];
    const float* v1        = (const float*)d_in[15];
    const float* k2        = (const float*)d_in[16];
    const float* cb2       = (const float*)d_in[17];
    const float* g2        = (const float*)d_in[18];
    const float* be2       = (const float*)d_in[19];
    const float* m2        = (const float*)d_in[20];
    const float* v2        = (const float*)d_in[21];
    float* out = (float*)d_out;

    // one-time host-side resource setup (no device memory involved)
    static cudaStream_t s2 = nullptr;
    static cudaEvent_t evFork = nullptr, evJoin = nullptr;
    static cudaEvent_t evC1 = nullptr, evZ = nullptr;
    if (s2 == nullptr) {
        cudaStreamCreateWithFlags(&s2, cudaStreamNonBlocking);
        cudaEventCreateWithFlags(&evFork, cudaEventDisableTiming);
        cudaEventCreateWithFlags(&evJoin, cudaEventDisableTiming);
        cudaEventCreateWithFlags(&evC1, cudaEventDisableTiming);
        cudaEventCreateWithFlags(&evZ, cudaEventDisableTiming);
    }

    const int DSMEM_MLP = 24576;
    cudaFuncSetAttribute(conv_mma_kernel<1>,
                         cudaFuncAttributeMaxDynamicSharedMemorySize, DSMEM_CONV);
    cudaFuncSetAttribute(conv_mma_kernel<2>,
                         cudaFuncAttributeMaxDynamicSharedMemorySize, DSMEM_CONV);
    cudaFuncSetAttribute(mlp_mma_kernel,
                         cudaFuncAttributeMaxDynamicSharedMemorySize, DSMEM_MLP);

    cudaEventRecord(evFork, 0);
    cudaStreamWaitEvent(s2, evFork, 0);

    // main stream: scatter (fused voxelize+scale) then weights then conv1
    scatter_kernel<<<(N_PTS * 32 + 255) / 256, 256>>>(inputs, vidx, pinv);
    build_W_kernel<<<(2 * 27 * 64 * 64 + 255) / 256, 256>>>(k1, k2);

    // s2: point branch, independent of the voxel chain
    mlp_mma_kernel<<<NTILE_M, 256, DSMEM_MLP, s2>>>(inputs, w_mlp, b_mlp,
                                                    g0, be0, m0, v0);
    cudaEventRecord(evJoin, s2);

    conv_mma_kernel<1><<<NTILE2, 256, DSMEM_CONV>>>(cb1, g1, be1, m1, v1);
    cudaEventRecord(evC1, 0);

    // s2: re-zero g_P for the next replay, concurrent with conv2
    cudaStreamWaitEvent(s2, evC1, 0);
    zero_P_kernel<<<2048, 256, 0, s2>>>();
    cudaEventRecord(evZ, s2);

    conv_mma_kernel<2><<<NTILE2, 256, DSMEM_CONV>>>(cb2, g2, be2, m2, v2);

    // join: gather needs conv2 (stream 0), mlp and zero_P (s2)
    cudaStreamWaitEvent(0, evJoin, 0);
    cudaStreamWaitEvent(0, evZ, 0);
    gather_kernel<<<(N_PTS * 32 + 255) / 256, 256>>>(pt_coords, out);
}